// round 1
// baseline (speedup 1.0000x reference)
#include <cuda_runtime.h>
#include <cuda_bf16.h>
#include <math.h>

// Problem constants
#define B_   32
#define NS_  4096
#define D_   256
#define H_   4
#define L_   6
#define NQ_  512
#define NK_  1024
#define DH_  64
#define SCALE_ 0.125f

#define MQ (B_*NQ_)   // 16384 rows
#define MK (B_*NK_)   // 32768 rows

// -------- persistent device scratch (static, no allocation) --------
__device__ float g_U  [(size_t)B_*NS_*D_];  // mutable copy of update_tensor
__device__ float g_q  [(size_t)MQ*D_];
__device__ float g_k  [(size_t)MK*D_];
__device__ float g_Qp [(size_t)MQ*D_];
__device__ float g_Kp [(size_t)MK*D_];
__device__ float g_Vp [(size_t)MK*D_];
__device__ float g_ctx[(size_t)MQ*D_];
__device__ float g_h  [(size_t)MQ*D_];
__device__ float g_t1 [(size_t)MQ*D_];
__device__ float g_f  [(size_t)MQ*D_];
__device__ float g_res[(size_t)MQ*D_];

// -------- helpers --------
__device__ __forceinline__ float block_sum256(float v, float* s8) {
    #pragma unroll
    for (int o = 16; o; o >>= 1) v += __shfl_xor_sync(0xffffffffu, v, o);
    __syncthreads();                      // protect s8 reuse across calls
    if ((threadIdx.x & 31) == 0) s8[threadIdx.x >> 5] = v;
    __syncthreads();
    float tot = 0.f;
    #pragma unroll
    for (int i = 0; i < 8; i++) tot += s8[i];
    return tot;
}

__device__ __forceinline__ float gelu_tanh(float x) {
    float x3 = x * x * x;
    float t = tanhf(0.7978845608028654f * (x + 0.044715f * x3));
    return 0.5f * x * (1.f + t);
}

// -------- init: copy update_tensor into g_U, zero output --------
__global__ void init_kernel(const float* __restrict__ upd, float* __restrict__ out) {
    size_t i = (size_t)blockIdx.x * blockDim.x + threadIdx.x;
    g_U[i] = upd[i];
    out[i] = 0.f;
}

// -------- gather + LayerNorm(sys) --------
// grid (n, B), block 256. out[(b*n+i)*256 + t]
__global__ void gather_ln(const float* __restrict__ emb, const int* __restrict__ idx,
                          const float* __restrict__ sc, const float* __restrict__ bi,
                          float* __restrict__ out, int n) {
    __shared__ float red[8];
    int i = blockIdx.x, b = blockIdx.y, t = threadIdx.x;
    int id = idx[i];
    float x = emb[(size_t)id * D_ + t] + g_U[((size_t)b * NS_ + id) * D_ + t];
    float m  = block_sum256(x, red) * (1.f / D_);
    float xc = x - m;
    float v  = block_sum256(xc * xc, red) * (1.f / D_);
    out[((size_t)(b * n + i)) * D_ + t] = xc * rsqrtf(v + 1e-5f) * sc[t] + bi[t];
}

// -------- fp32 tiled GEMM: C[M,256] = A[M,256] * W[256,256] (+bias, +gelu) --------
// grid (4, M/64), block 256, 64x64x32 tiles, 4x4 microtile
template<int EPI>   // 0=none, 1=+bias, 2=+bias+gelu
__global__ void gemm256(const float* __restrict__ A, const float* __restrict__ W,
                        const float* __restrict__ bias, float* __restrict__ C) {
    __shared__ float As[32][65];   // [k][m], padded
    __shared__ float Bs[32][64];   // [k][n]
    int bm = blockIdx.y * 64, bn = blockIdx.x * 64;
    int t = threadIdx.x;
    int tx = t & 15, ty = t >> 4;
    float acc[4][4] = {};

    for (int k0 = 0; k0 < 256; k0 += 32) {
        #pragma unroll
        for (int i = 0; i < 8; i++) {
            int e = t + i * 256;
            int r = e >> 5, c = e & 31;
            As[c][r] = A[(size_t)(bm + r) * 256 + k0 + c];
        }
        #pragma unroll
        for (int i = 0; i < 8; i++) {
            int e = t + i * 256;
            int r = e >> 6, c = e & 63;
            Bs[r][c] = W[(size_t)(k0 + r) * 256 + bn + c];
        }
        __syncthreads();
        #pragma unroll
        for (int k = 0; k < 32; k++) {
            float a[4], bb[4];
            #pragma unroll
            for (int j = 0; j < 4; j++) a[j]  = As[k][ty * 4 + j];
            #pragma unroll
            for (int j = 0; j < 4; j++) bb[j] = Bs[k][tx * 4 + j];
            #pragma unroll
            for (int i = 0; i < 4; i++)
                #pragma unroll
                for (int j = 0; j < 4; j++)
                    acc[i][j] += a[i] * bb[j];
        }
        __syncthreads();
    }
    #pragma unroll
    for (int i = 0; i < 4; i++) {
        int row = bm + ty * 4 + i;
        #pragma unroll
        for (int j = 0; j < 4; j++) {
            int col = bn + tx * 4 + j;
            float v = acc[i][j];
            if (EPI >= 1) v += bias[col];
            if (EPI == 2) v = gelu_tanh(v);
            C[(size_t)row * 256 + col] = v;
        }
    }
}

// -------- attention: warp per q-row, two-pass softmax with smem score row --------
// grid (NQ/8, H, B), block 256 (8 warps)
__global__ void attn_kernel(const float* __restrict__ Qp, const float* __restrict__ Kp,
                            const float* __restrict__ Vp, const float* __restrict__ maskl,
                            float* __restrict__ ctx) {
    __shared__ float q_s[8][64];
    __shared__ float sc[8][NK_];
    int w = threadIdx.x >> 5, lane = threadIdx.x & 31;
    int b = blockIdx.z, h = blockIdx.y;
    int r = blockIdx.x * 8 + w;

    const float* qrow = Qp + ((size_t)(b * NQ_ + r)) * D_ + h * DH_;
    float2 qv = *(const float2*)(qrow + lane * 2);
    q_s[w][lane * 2]     = qv.x;
    q_s[w][lane * 2 + 1] = qv.y;
    __syncwarp();

    const float* Kb   = Kp + (size_t)b * NK_ * D_ + h * DH_;
    const float* Mrow = maskl + (size_t)r * NK_;

    float mmax = -1e30f;
    for (int kk = lane; kk < NK_; kk += 32) {
        const float* krow = Kb + (size_t)kk * D_;
        float acc = 0.f;
        #pragma unroll
        for (int d = 0; d < DH_; d += 4) {
            float4 k4 = *(const float4*)(krow + d);
            acc += q_s[w][d] * k4.x + q_s[w][d+1] * k4.y
                 + q_s[w][d+2] * k4.z + q_s[w][d+3] * k4.w;
        }
        float s = (Mrow[kk] > 0.5f) ? acc * SCALE_ : -1e9f;
        sc[w][kk] = s;
        mmax = fmaxf(mmax, s);
    }
    #pragma unroll
    for (int o = 16; o; o >>= 1) mmax = fmaxf(mmax, __shfl_xor_sync(0xffffffffu, mmax, o));

    float ssum = 0.f;
    for (int kk = lane; kk < NK_; kk += 32) {
        float e = __expf(sc[w][kk] - mmax);
        sc[w][kk] = e;
        ssum += e;
    }
    #pragma unroll
    for (int o = 16; o; o >>= 1) ssum += __shfl_xor_sync(0xffffffffu, ssum, o);
    float inv = 1.f / ssum;
    __syncwarp();

    const float* Vb = Vp + (size_t)b * NK_ * D_ + h * DH_;
    int d0 = lane * 2;
    float a0 = 0.f, a1 = 0.f;
    #pragma unroll 4
    for (int k = 0; k < NK_; k++) {
        float p = sc[w][k];
        float2 v = *(const float2*)(Vb + (size_t)k * D_ + d0);
        a0 += p * v.x;
        a1 += p * v.y;
    }
    float* crow = ctx + ((size_t)(b * NQ_ + r)) * D_ + h * DH_ + d0;
    crow[0] = a0 * inv;
    crow[1] = a1 * inv;
}

// -------- plain LayerNorm over rows --------
__global__ void ln_kernel(const float* __restrict__ in, const float* __restrict__ sc,
                          const float* __restrict__ bi, float* __restrict__ out) {
    __shared__ float red[8];
    int row = blockIdx.x, t = threadIdx.x;
    float x  = in[(size_t)row * D_ + t];
    float m  = block_sum256(x, red) * (1.f / D_);
    float xc = x - m;
    float v  = block_sum256(xc * xc, red) * (1.f / D_);
    out[(size_t)row * D_ + t] = xc * rsqrtf(v + 1e-5f) * sc[t] + bi[t];
}

// -------- residual add + LN(outer) + LN(eff) fused --------
__global__ void add_double_ln(const float* __restrict__ hb, const float* __restrict__ fb,
                              const float* __restrict__ os, const float* __restrict__ ob,
                              const float* __restrict__ es, const float* __restrict__ eb,
                              float* __restrict__ out) {
    __shared__ float red[8];
    int row = blockIdx.x, t = threadIdx.x;
    float x  = hb[(size_t)row * D_ + t] + fb[(size_t)row * D_ + t];
    float m  = block_sum256(x, red) * (1.f / D_);
    float xc = x - m;
    float v  = block_sum256(xc * xc, red) * (1.f / D_);
    float u  = xc * rsqrtf(v + 1e-5f) * os[t] + ob[t];
    float m2 = block_sum256(u, red) * (1.f / D_);
    float uc = u - m2;
    float v2 = block_sum256(uc * uc, red) * (1.f / D_);
    out[(size_t)row * D_ + t] = uc * rsqrtf(v2 + 1e-5f) * es[t] + eb[t];
}

// -------- scatter add (atomic: handles duplicate indices) --------
__global__ void scatter_add(const float* __restrict__ res, const int* __restrict__ qidx,
                            float* __restrict__ out) {
    int i = blockIdx.x, b = blockIdx.y, t = threadIdx.x;
    int id = qidx[i];
    float v = res[((size_t)(b * NQ_ + i)) * D_ + t];
    atomicAdd(&g_U[((size_t)b * NS_ + id) * D_ + t], v);
    atomicAdd(&out[((size_t)b * NS_ + id) * D_ + t], v);
}

// -------- host launcher --------
extern "C" void kernel_launch(void* const* d_in, const int* in_sizes, int n_in,
                              void* d_out, int out_size) {
    const float* upd   = (const float*)d_in[0];
    const float* emb   = (const float*)d_in[1];
    const float* maskl = (const float*)d_in[2];
    const float* Wq    = (const float*)d_in[3];
    const float* Wk    = (const float*)d_in[4];
    const float* Wv    = (const float*)d_in[5];
    const float* Wo    = (const float*)d_in[6];
    const float* W1    = (const float*)d_in[7];
    const float* b1    = (const float*)d_in[8];
    const float* W2    = (const float*)d_in[9];
    const float* b2    = (const float*)d_in[10];
    const float* sys_s = (const float*)d_in[11];
    const float* sys_b = (const float*)d_in[12];
    const float* eff_s = (const float*)d_in[13];
    const float* eff_b = (const float*)d_in[14];
    const float* in_s  = (const float*)d_in[15];
    const float* in_b  = (const float*)d_in[16];
    const float* out_s = (const float*)d_in[17];
    const float* out_b = (const float*)d_in[18];
    const int*   qidx  = (const int*)d_in[19];
    const int*   kidx  = (const int*)d_in[20];
    float* out = (float*)d_out;

    float *qb, *kb, *Qp, *Kp, *Vp, *ctx, *hb, *t1, *fb, *res;
    cudaGetSymbolAddress((void**)&qb,  g_q);
    cudaGetSymbolAddress((void**)&kb,  g_k);
    cudaGetSymbolAddress((void**)&Qp,  g_Qp);
    cudaGetSymbolAddress((void**)&Kp,  g_Kp);
    cudaGetSymbolAddress((void**)&Vp,  g_Vp);
    cudaGetSymbolAddress((void**)&ctx, g_ctx);
    cudaGetSymbolAddress((void**)&hb,  g_h);
    cudaGetSymbolAddress((void**)&t1,  g_t1);
    cudaGetSymbolAddress((void**)&fb,  g_f);
    cudaGetSymbolAddress((void**)&res, g_res);

    // init: copy U, zero output
    init_kernel<<<(B_ * NS_ * D_) / 256, 256>>>(upd, out);

    for (int l = 0; l < L_; l++) {
        gather_ln<<<dim3(NQ_, B_), 256>>>(emb, qidx + l * NQ_, sys_s, sys_b, qb, NQ_);
        gather_ln<<<dim3(NK_, B_), 256>>>(emb, kidx + l * NK_, sys_s, sys_b, kb, NK_);

        gemm256<0><<<dim3(4, MQ / 64), 256>>>(qb, Wq, nullptr, Qp);
        gemm256<0><<<dim3(4, MK / 64), 256>>>(kb, Wk, nullptr, Kp);
        gemm256<0><<<dim3(4, MK / 64), 256>>>(kb, Wv, nullptr, Vp);

        attn_kernel<<<dim3(NQ_ / 8, H_, B_), 256>>>(Qp, Kp, Vp,
                                                    maskl + (size_t)l * NQ_ * NK_, ctx);

        gemm256<0><<<dim3(4, MQ / 64), 256>>>(ctx, Wo, nullptr, t1);
        ln_kernel<<<MQ, 256>>>(t1, in_s, in_b, hb);

        gemm256<2><<<dim3(4, MQ / 64), 256>>>(hb, W1, b1, t1);   // gelu(h@W1+b1)
        gemm256<1><<<dim3(4, MQ / 64), 256>>>(t1, W2, b2, fb);   // @W2 + b2

        add_double_ln<<<MQ, 256>>>(hb, fb, out_s, out_b, eff_s, eff_b, res);

        scatter_add<<<dim3(NQ_, B_), 256>>>(res, qidx + l * NQ_, out);
    }
}

// round 3
// speedup vs baseline: 4.9861x; 4.9861x over previous
#include <cuda_runtime.h>
#include <cuda_bf16.h>
#include <math.h>

// Problem constants
#define B_   32
#define NS_  4096
#define D_   256
#define H_   4
#define L_   6
#define NQ_  512
#define NK_  1024
#define DH_  64
#define SCALE_ 0.125f

#define MQ (B_*NQ_)   // 16384 rows
#define MK (B_*NK_)   // 32768 rows

// -------- persistent device scratch (static, no allocation) --------
__device__ float g_U  [(size_t)B_*NS_*D_];  // mutable copy of update_tensor
__device__ float g_q  [(size_t)MQ*D_];
__device__ float g_k  [(size_t)MK*D_];
__device__ float g_Qp [(size_t)MQ*D_];
__device__ float g_Kp [(size_t)MK*D_];
__device__ float g_Vp [(size_t)MK*D_];
__device__ float g_ctx[(size_t)MQ*D_];
__device__ float g_h  [(size_t)MQ*D_];
__device__ float g_t1 [(size_t)MQ*D_];
__device__ float g_f  [(size_t)MQ*D_];
__device__ float g_res[(size_t)MQ*D_];

// -------- helpers --------
__device__ __forceinline__ float block_sum256(float v, float* s8) {
    #pragma unroll
    for (int o = 16; o; o >>= 1) v += __shfl_xor_sync(0xffffffffu, v, o);
    __syncthreads();
    if ((threadIdx.x & 31) == 0) s8[threadIdx.x >> 5] = v;
    __syncthreads();
    float tot = 0.f;
    #pragma unroll
    for (int i = 0; i < 8; i++) tot += s8[i];
    return tot;
}

__device__ __forceinline__ float gelu_tanh(float x) {
    float x3 = x * x * x;
    float t = tanhf(0.7978845608028654f * (x + 0.044715f * x3));
    return 0.5f * x * (1.f + t);
}

// -------- init: copy update_tensor into g_U, zero output --------
__global__ void init_kernel(const float* __restrict__ upd, float* __restrict__ out) {
    size_t i = (size_t)blockIdx.x * blockDim.x + threadIdx.x;
    g_U[i] = upd[i];
    out[i] = 0.f;
}

// -------- gather + LayerNorm(sys) --------
__global__ void gather_ln(const float* __restrict__ emb, const int* __restrict__ idx,
                          const float* __restrict__ sc, const float* __restrict__ bi,
                          float* __restrict__ out, int n) {
    __shared__ float red[8];
    int i = blockIdx.x, b = blockIdx.y, t = threadIdx.x;
    int id = idx[i];
    float x = emb[(size_t)id * D_ + t] + g_U[((size_t)b * NS_ + id) * D_ + t];
    float m  = block_sum256(x, red) * (1.f / D_);
    float xc = x - m;
    float v  = block_sum256(xc * xc, red) * (1.f / D_);
    out[((size_t)(b * n + i)) * D_ + t] = xc * rsqrtf(v + 1e-5f) * sc[t] + bi[t];
}

// -------- fp32 tiled GEMM: C[M,256] = A[M,256] * W[256,256] (+bias, +gelu) --------
template<int EPI>   // 0=none, 1=+bias, 2=+bias+gelu
__global__ void gemm256(const float* __restrict__ A, const float* __restrict__ W,
                        const float* __restrict__ bias, float* __restrict__ C) {
    __shared__ float As[32][65];   // [k][m], padded
    __shared__ float Bs[32][64];   // [k][n]
    int bm = blockIdx.y * 64, bn = blockIdx.x * 64;
    int t = threadIdx.x;
    int tx = t & 15, ty = t >> 4;
    float acc[4][4] = {};

    for (int k0 = 0; k0 < 256; k0 += 32) {
        #pragma unroll
        for (int i = 0; i < 8; i++) {
            int e = t + i * 256;
            int r = e >> 5, c = e & 31;
            As[c][r] = A[(size_t)(bm + r) * 256 + k0 + c];
        }
        #pragma unroll
        for (int i = 0; i < 8; i++) {
            int e = t + i * 256;
            int r = e >> 6, c = e & 63;
            Bs[r][c] = W[(size_t)(k0 + r) * 256 + bn + c];
        }
        __syncthreads();
        #pragma unroll
        for (int k = 0; k < 32; k++) {
            float a[4], bb[4];
            #pragma unroll
            for (int j = 0; j < 4; j++) a[j]  = As[k][ty * 4 + j];
            #pragma unroll
            for (int j = 0; j < 4; j++) bb[j] = Bs[k][tx * 4 + j];
            #pragma unroll
            for (int i = 0; i < 4; i++)
                #pragma unroll
                for (int j = 0; j < 4; j++)
                    acc[i][j] += a[i] * bb[j];
        }
        __syncthreads();
    }
    #pragma unroll
    for (int i = 0; i < 4; i++) {
        int row = bm + ty * 4 + i;
        #pragma unroll
        for (int j = 0; j < 4; j++) {
            int col = bn + tx * 4 + j;
            float v = acc[i][j];
            if (EPI >= 1) v += bias[col];
            if (EPI == 2) v = gelu_tanh(v);
            C[(size_t)row * 256 + col] = v;
        }
    }
}

// -------- flash attention: CTA = 64 q-rows of one (b,h), K-tiles of 64 --------
// grid (NQ/64=8, H, B), block 256 (16x16 threads, 4x4 microtile)
// dynamic smem: Qt[64][65] (d-major) | Kt[64][68] (d-major) | Vs[64][68] | Ps[64][68]
#define QT_STR 65
#define KT_STR 68
#define ATTN_SMEM ((64*QT_STR + 3*64*KT_STR) * sizeof(float))

__global__ void flash_attn(const float* __restrict__ Qp, const float* __restrict__ Kp,
                           const float* __restrict__ Vp, const float* __restrict__ maskl,
                           float* __restrict__ ctx) {
    extern __shared__ float sm[];
    float* Qt = sm;                       // [d][qr]  stride 65
    float* Kt = Qt + 64 * QT_STR;         // [d][kr]  stride 68
    float* Vs = Kt + 64 * KT_STR;         // [kr][c]  stride 68
    float* Ps = Vs + 64 * KT_STR;         // [qr][kr] stride 68 (bias, then p)

    int t = threadIdx.x;
    int tx = t & 15, ty = t >> 4;
    int qb = blockIdx.x, h = blockIdx.y, b = blockIdx.z;

    // ---- load Q tile transposed: Qt[d][qr] ----
    {
        int r  = t >> 4;          // 0..15
        int c4 = (t & 15) * 4;    // d chunk
        #pragma unroll
        for (int rr = r; rr < 64; rr += 16) {
            float4 v = *(const float4*)(Qp + ((size_t)(b * NQ_) + qb * 64 + rr) * D_ + h * DH_ + c4);
            Qt[(c4 + 0) * QT_STR + rr] = v.x;
            Qt[(c4 + 1) * QT_STR + rr] = v.y;
            Qt[(c4 + 2) * QT_STR + rr] = v.z;
            Qt[(c4 + 3) * QT_STR + rr] = v.w;
        }
    }

    float acc[4][4] = {};
    float run_m[4], run_l[4];
    #pragma unroll
    for (int i = 0; i < 4; i++) { run_m[i] = -1e30f; run_l[i] = 0.f; }

    for (int kt = 0; kt < NK_ / 64; kt++) {
        __syncthreads();   // protect prev-iter PV reads (and first-iter Qt writes)

        // ---- load K (transposed), V (row-major), mask-bias into Ps ----
        {
            int r  = t >> 4;
            int c4 = (t & 15) * 4;
            #pragma unroll
            for (int rr = r; rr < 64; rr += 16) {
                size_t krow = ((size_t)(b * NK_) + kt * 64 + rr) * D_ + h * DH_ + c4;
                float4 kv = *(const float4*)(Kp + krow);
                Kt[(c4 + 0) * KT_STR + rr] = kv.x;
                Kt[(c4 + 1) * KT_STR + rr] = kv.y;
                Kt[(c4 + 2) * KT_STR + rr] = kv.z;
                Kt[(c4 + 3) * KT_STR + rr] = kv.w;

                float4 vv = *(const float4*)(Vp + krow);
                *(float4*)&Vs[rr * KT_STR + c4] = vv;

                float4 mv = *(const float4*)(maskl + (size_t)(qb * 64 + rr) * NK_ + kt * 64 + c4);
                float4 bias;
                bias.x = mv.x > 0.5f ? 0.f : -1e9f;
                bias.y = mv.y > 0.5f ? 0.f : -1e9f;
                bias.z = mv.z > 0.5f ? 0.f : -1e9f;
                bias.w = mv.w > 0.5f ? 0.f : -1e9f;
                *(float4*)&Ps[rr * KT_STR + c4] = bias;
            }
        }
        __syncthreads();

        // ---- S = (Q . K^T) * SCALE + bias ----
        float s[4][4] = {};
        #pragma unroll
        for (int d = 0; d < 64; d++) {
            float a0 = Qt[d * QT_STR + ty * 4 + 0];
            float a1 = Qt[d * QT_STR + ty * 4 + 1];
            float a2 = Qt[d * QT_STR + ty * 4 + 2];
            float a3 = Qt[d * QT_STR + ty * 4 + 3];
            float4 bk = *(const float4*)&Kt[d * KT_STR + tx * 4];
            s[0][0] += a0 * bk.x; s[0][1] += a0 * bk.y; s[0][2] += a0 * bk.z; s[0][3] += a0 * bk.w;
            s[1][0] += a1 * bk.x; s[1][1] += a1 * bk.y; s[1][2] += a1 * bk.z; s[1][3] += a1 * bk.w;
            s[2][0] += a2 * bk.x; s[2][1] += a2 * bk.y; s[2][2] += a2 * bk.z; s[2][3] += a2 * bk.w;
            s[3][0] += a3 * bk.x; s[3][1] += a3 * bk.y; s[3][2] += a3 * bk.z; s[3][3] += a3 * bk.w;
        }
        #pragma unroll
        for (int i = 0; i < 4; i++) {
            float4 bias = *(const float4*)&Ps[(ty * 4 + i) * KT_STR + tx * 4];
            s[i][0] = s[i][0] * SCALE_ + bias.x;
            s[i][1] = s[i][1] * SCALE_ + bias.y;
            s[i][2] = s[i][2] * SCALE_ + bias.z;
            s[i][3] = s[i][3] * SCALE_ + bias.w;
        }

        // ---- online softmax (row reductions across 16 tx threads) ----
        #pragma unroll
        for (int i = 0; i < 4; i++) {
            float m = fmaxf(fmaxf(s[i][0], s[i][1]), fmaxf(s[i][2], s[i][3]));
            #pragma unroll
            for (int o = 8; o; o >>= 1) m = fmaxf(m, __shfl_xor_sync(0xffffffffu, m, o));
            float nm  = fmaxf(run_m[i], m);
            float fac = __expf(run_m[i] - nm);
            float sum = 0.f;
            #pragma unroll
            for (int j = 0; j < 4; j++) { s[i][j] = __expf(s[i][j] - nm); sum += s[i][j]; }
            #pragma unroll
            for (int o = 8; o; o >>= 1) sum += __shfl_xor_sync(0xffffffffu, sum, o);
            run_l[i] = run_l[i] * fac + sum;
            run_m[i] = nm;
            acc[i][0] *= fac; acc[i][1] *= fac; acc[i][2] *= fac; acc[i][3] *= fac;
            // write p (same elements this thread read bias from — no cross-thread hazard)
            *(float4*)&Ps[(ty * 4 + i) * KT_STR + tx * 4] = make_float4(s[i][0], s[i][1], s[i][2], s[i][3]);
        }
        __syncthreads();

        // ---- acc += P . V ----
        #pragma unroll
        for (int kk = 0; kk < 64; kk++) {
            float a0 = Ps[(ty * 4 + 0) * KT_STR + kk];
            float a1 = Ps[(ty * 4 + 1) * KT_STR + kk];
            float a2 = Ps[(ty * 4 + 2) * KT_STR + kk];
            float a3 = Ps[(ty * 4 + 3) * KT_STR + kk];
            float4 v = *(const float4*)&Vs[kk * KT_STR + tx * 4];
            acc[0][0] += a0 * v.x; acc[0][1] += a0 * v.y; acc[0][2] += a0 * v.z; acc[0][3] += a0 * v.w;
            acc[1][0] += a1 * v.x; acc[1][1] += a1 * v.y; acc[1][2] += a1 * v.z; acc[1][3] += a1 * v.w;
            acc[2][0] += a2 * v.x; acc[2][1] += a2 * v.y; acc[2][2] += a2 * v.z; acc[2][3] += a2 * v.w;
            acc[3][0] += a3 * v.x; acc[3][1] += a3 * v.y; acc[3][2] += a3 * v.z; acc[3][3] += a3 * v.w;
        }
    }

    // ---- epilogue: ctx = acc / run_l ----
    #pragma unroll
    for (int i = 0; i < 4; i++) {
        float inv = 1.f / run_l[i];
        float4 o = make_float4(acc[i][0] * inv, acc[i][1] * inv, acc[i][2] * inv, acc[i][3] * inv);
        *(float4*)(ctx + ((size_t)(b * NQ_) + qb * 64 + ty * 4 + i) * D_ + h * DH_ + tx * 4) = o;
    }
}

// -------- plain LayerNorm over rows --------
__global__ void ln_kernel(const float* __restrict__ in, const float* __restrict__ sc,
                          const float* __restrict__ bi, float* __restrict__ out) {
    __shared__ float red[8];
    int row = blockIdx.x, t = threadIdx.x;
    float x  = in[(size_t)row * D_ + t];
    float m  = block_sum256(x, red) * (1.f / D_);
    float xc = x - m;
    float v  = block_sum256(xc * xc, red) * (1.f / D_);
    out[(size_t)row * D_ + t] = xc * rsqrtf(v + 1e-5f) * sc[t] + bi[t];
}

// -------- residual add + LN(outer) + LN(eff) fused --------
__global__ void add_double_ln(const float* __restrict__ hb, const float* __restrict__ fb,
                              const float* __restrict__ os, const float* __restrict__ ob,
                              const float* __restrict__ es, const float* __restrict__ eb,
                              float* __restrict__ out) {
    __shared__ float red[8];
    int row = blockIdx.x, t = threadIdx.x;
    float x  = hb[(size_t)row * D_ + t] + fb[(size_t)row * D_ + t];
    float m  = block_sum256(x, red) * (1.f / D_);
    float xc = x - m;
    float v  = block_sum256(xc * xc, red) * (1.f / D_);
    float u  = xc * rsqrtf(v + 1e-5f) * os[t] + ob[t];
    float m2 = block_sum256(u, red) * (1.f / D_);
    float uc = u - m2;
    float v2 = block_sum256(uc * uc, red) * (1.f / D_);
    out[(size_t)row * D_ + t] = uc * rsqrtf(v2 + 1e-5f) * es[t] + eb[t];
}

// -------- scatter add (atomic: handles duplicate indices) --------
__global__ void scatter_add(const float* __restrict__ res, const int* __restrict__ qidx,
                            float* __restrict__ out) {
    int i = blockIdx.x, b = blockIdx.y, t = threadIdx.x;
    int id = qidx[i];
    float v = res[((size_t)(b * NQ_ + i)) * D_ + t];
    atomicAdd(&g_U[((size_t)b * NS_ + id) * D_ + t], v);
    atomicAdd(&out[((size_t)b * NS_ + id) * D_ + t], v);
}

// -------- host launcher --------
extern "C" void kernel_launch(void* const* d_in, const int* in_sizes, int n_in,
                              void* d_out, int out_size) {
    const float* upd   = (const float*)d_in[0];
    const float* emb   = (const float*)d_in[1];
    const float* maskl = (const float*)d_in[2];
    const float* Wq    = (const float*)d_in[3];
    const float* Wk    = (const float*)d_in[4];
    const float* Wv    = (const float*)d_in[5];
    const float* Wo    = (const float*)d_in[6];
    const float* W1    = (const float*)d_in[7];
    const float* b1    = (const float*)d_in[8];
    const float* W2    = (const float*)d_in[9];
    const float* b2    = (const float*)d_in[10];
    const float* sys_s = (const float*)d_in[11];
    const float* sys_b = (const float*)d_in[12];
    const float* eff_s = (const float*)d_in[13];
    const float* eff_b = (const float*)d_in[14];
    const float* in_s  = (const float*)d_in[15];
    const float* in_b  = (const float*)d_in[16];
    const float* out_s = (const float*)d_in[17];
    const float* out_b = (const float*)d_in[18];
    const int*   qidx  = (const int*)d_in[19];
    const int*   kidx  = (const int*)d_in[20];
    float* out = (float*)d_out;

    float *qb, *kb, *Qp, *Kp, *Vp, *ctx, *hb, *t1, *fb, *res;
    cudaGetSymbolAddress((void**)&qb,  g_q);
    cudaGetSymbolAddress((void**)&kb,  g_k);
    cudaGetSymbolAddress((void**)&Qp,  g_Qp);
    cudaGetSymbolAddress((void**)&Kp,  g_Kp);
    cudaGetSymbolAddress((void**)&Vp,  g_Vp);
    cudaGetSymbolAddress((void**)&ctx, g_ctx);
    cudaGetSymbolAddress((void**)&hb,  g_h);
    cudaGetSymbolAddress((void**)&t1,  g_t1);
    cudaGetSymbolAddress((void**)&fb,  g_f);
    cudaGetSymbolAddress((void**)&res, g_res);

    cudaFuncSetAttribute(flash_attn, cudaFuncAttributeMaxDynamicSharedMemorySize,
                         (int)ATTN_SMEM);

    // init: copy U, zero output
    init_kernel<<<(B_ * NS_ * D_) / 256, 256>>>(upd, out);

    for (int l = 0; l < L_; l++) {
        gather_ln<<<dim3(NQ_, B_), 256>>>(emb, qidx + l * NQ_, sys_s, sys_b, qb, NQ_);
        gather_ln<<<dim3(NK_, B_), 256>>>(emb, kidx + l * NK_, sys_s, sys_b, kb, NK_);

        gemm256<0><<<dim3(4, MQ / 64), 256>>>(qb, Wq, nullptr, Qp);
        gemm256<0><<<dim3(4, MK / 64), 256>>>(kb, Wk, nullptr, Kp);
        gemm256<0><<<dim3(4, MK / 64), 256>>>(kb, Wv, nullptr, Vp);

        flash_attn<<<dim3(NQ_ / 64, H_, B_), 256, ATTN_SMEM>>>(
            Qp, Kp, Vp, maskl + (size_t)l * NQ_ * NK_, ctx);

        gemm256<0><<<dim3(4, MQ / 64), 256>>>(ctx, Wo, nullptr, t1);
        ln_kernel<<<MQ, 256>>>(t1, in_s, in_b, hb);

        gemm256<2><<<dim3(4, MQ / 64), 256>>>(hb, W1, b1, t1);   // gelu(h@W1+b1)
        gemm256<1><<<dim3(4, MQ / 64), 256>>>(t1, W2, b2, fb);   // @W2 + b2

        add_double_ln<<<MQ, 256>>>(hb, fb, out_s, out_b, eff_s, eff_b, res);

        scatter_add<<<dim3(NQ_, B_), 256>>>(res, qidx + l * NQ_, out);
    }
}

// round 4
// speedup vs baseline: 6.0590x; 1.2152x over previous
#include <cuda_runtime.h>
#include <cuda_bf16.h>
#include <mma.h>
#include <math.h>

using namespace nvcuda;

// Problem constants
#define B_   32
#define NS_  4096
#define D_   256
#define H_   4
#define L_   6
#define NQ_  512
#define NK_  1024
#define DH_  64
#define SCALE_ 0.125f

#define MQ (B_*NQ_)   // 16384 rows
#define MK (B_*NK_)   // 32768 rows

// -------- persistent device scratch (static, no allocation) --------
__device__ float g_U  [(size_t)B_*NS_*D_];  // mutable copy of update_tensor
__device__ float g_q  [(size_t)MQ*D_];
__device__ float g_k  [(size_t)MK*D_];
__device__ float g_Qp [(size_t)MQ*D_];
__device__ float g_Kp [(size_t)MK*D_];
__device__ float g_Vp [(size_t)MK*D_];
__device__ float g_ctx[(size_t)MQ*D_];
__device__ float g_h  [(size_t)MQ*D_];
__device__ float g_t1 [(size_t)MQ*D_];
__device__ float g_f  [(size_t)MQ*D_];
__device__ float g_res[(size_t)MQ*D_];

// -------- helpers --------
__device__ __forceinline__ float block_sum256(float v, float* s8) {
    #pragma unroll
    for (int o = 16; o; o >>= 1) v += __shfl_xor_sync(0xffffffffu, v, o);
    __syncthreads();
    if ((threadIdx.x & 31) == 0) s8[threadIdx.x >> 5] = v;
    __syncthreads();
    float tot = 0.f;
    #pragma unroll
    for (int i = 0; i < 8; i++) tot += s8[i];
    return tot;
}

__device__ __forceinline__ float gelu_tanh(float x) {
    float x3 = x * x * x;
    float t = tanhf(0.7978845608028654f * (x + 0.044715f * x3));
    return 0.5f * x * (1.f + t);
}

__device__ __forceinline__ float to_tf32(float x) {
    return wmma::__float_to_tf32(x);
}

// -------- init: copy update_tensor into g_U, zero output --------
__global__ void init_kernel(const float* __restrict__ upd, float* __restrict__ out) {
    size_t i = (size_t)blockIdx.x * blockDim.x + threadIdx.x;
    g_U[i] = upd[i];
    out[i] = 0.f;
}

// -------- gather + LayerNorm(sys) --------
__global__ void gather_ln(const float* __restrict__ emb, const int* __restrict__ idx,
                          const float* __restrict__ sc, const float* __restrict__ bi,
                          float* __restrict__ out, int n) {
    __shared__ float red[8];
    int i = blockIdx.x, b = blockIdx.y, t = threadIdx.x;
    int id = idx[i];
    float x = emb[(size_t)id * D_ + t] + g_U[((size_t)b * NS_ + id) * D_ + t];
    float m  = block_sum256(x, red) * (1.f / D_);
    float xc = x - m;
    float v  = block_sum256(xc * xc, red) * (1.f / D_);
    out[((size_t)(b * n + i)) * D_ + t] = xc * rsqrtf(v + 1e-5f) * sc[t] + bi[t];
}

// -------- tf32 tensor-core GEMM: C[M,256] = A[M,256] * W[256,256] --------
// grid (2, M/128), block 256 (8 warps, 2x4 warp grid, warp tile 64x32)
#define AS_LD 40
#define BS_LD 136
__global__ void gemm_tc(const float* __restrict__ A, const float* __restrict__ W,
                        float* __restrict__ C) {
    __shared__ float As[128][AS_LD];
    __shared__ float Bs[32][BS_LD];
    int t = threadIdx.x, w = t >> 5;
    int bm = blockIdx.y * 128, bn = blockIdx.x * 128;
    int wm = (w >> 2) * 64, wn = (w & 3) * 32;

    wmma::fragment<wmma::accumulator, 16, 16, 8, float> acc[4][2];
    #pragma unroll
    for (int mi = 0; mi < 4; mi++)
        #pragma unroll
        for (int ni = 0; ni < 2; ni++) wmma::fill_fragment(acc[mi][ni], 0.f);

    int ac = (t & 7) * 4, ar = t >> 3;          // A loader
    int bc = (t & 31) * 4, br = t >> 5;         // B loader

    for (int k0 = 0; k0 < 256; k0 += 32) {
        #pragma unroll
        for (int i = 0; i < 4; i++) {
            int row = ar + i * 32;
            float4 v = *(const float4*)(A + (size_t)(bm + row) * 256 + k0 + ac);
            As[row][ac + 0] = to_tf32(v.x);
            As[row][ac + 1] = to_tf32(v.y);
            As[row][ac + 2] = to_tf32(v.z);
            As[row][ac + 3] = to_tf32(v.w);
        }
        #pragma unroll
        for (int i = 0; i < 4; i++) {
            int row = br + i * 8;
            float4 v = *(const float4*)(W + (size_t)(k0 + row) * 256 + bn + bc);
            Bs[row][bc + 0] = to_tf32(v.x);
            Bs[row][bc + 1] = to_tf32(v.y);
            Bs[row][bc + 2] = to_tf32(v.z);
            Bs[row][bc + 3] = to_tf32(v.w);
        }
        __syncthreads();
        #pragma unroll
        for (int ks = 0; ks < 4; ks++) {
            wmma::fragment<wmma::matrix_a, 16, 16, 8, wmma::precision::tf32, wmma::row_major> a[4];
            wmma::fragment<wmma::matrix_b, 16, 16, 8, wmma::precision::tf32, wmma::row_major> b[2];
            #pragma unroll
            for (int mi = 0; mi < 4; mi++)
                wmma::load_matrix_sync(a[mi], &As[wm + mi * 16][ks * 8], AS_LD);
            #pragma unroll
            for (int ni = 0; ni < 2; ni++)
                wmma::load_matrix_sync(b[ni], &Bs[ks * 8][wn + ni * 16], BS_LD);
            #pragma unroll
            for (int mi = 0; mi < 4; mi++)
                #pragma unroll
                for (int ni = 0; ni < 2; ni++)
                    wmma::mma_sync(acc[mi][ni], a[mi], b[ni], acc[mi][ni]);
        }
        __syncthreads();
    }
    #pragma unroll
    for (int mi = 0; mi < 4; mi++)
        #pragma unroll
        for (int ni = 0; ni < 2; ni++)
            wmma::store_matrix_sync(C + (size_t)(bm + wm + mi * 16) * 256 + bn + wn + ni * 16,
                                    acc[mi][ni], 256, wmma::mem_row_major);
}

// -------- elementwise bias + gelu (after W1 gemm) --------
__global__ void bias_gelu(float* __restrict__ x, const float* __restrict__ bias) {
    size_t i = (size_t)blockIdx.x * blockDim.x + threadIdx.x;
    int c = (int)(i & 255);
    x[i] = gelu_tanh(x[i] + bias[c]);
}

// -------- flash attention with tf32 wmma for S=QK^T and O=PV --------
// grid (NQ/64=8, H, B), block 256
// dyn smem: Qs[64][72] | Ks[64][72](=Os) | Vs[64][72] | Ps[64][72]
#define FA_LD 72
#define ATTN_SMEM (4 * 64 * FA_LD * sizeof(float))

__global__ void flash_attn(const float* __restrict__ Qp, const float* __restrict__ Kp,
                           const float* __restrict__ Vp, const float* __restrict__ maskl,
                           float* __restrict__ ctx) {
    extern __shared__ float sm[];
    float* Qs = sm;                    // [qr][d]
    float* Ks = Qs + 64 * FA_LD;       // [kr][d]  (aliased as Os after PV mma)
    float* Vs = Ks + 64 * FA_LD;       // [kr][d]
    float* Ps = Vs + 64 * FA_LD;       // [qr][kr] scores / probs
    float* Os = Ks;                    // alias

    int t = threadIdx.x;
    int tx = t & 15, ty = t >> 4;
    int w  = t >> 5;
    int qb = blockIdx.x, h = blockIdx.y, b = blockIdx.z;

    int wm  = (w >> 1) * 16;           // S/O row tile for this warp
    int wn0 = (w & 1) * 32;            // S/O col half

    // loader mapping: 64x64 tile, each thread 4 rows x float4
    int lc = (t & 15) * 4, lr = t >> 4;

    // ---- load Q tile (row-major, tf32) ----
    #pragma unroll
    for (int i = 0; i < 4; i++) {
        int row = lr + i * 16;
        float4 v = *(const float4*)(Qp + ((size_t)(b * NQ_) + qb * 64 + row) * D_ + h * DH_ + lc);
        Qs[row * FA_LD + lc + 0] = to_tf32(v.x);
        Qs[row * FA_LD + lc + 1] = to_tf32(v.y);
        Qs[row * FA_LD + lc + 2] = to_tf32(v.z);
        Qs[row * FA_LD + lc + 3] = to_tf32(v.w);
    }

    float acc[4][4] = {};
    float run_m[4], run_l[4];
    #pragma unroll
    for (int i = 0; i < 4; i++) { run_m[i] = -1e30f; run_l[i] = 0.f; }

    for (int kt = 0; kt < NK_ / 64; kt++) {
        __syncthreads();   // Os consumed (prev iter) / Qs ready (first iter)

        // ---- load K, V tiles (row-major, tf32) ----
        #pragma unroll
        for (int i = 0; i < 4; i++) {
            int row = lr + i * 16;
            size_t g = ((size_t)(b * NK_) + kt * 64 + row) * D_ + h * DH_ + lc;
            float4 kv = *(const float4*)(Kp + g);
            Ks[row * FA_LD + lc + 0] = to_tf32(kv.x);
            Ks[row * FA_LD + lc + 1] = to_tf32(kv.y);
            Ks[row * FA_LD + lc + 2] = to_tf32(kv.z);
            Ks[row * FA_LD + lc + 3] = to_tf32(kv.w);
            float4 vv = *(const float4*)(Vp + g);
            Vs[row * FA_LD + lc + 0] = to_tf32(vv.x);
            Vs[row * FA_LD + lc + 1] = to_tf32(vv.y);
            Vs[row * FA_LD + lc + 2] = to_tf32(vv.z);
            Vs[row * FA_LD + lc + 3] = to_tf32(vv.w);
        }
        __syncthreads();

        // ---- S = Q . K^T (wmma, K as col-major B) ----
        {
            wmma::fragment<wmma::accumulator, 16, 16, 8, float> sfr[2];
            wmma::fill_fragment(sfr[0], 0.f);
            wmma::fill_fragment(sfr[1], 0.f);
            #pragma unroll
            for (int ks = 0; ks < 8; ks++) {
                wmma::fragment<wmma::matrix_a, 16, 16, 8, wmma::precision::tf32, wmma::row_major> a;
                wmma::load_matrix_sync(a, &Qs[wm * FA_LD + ks * 8], FA_LD);
                #pragma unroll
                for (int ni = 0; ni < 2; ni++) {
                    wmma::fragment<wmma::matrix_b, 16, 16, 8, wmma::precision::tf32, wmma::col_major> bk;
                    wmma::load_matrix_sync(bk, &Ks[(wn0 + ni * 16) * FA_LD + ks * 8], FA_LD);
                    wmma::mma_sync(sfr[ni], a, bk, sfr[ni]);
                }
            }
            #pragma unroll
            for (int ni = 0; ni < 2; ni++)
                wmma::store_matrix_sync(&Ps[wm * FA_LD + wn0 + ni * 16], sfr[ni], FA_LD,
                                        wmma::mem_row_major);
        }
        __syncthreads();

        // ---- online softmax on Ps (mask from gmem) ----
        #pragma unroll
        for (int i = 0; i < 4; i++) {
            int row = ty * 4 + i;
            float4 sv = *(const float4*)&Ps[row * FA_LD + tx * 4];
            float4 mv = *(const float4*)(maskl + (size_t)(qb * 64 + row) * NK_ + kt * 64 + tx * 4);
            float s0 = mv.x > 0.5f ? sv.x * SCALE_ : -1e9f;
            float s1 = mv.y > 0.5f ? sv.y * SCALE_ : -1e9f;
            float s2 = mv.z > 0.5f ? sv.z * SCALE_ : -1e9f;
            float s3 = mv.w > 0.5f ? sv.w * SCALE_ : -1e9f;
            float m = fmaxf(fmaxf(s0, s1), fmaxf(s2, s3));
            #pragma unroll
            for (int o = 8; o; o >>= 1) m = fmaxf(m, __shfl_xor_sync(0xffffffffu, m, o));
            float nm  = fmaxf(run_m[i], m);
            float fac = __expf(run_m[i] - nm);
            s0 = __expf(s0 - nm); s1 = __expf(s1 - nm);
            s2 = __expf(s2 - nm); s3 = __expf(s3 - nm);
            float sum = s0 + s1 + s2 + s3;
            #pragma unroll
            for (int o = 8; o; o >>= 1) sum += __shfl_xor_sync(0xffffffffu, sum, o);
            run_l[i] = run_l[i] * fac + sum;
            run_m[i] = nm;
            acc[i][0] *= fac; acc[i][1] *= fac; acc[i][2] *= fac; acc[i][3] *= fac;
            *(float4*)&Ps[row * FA_LD + tx * 4] =
                make_float4(to_tf32(s0), to_tf32(s1), to_tf32(s2), to_tf32(s3));
        }
        __syncthreads();

        // ---- dO = P . V (wmma), store to Os (aliases Ks) ----
        {
            wmma::fragment<wmma::accumulator, 16, 16, 8, float> ofr[2];
            wmma::fill_fragment(ofr[0], 0.f);
            wmma::fill_fragment(ofr[1], 0.f);
            #pragma unroll
            for (int ks = 0; ks < 8; ks++) {
                wmma::fragment<wmma::matrix_a, 16, 16, 8, wmma::precision::tf32, wmma::row_major> a;
                wmma::load_matrix_sync(a, &Ps[wm * FA_LD + ks * 8], FA_LD);
                #pragma unroll
                for (int ni = 0; ni < 2; ni++) {
                    wmma::fragment<wmma::matrix_b, 16, 16, 8, wmma::precision::tf32, wmma::row_major> bv;
                    wmma::load_matrix_sync(bv, &Vs[(ks * 8) * FA_LD + wn0 + ni * 16], FA_LD);
                    wmma::mma_sync(ofr[ni], a, bv, ofr[ni]);
                }
            }
            #pragma unroll
            for (int ni = 0; ni < 2; ni++)
                wmma::store_matrix_sync(&Os[wm * FA_LD + wn0 + ni * 16], ofr[ni], FA_LD,
                                        wmma::mem_row_major);
        }
        __syncthreads();

        // ---- scalar accumulate (acc already rescaled by fac) ----
        #pragma unroll
        for (int i = 0; i < 4; i++) {
            float4 dv = *(const float4*)&Os[(ty * 4 + i) * FA_LD + tx * 4];
            acc[i][0] += dv.x; acc[i][1] += dv.y; acc[i][2] += dv.z; acc[i][3] += dv.w;
        }
    }

    // ---- epilogue: ctx = acc / run_l ----
    #pragma unroll
    for (int i = 0; i < 4; i++) {
        float inv = 1.f / run_l[i];
        float4 o = make_float4(acc[i][0] * inv, acc[i][1] * inv, acc[i][2] * inv, acc[i][3] * inv);
        *(float4*)(ctx + ((size_t)(b * NQ_) + qb * 64 + ty * 4 + i) * D_ + h * DH_ + tx * 4) = o;
    }
}

// -------- plain LayerNorm over rows --------
__global__ void ln_kernel(const float* __restrict__ in, const float* __restrict__ sc,
                          const float* __restrict__ bi, float* __restrict__ out) {
    __shared__ float red[8];
    int row = blockIdx.x, t = threadIdx.x;
    float x  = in[(size_t)row * D_ + t];
    float m  = block_sum256(x, red) * (1.f / D_);
    float xc = x - m;
    float v  = block_sum256(xc * xc, red) * (1.f / D_);
    out[(size_t)row * D_ + t] = xc * rsqrtf(v + 1e-5f) * sc[t] + bi[t];
}

// -------- residual add (+b2) + LN(outer) + LN(eff) fused --------
__global__ void add_double_ln(const float* __restrict__ hb, const float* __restrict__ fb,
                              const float* __restrict__ b2,
                              const float* __restrict__ os, const float* __restrict__ ob,
                              const float* __restrict__ es, const float* __restrict__ eb,
                              float* __restrict__ out) {
    __shared__ float red[8];
    int row = blockIdx.x, t = threadIdx.x;
    float x  = hb[(size_t)row * D_ + t] + fb[(size_t)row * D_ + t] + b2[t];
    float m  = block_sum256(x, red) * (1.f / D_);
    float xc = x - m;
    float v  = block_sum256(xc * xc, red) * (1.f / D_);
    float u  = xc * rsqrtf(v + 1e-5f) * os[t] + ob[t];
    float m2 = block_sum256(u, red) * (1.f / D_);
    float uc = u - m2;
    float v2 = block_sum256(uc * uc, red) * (1.f / D_);
    out[(size_t)row * D_ + t] = uc * rsqrtf(v2 + 1e-5f) * es[t] + eb[t];
}

// -------- scatter add (atomic: handles duplicate indices) --------
__global__ void scatter_add(const float* __restrict__ res, const int* __restrict__ qidx,
                            float* __restrict__ out) {
    int i = blockIdx.x, b = blockIdx.y, t = threadIdx.x;
    int id = qidx[i];
    float v = res[((size_t)(b * NQ_ + i)) * D_ + t];
    atomicAdd(&g_U[((size_t)b * NS_ + id) * D_ + t], v);
    atomicAdd(&out[((size_t)b * NS_ + id) * D_ + t], v);
}

// -------- host launcher --------
extern "C" void kernel_launch(void* const* d_in, const int* in_sizes, int n_in,
                              void* d_out, int out_size) {
    const float* upd   = (const float*)d_in[0];
    const float* emb   = (const float*)d_in[1];
    const float* maskl = (const float*)d_in[2];
    const float* Wq    = (const float*)d_in[3];
    const float* Wk    = (const float*)d_in[4];
    const float* Wv    = (const float*)d_in[5];
    const float* Wo    = (const float*)d_in[6];
    const float* W1    = (const float*)d_in[7];
    const float* b1    = (const float*)d_in[8];
    const float* W2    = (const float*)d_in[9];
    const float* b2    = (const float*)d_in[10];
    const float* sys_s = (const float*)d_in[11];
    const float* sys_b = (const float*)d_in[12];
    const float* eff_s = (const float*)d_in[13];
    const float* eff_b = (const float*)d_in[14];
    const float* in_s  = (const float*)d_in[15];
    const float* in_b  = (const float*)d_in[16];
    const float* out_s = (const float*)d_in[17];
    const float* out_b = (const float*)d_in[18];
    const int*   qidx  = (const int*)d_in[19];
    const int*   kidx  = (const int*)d_in[20];
    float* out = (float*)d_out;

    float *qb, *kb, *Qp, *Kp, *Vp, *ctx, *hb, *t1, *fb, *res;
    cudaGetSymbolAddress((void**)&qb,  g_q);
    cudaGetSymbolAddress((void**)&kb,  g_k);
    cudaGetSymbolAddress((void**)&Qp,  g_Qp);
    cudaGetSymbolAddress((void**)&Kp,  g_Kp);
    cudaGetSymbolAddress((void**)&Vp,  g_Vp);
    cudaGetSymbolAddress((void**)&ctx, g_ctx);
    cudaGetSymbolAddress((void**)&hb,  g_h);
    cudaGetSymbolAddress((void**)&t1,  g_t1);
    cudaGetSymbolAddress((void**)&fb,  g_f);
    cudaGetSymbolAddress((void**)&res, g_res);

    cudaFuncSetAttribute(flash_attn, cudaFuncAttributeMaxDynamicSharedMemorySize,
                         (int)ATTN_SMEM);

    // init: copy U, zero output
    init_kernel<<<(B_ * NS_ * D_) / 256, 256>>>(upd, out);

    for (int l = 0; l < L_; l++) {
        gather_ln<<<dim3(NQ_, B_), 256>>>(emb, qidx + l * NQ_, sys_s, sys_b, qb, NQ_);
        gather_ln<<<dim3(NK_, B_), 256>>>(emb, kidx + l * NK_, sys_s, sys_b, kb, NK_);

        gemm_tc<<<dim3(2, MQ / 128), 256>>>(qb, Wq, Qp);
        gemm_tc<<<dim3(2, MK / 128), 256>>>(kb, Wk, Kp);
        gemm_tc<<<dim3(2, MK / 128), 256>>>(kb, Wv, Vp);

        flash_attn<<<dim3(NQ_ / 64, H_, B_), 256, ATTN_SMEM>>>(
            Qp, Kp, Vp, maskl + (size_t)l * NQ_ * NK_, ctx);

        gemm_tc<<<dim3(2, MQ / 128), 256>>>(ctx, Wo, t1);
        ln_kernel<<<MQ, 256>>>(t1, in_s, in_b, hb);

        gemm_tc<<<dim3(2, MQ / 128), 256>>>(hb, W1, t1);
        bias_gelu<<<(MQ * D_) / 256, 256>>>(t1, b1);
        gemm_tc<<<dim3(2, MQ / 128), 256>>>(t1, W2, fb);

        add_double_ln<<<MQ, 256>>>(hb, fb, b2, out_s, out_b, eff_s, eff_b, res);

        scatter_add<<<dim3(NQ_, B_), 256>>>(res, qidx + l * NQ_, out);
    }
}

// round 9
// speedup vs baseline: 10.0266x; 1.6548x over previous
#include <cuda_runtime.h>
#include <cuda_bf16.h>
#include <mma.h>
#include <math.h>

using namespace nvcuda;

// Problem constants
#define B_   32
#define NS_  4096
#define D_   256
#define H_   4
#define L_   6
#define NQ_  512
#define NK_  1024
#define DH_  64
#define SCALE_ 0.125f

#define MQ (B_*NQ_)   // 16384 rows
#define MK (B_*NK_)   // 32768 rows

// -------- persistent device scratch (static, no allocation) --------
__device__ float g_U  [(size_t)B_*NS_*D_];
__device__ float g_q  [(size_t)MQ*D_];
__device__ float g_k  [(size_t)MK*D_];
__device__ float g_Qp [(size_t)MQ*D_];
__device__ float g_Kp [(size_t)MK*D_];
__device__ float g_Vp [(size_t)MK*D_];
__device__ float g_ctx[(size_t)MQ*D_];
__device__ float g_h  [(size_t)MQ*D_];
__device__ float g_t1 [(size_t)MQ*D_];
__device__ float g_f  [(size_t)MQ*D_];
__device__ float g_res[(size_t)MQ*D_];
__device__ float g_Wr [6 * 256 * 256];                     // tf32-rounded weights
__device__ unsigned long long g_mb[(size_t)L_*NQ_*16];     // mask bitmaps

// -------- helpers --------
__device__ __forceinline__ float to_tf32(float x) { return wmma::__float_to_tf32(x); }

__device__ __forceinline__ float block_sum256(float v, float* s8) {
    #pragma unroll
    for (int o = 16; o; o >>= 1) v += __shfl_xor_sync(0xffffffffu, v, o);
    __syncthreads();
    if ((threadIdx.x & 31) == 0) s8[threadIdx.x >> 5] = v;
    __syncthreads();
    float tot = 0.f;
    #pragma unroll
    for (int i = 0; i < 8; i++) tot += s8[i];
    return tot;
}

__device__ __forceinline__ float gelu_tanh(float x) {
    float x3 = x * x * x;
    float t = tanhf(0.7978845608028654f * (x + 0.044715f * x3));
    return 0.5f * x * (1.f + t);
}

__device__ __forceinline__ void cp16(void* dst, const void* src) {
    unsigned s = (unsigned)__cvta_generic_to_shared(dst);
    asm volatile("cp.async.cg.shared.global [%0], [%1], 16;\n" :: "r"(s), "l"(src));
}
#define CP_COMMIT() asm volatile("cp.async.commit_group;\n")
#define CP_WAIT(n)  asm volatile("cp.async.wait_group %0;\n" :: "n"(n))

#define MMA_TF32(c, a0, a1, a2, a3, b0v, b1v) \
    asm volatile("mma.sync.aligned.m16n8k8.row.col.f32.tf32.tf32.f32 " \
        "{%0,%1,%2,%3}, {%4,%5,%6,%7}, {%8,%9}, {%0,%1,%2,%3};" \
        : "+f"(c[0]), "+f"(c[1]), "+f"(c[2]), "+f"(c[3]) \
        : "r"(a0), "r"(a1), "r"(a2), "r"(a3), "r"(b0v), "r"(b1v))

// -------- prep kernels (once per launch, graph-captured) --------
__global__ void init_kernel(const float* __restrict__ upd, float* __restrict__ out) {
    size_t i = (size_t)blockIdx.x * blockDim.x + threadIdx.x;
    g_U[i] = upd[i];
    out[i] = 0.f;
}

__global__ void round_copy(const float* __restrict__ src, float* __restrict__ dst) {
    size_t i = (size_t)blockIdx.x * blockDim.x + threadIdx.x;
    dst[i] = to_tf32(src[i]);
}

// one warp per 64-bit word: word w <-> maskl[w*64 .. w*64+63]
__global__ void mask_bits_kernel(const float* __restrict__ maskl) {
    size_t gt = (size_t)blockIdx.x * blockDim.x + threadIdx.x;
    size_t wid = gt >> 5;
    int lane = (int)(gt & 31);
    if (wid >= (size_t)L_ * NQ_ * 16) return;
    const float* src = maskl + wid * 64;
    unsigned lo = __ballot_sync(0xffffffffu, src[lane]      > 0.5f);
    unsigned hi = __ballot_sync(0xffffffffu, src[lane + 32] > 0.5f);
    if (lane == 0) g_mb[wid] = (unsigned long long)lo | ((unsigned long long)hi << 32);
}

// -------- gather + LayerNorm(sys), tf32-rounded store --------
__global__ void gather_ln(const float* __restrict__ emb, const int* __restrict__ idx,
                          const float* __restrict__ sc, const float* __restrict__ bi,
                          float* __restrict__ out, int n) {
    __shared__ float red[8];
    int i = blockIdx.x, b = blockIdx.y, t = threadIdx.x;
    int id = idx[i];
    float x = emb[(size_t)id * D_ + t] + g_U[((size_t)b * NS_ + id) * D_ + t];
    float m  = block_sum256(x, red) * (1.f / D_);
    float xc = x - m;
    float v  = block_sum256(xc * xc, red) * (1.f / D_);
    out[((size_t)(b * n + i)) * D_ + t] = to_tf32(xc * rsqrtf(v + 1e-5f) * sc[t] + bi[t]);
}

// -------- tf32 tensor-core GEMM, cp.async 2-stage --------
// grid (2, M/128), block 256; A,W must be tf32-pre-rounded
#define AS_LD 40
#define BS_LD 136
#define AS_STG (128 * AS_LD)
#define BS_STG (32 * BS_LD)
#define GEMM_SMEM ((2 * AS_STG + 2 * BS_STG) * sizeof(float))

template<int ROUND>
__global__ __launch_bounds__(256, 2)
void gemm_tc(const float* __restrict__ A, const float* __restrict__ W,
             float* __restrict__ C) {
    extern __shared__ float sm[];
    float* As = sm;
    float* Bs = sm + 2 * AS_STG;
    int t = threadIdx.x, w = t >> 5;
    int bm = blockIdx.y * 128, bn = blockIdx.x * 128;
    int wm = (w >> 2) * 64, wn = (w & 3) * 32;

    wmma::fragment<wmma::accumulator, 16, 16, 8, float> acc[4][2];
    #pragma unroll
    for (int mi = 0; mi < 4; mi++)
        #pragma unroll
        for (int ni = 0; ni < 2; ni++) wmma::fill_fragment(acc[mi][ni], 0.f);

    auto load_stage = [&](int ks, int bf) {
        int k0 = ks * 32;
        #pragma unroll
        for (int i = 0; i < 4; i++) {
            int idx = t + i * 256;
            {   int row = idx >> 3, c4 = (idx & 7) * 4;
                cp16(As + bf * AS_STG + row * AS_LD + c4,
                     A + (size_t)(bm + row) * 256 + k0 + c4); }
            {   int row = idx >> 5, c4 = (idx & 31) * 4;
                cp16(Bs + bf * BS_STG + row * BS_LD + c4,
                     W + (size_t)(k0 + row) * 256 + bn + c4); }
        }
    };

    load_stage(0, 0); CP_COMMIT();
    int buf = 0;
    for (int ks8 = 0; ks8 < 8; ks8++) {
        if (ks8 < 7) { load_stage(ks8 + 1, buf ^ 1); CP_COMMIT(); CP_WAIT(1); }
        else CP_WAIT(0);
        __syncthreads();
        const float* Ab = As + buf * AS_STG;
        const float* Bb = Bs + buf * BS_STG;
        #pragma unroll
        for (int ks = 0; ks < 4; ks++) {
            wmma::fragment<wmma::matrix_a, 16, 16, 8, wmma::precision::tf32, wmma::row_major> a[4];
            wmma::fragment<wmma::matrix_b, 16, 16, 8, wmma::precision::tf32, wmma::row_major> bfr[2];
            #pragma unroll
            for (int mi = 0; mi < 4; mi++)
                wmma::load_matrix_sync(a[mi], &Ab[(wm + mi * 16) * AS_LD + ks * 8], AS_LD);
            #pragma unroll
            for (int ni = 0; ni < 2; ni++)
                wmma::load_matrix_sync(bfr[ni], &Bb[(ks * 8) * BS_LD + wn + ni * 16], BS_LD);
            #pragma unroll
            for (int mi = 0; mi < 4; mi++)
                #pragma unroll
                for (int ni = 0; ni < 2; ni++)
                    wmma::mma_sync(acc[mi][ni], a[mi], bfr[ni], acc[mi][ni]);
        }
        __syncthreads();
        buf ^= 1;
    }
    #pragma unroll
    for (int mi = 0; mi < 4; mi++)
        #pragma unroll
        for (int ni = 0; ni < 2; ni++) {
            if (ROUND) {
                #pragma unroll
                for (int e = 0; e < acc[mi][ni].num_elements; e++)
                    acc[mi][ni].x[e] = to_tf32(acc[mi][ni].x[e]);
            }
            wmma::store_matrix_sync(C + (size_t)(bm + wm + mi * 16) * 256 + bn + wn + ni * 16,
                                    acc[mi][ni], 256, wmma::mem_row_major);
        }
}

// -------- elementwise bias + gelu (tf32-rounded: feeds W2 gemm) --------
__global__ void bias_gelu(float* __restrict__ x, const float* __restrict__ bias) {
    size_t i = (size_t)blockIdx.x * blockDim.x + threadIdx.x;
    int c = (int)(i & 255);
    x[i] = to_tf32(gelu_tanh(x[i] + bias[c]));
}

// -------- flash attention: mma.sync m16n8k8 tf32, register softmax --------
// grid (NQ/128=4, H, B), block 256 (8 warps, warp = 16 q rows), K-tiles of 64
#define KS_LD 68
#define VS_LD 72
#define KS_STG (64 * KS_LD)
#define VS_STG (64 * VS_LD)
#define PW_STG (16 * VS_LD)
#define FA_SMEM ((2 * KS_STG + 2 * VS_STG + 8 * PW_STG) * sizeof(float))

__global__ __launch_bounds__(256, 1)
void flash_attn(const float* __restrict__ Qp, const float* __restrict__ Kp,
                const float* __restrict__ Vp, const unsigned long long* __restrict__ mb,
                float* __restrict__ ctx) {
    extern __shared__ float sm[];
    float* Ks0 = sm;
    float* Vs0 = sm + 2 * KS_STG;
    int t = threadIdx.x, lane = t & 31, w = t >> 5;
    int gid = lane >> 2, tid4 = lane & 3;
    int qb = blockIdx.x, h = blockIdx.y, b = blockIdx.z;
    float* Pw = sm + 2 * KS_STG + 2 * VS_STG + w * PW_STG;

    int qrow = qb * 128 + w * 16 + gid;                       // row in [0,NQ)
    size_t qg0 = ((size_t)b * NQ_ + qrow) * D_ + h * DH_;

    // ---- preload Q fragments (Q is tf32-pre-rounded) ----
    unsigned qa[8][4];
    #pragma unroll
    for (int kc = 0; kc < 8; kc++) {
        qa[kc][0] = __float_as_uint(Qp[qg0 + kc * 8 + tid4]);
        qa[kc][1] = __float_as_uint(Qp[qg0 + (size_t)8 * D_ + kc * 8 + tid4]);
        qa[kc][2] = __float_as_uint(Qp[qg0 + kc * 8 + tid4 + 4]);
        qa[kc][3] = __float_as_uint(Qp[qg0 + (size_t)8 * D_ + kc * 8 + tid4 + 4]);
    }

    float o[8][4];
    #pragma unroll
    for (int j = 0; j < 8; j++) { o[j][0] = o[j][1] = o[j][2] = o[j][3] = 0.f; }
    float run_m0 = -1e30f, run_m1 = -1e30f, run_l0 = 0.f, run_l1 = 0.f;

    auto load_stage = [&](int kt2, int bf) {
        const float* kg = Kp + ((size_t)b * NK_ + kt2 * 64) * D_ + h * DH_;
        const float* vg = Vp + ((size_t)b * NK_ + kt2 * 64) * D_ + h * DH_;
        float* kd = Ks0 + bf * KS_STG;
        float* vd = Vs0 + bf * VS_STG;
        #pragma unroll
        for (int i = 0; i < 4; i++) {
            int idx = t + i * 256;
            int row = idx >> 4, c4 = (idx & 15) * 4;
            cp16(kd + row * KS_LD + c4, kg + (size_t)row * D_ + c4);
            cp16(vd + row * VS_LD + c4, vg + (size_t)row * D_ + c4);
        }
    };

    load_stage(0, 0); CP_COMMIT();
    int buf = 0;
    for (int kt = 0; kt < 16; kt++) {
        if (kt < 15) { load_stage(kt + 1, buf ^ 1); CP_COMMIT(); CP_WAIT(1); }
        else CP_WAIT(0);
        __syncthreads();
        const float* Kb = Ks0 + buf * KS_STG;
        const float* Vb = Vs0 + buf * VS_STG;

        // ---- S = Q . K^T (register accumulators, C-layout) ----
        float s[8][4];
        #pragma unroll
        for (int j = 0; j < 8; j++) { s[j][0] = s[j][1] = s[j][2] = s[j][3] = 0.f; }
        #pragma unroll
        for (int kc = 0; kc < 8; kc++) {
            #pragma unroll
            for (int j = 0; j < 8; j++) {
                unsigned b0 = __float_as_uint(Kb[(j * 8 + gid) * KS_LD + kc * 8 + tid4]);
                unsigned b1 = __float_as_uint(Kb[(j * 8 + gid) * KS_LD + kc * 8 + tid4 + 4]);
                MMA_TF32(s[j], qa[kc][0], qa[kc][1], qa[kc][2], qa[kc][3], b0, b1);
            }
        }

        // ---- mask (bitmap) + online softmax in registers ----
        unsigned long long w0 = mb[(size_t)qrow * 16 + kt];
        unsigned long long w1 = mb[(size_t)(qrow + 8) * 16 + kt];
        float mx0 = -1e30f, mx1 = -1e30f;
        #pragma unroll
        for (int j = 0; j < 8; j++) {
            int sh = j * 8 + 2 * tid4;
            s[j][0] = ((w0 >> sh) & 1ull)       ? s[j][0] * SCALE_ : -1e9f;
            s[j][1] = ((w0 >> (sh + 1)) & 1ull) ? s[j][1] * SCALE_ : -1e9f;
            s[j][2] = ((w1 >> sh) & 1ull)       ? s[j][2] * SCALE_ : -1e9f;
            s[j][3] = ((w1 >> (sh + 1)) & 1ull) ? s[j][3] * SCALE_ : -1e9f;
            mx0 = fmaxf(mx0, fmaxf(s[j][0], s[j][1]));
            mx1 = fmaxf(mx1, fmaxf(s[j][2], s[j][3]));
        }
        mx0 = fmaxf(mx0, __shfl_xor_sync(0xffffffffu, mx0, 1));
        mx0 = fmaxf(mx0, __shfl_xor_sync(0xffffffffu, mx0, 2));
        mx1 = fmaxf(mx1, __shfl_xor_sync(0xffffffffu, mx1, 1));
        mx1 = fmaxf(mx1, __shfl_xor_sync(0xffffffffu, mx1, 2));
        float nm0 = fmaxf(run_m0, mx0), nm1 = fmaxf(run_m1, mx1);
        float fac0 = __expf(run_m0 - nm0), fac1 = __expf(run_m1 - nm1);
        run_m0 = nm0; run_m1 = nm1;
        float sum0 = 0.f, sum1 = 0.f;
        #pragma unroll
        for (int j = 0; j < 8; j++) {
            s[j][0] = __expf(s[j][0] - nm0); s[j][1] = __expf(s[j][1] - nm0);
            s[j][2] = __expf(s[j][2] - nm1); s[j][3] = __expf(s[j][3] - nm1);
            sum0 += s[j][0] + s[j][1]; sum1 += s[j][2] + s[j][3];
            *(float2*)&Pw[gid * VS_LD + j * 8 + 2 * tid4] =
                make_float2(to_tf32(s[j][0]), to_tf32(s[j][1]));
            *(float2*)&Pw[(gid + 8) * VS_LD + j * 8 + 2 * tid4] =
                make_float2(to_tf32(s[j][2]), to_tf32(s[j][3]));
        }
        sum0 += __shfl_xor_sync(0xffffffffu, sum0, 1);
        sum0 += __shfl_xor_sync(0xffffffffu, sum0, 2);
        sum1 += __shfl_xor_sync(0xffffffffu, sum1, 1);
        sum1 += __shfl_xor_sync(0xffffffffu, sum1, 2);
        run_l0 = run_l0 * fac0 + sum0;
        run_l1 = run_l1 * fac1 + sum1;
        #pragma unroll
        for (int j = 0; j < 8; j++) { o[j][0] *= fac0; o[j][1] *= fac0; o[j][2] *= fac1; o[j][3] *= fac1; }
        __syncwarp();

        // ---- O += P . V ----
        #pragma unroll
        for (int kc = 0; kc < 8; kc++) {
            unsigned pa0 = __float_as_uint(Pw[gid * VS_LD + kc * 8 + tid4]);
            unsigned pa1 = __float_as_uint(Pw[(gid + 8) * VS_LD + kc * 8 + tid4]);
            unsigned pa2 = __float_as_uint(Pw[gid * VS_LD + kc * 8 + tid4 + 4]);
            unsigned pa3 = __float_as_uint(Pw[(gid + 8) * VS_LD + kc * 8 + tid4 + 4]);
            #pragma unroll
            for (int j2 = 0; j2 < 8; j2++) {
                unsigned b0 = __float_as_uint(Vb[(kc * 8 + tid4) * VS_LD + j2 * 8 + gid]);
                unsigned b1 = __float_as_uint(Vb[(kc * 8 + tid4 + 4) * VS_LD + j2 * 8 + gid]);
                MMA_TF32(o[j2], pa0, pa1, pa2, pa3, b0, b1);
            }
        }
        __syncthreads();
        buf ^= 1;
    }

    // ---- epilogue: ctx = O / l (tf32-rounded: feeds Wo gemm) ----
    float inv0 = 1.f / run_l0, inv1 = 1.f / run_l1;
    float* c0 = ctx + qg0;
    #pragma unroll
    for (int j2 = 0; j2 < 8; j2++) {
        *(float2*)&c0[j2 * 8 + 2 * tid4] =
            make_float2(to_tf32(o[j2][0] * inv0), to_tf32(o[j2][1] * inv0));
        *(float2*)&c0[(size_t)8 * D_ + j2 * 8 + 2 * tid4] =
            make_float2(to_tf32(o[j2][2] * inv1), to_tf32(o[j2][3] * inv1));
    }
}

// -------- plain LayerNorm (tf32-rounded: feeds W1 gemm; also residual) --------
__global__ void ln_kernel(const float* __restrict__ in, const float* __restrict__ sc,
                          const float* __restrict__ bi, float* __restrict__ out) {
    __shared__ float red[8];
    int row = blockIdx.x, t = threadIdx.x;
    float x  = in[(size_t)row * D_ + t];
    float m  = block_sum256(x, red) * (1.f / D_);
    float xc = x - m;
    float v  = block_sum256(xc * xc, red) * (1.f / D_);
    out[(size_t)row * D_ + t] = to_tf32(xc * rsqrtf(v + 1e-5f) * sc[t] + bi[t]);
}

// -------- residual add (+b2) + LN(outer) + LN(eff) fused --------
__global__ void add_double_ln(const float* __restrict__ hb, const float* __restrict__ fb,
                              const float* __restrict__ b2,
                              const float* __restrict__ os, const float* __restrict__ ob,
                              const float* __restrict__ es, const float* __restrict__ eb,
                              float* __restrict__ out) {
    __shared__ float red[8];
    int row = blockIdx.x, t = threadIdx.x;
    float x  = hb[(size_t)row * D_ + t] + fb[(size_t)row * D_ + t] + b2[t];
    float m  = block_sum256(x, red) * (1.f / D_);
    float xc = x - m;
    float v  = block_sum256(xc * xc, red) * (1.f / D_);
    float u  = xc * rsqrtf(v + 1e-5f) * os[t] + ob[t];
    float m2 = block_sum256(u, red) * (1.f / D_);
    float uc = u - m2;
    float v2 = block_sum256(uc * uc, red) * (1.f / D_);
    out[(size_t)row * D_ + t] = uc * rsqrtf(v2 + 1e-5f) * es[t] + eb[t];
}

// -------- scatter add (atomic: handles duplicate indices) --------
__global__ void scatter_add(const float* __restrict__ res, const int* __restrict__ qidx,
                            float* __restrict__ out) {
    int i = blockIdx.x, b = blockIdx.y, t = threadIdx.x;
    int id = qidx[i];
    float v = res[((size_t)(b * NQ_ + i)) * D_ + t];
    atomicAdd(&g_U[((size_t)b * NS_ + id) * D_ + t], v);
    atomicAdd(&out[((size_t)b * NS_ + id) * D_ + t], v);
}

// -------- host launcher --------
extern "C" void kernel_launch(void* const* d_in, const int* in_sizes, int n_in,
                              void* d_out, int out_size) {
    const float* upd   = (const float*)d_in[0];
    const float* emb   = (const float*)d_in[1];
    const float* maskl = (const float*)d_in[2];
    const float* Wq    = (const float*)d_in[3];
    const float* Wk    = (const float*)d_in[4];
    const float* Wv    = (const float*)d_in[5];
    const float* Wo    = (const float*)d_in[6];
    const float* W1    = (const float*)d_in[7];
    const float* b1    = (const float*)d_in[8];
    const float* W2    = (const float*)d_in[9];
    const float* b2    = (const float*)d_in[10];
    const float* sys_s = (const float*)d_in[11];
    const float* sys_b = (const float*)d_in[12];
    const float* eff_s = (const float*)d_in[13];
    const float* eff_b = (const float*)d_in[14];
    const float* in_s  = (const float*)d_in[15];
    const float* in_b  = (const float*)d_in[16];
    const float* out_s = (const float*)d_in[17];
    const float* out_b = (const float*)d_in[18];
    const int*   qidx  = (const int*)d_in[19];
    const int*   kidx  = (const int*)d_in[20];
    float* out = (float*)d_out;

    float *qb, *kb, *Qp, *Kp, *Vp, *ctx, *hb, *t1, *fb, *res, *Wr;
    unsigned long long* mbp;
    cudaGetSymbolAddress((void**)&qb,  g_q);
    cudaGetSymbolAddress((void**)&kb,  g_k);
    cudaGetSymbolAddress((void**)&Qp,  g_Qp);
    cudaGetSymbolAddress((void**)&Kp,  g_Kp);
    cudaGetSymbolAddress((void**)&Vp,  g_Vp);
    cudaGetSymbolAddress((void**)&ctx, g_ctx);
    cudaGetSymbolAddress((void**)&hb,  g_h);
    cudaGetSymbolAddress((void**)&t1,  g_t1);
    cudaGetSymbolAddress((void**)&fb,  g_f);
    cudaGetSymbolAddress((void**)&res, g_res);
    cudaGetSymbolAddress((void**)&Wr,  g_Wr);
    cudaGetSymbolAddress((void**)&mbp, g_mb);

    cudaFuncSetAttribute(flash_attn, cudaFuncAttributeMaxDynamicSharedMemorySize, (int)FA_SMEM);
    cudaFuncSetAttribute(gemm_tc<0>, cudaFuncAttributeMaxDynamicSharedMemorySize, (int)GEMM_SMEM);
    cudaFuncSetAttribute(gemm_tc<1>, cudaFuncAttributeMaxDynamicSharedMemorySize, (int)GEMM_SMEM);

    // prep: copy U, zero out, round weights, build mask bitmaps
    init_kernel<<<(B_ * NS_ * D_) / 256, 256>>>(upd, out);
    const float* Ws[6] = {Wq, Wk, Wv, Wo, W1, W2};
    for (int i = 0; i < 6; i++)
        round_copy<<<(256 * 256) / 256, 256>>>(Ws[i], Wr + (size_t)i * 65536);
    mask_bits_kernel<<<(L_ * NQ_ * 16 * 32) / 256, 256>>>(maskl);

    const float* rWq = Wr;
    const float* rWk = Wr + 1 * 65536;
    const float* rWv = Wr + 2 * 65536;
    const float* rWo = Wr + 3 * 65536;
    const float* rW1 = Wr + 4 * 65536;
    const float* rW2 = Wr + 5 * 65536;

    for (int l = 0; l < L_; l++) {
        gather_ln<<<dim3(NQ_, B_), 256>>>(emb, qidx + l * NQ_, sys_s, sys_b, qb, NQ_);
        gather_ln<<<dim3(NK_, B_), 256>>>(emb, kidx + l * NK_, sys_s, sys_b, kb, NK_);

        gemm_tc<1><<<dim3(2, MQ / 128), 256, GEMM_SMEM>>>(qb, rWq, Qp);
        gemm_tc<1><<<dim3(2, MK / 128), 256, GEMM_SMEM>>>(kb, rWk, Kp);
        gemm_tc<1><<<dim3(2, MK / 128), 256, GEMM_SMEM>>>(kb, rWv, Vp);

        flash_attn<<<dim3(NQ_ / 128, H_, B_), 256, FA_SMEM>>>(
            Qp, Kp, Vp, mbp + (size_t)l * NQ_ * 16, ctx);

        gemm_tc<0><<<dim3(2, MQ / 128), 256, GEMM_SMEM>>>(ctx, rWo, t1);
        ln_kernel<<<MQ, 256>>>(t1, in_s, in_b, hb);

        gemm_tc<0><<<dim3(2, MQ / 128), 256, GEMM_SMEM>>>(hb, rW1, t1);
        bias_gelu<<<(MQ * D_) / 256, 256>>>(t1, b1);
        gemm_tc<0><<<dim3(2, MQ / 128), 256, GEMM_SMEM>>>(t1, rW2, fb);

        add_double_ln<<<MQ, 256>>>(hb, fb, b2, out_s, out_b, eff_s, eff_b, res);

        scatter_add<<<dim3(NQ_, B_), 256>>>(res, qidx + l * NQ_, out);
    }
}

// round 10
// speedup vs baseline: 14.0180x; 1.3981x over previous
#include <cuda_runtime.h>
#include <cuda_bf16.h>
#include <mma.h>
#include <math.h>

using namespace nvcuda;

// Problem constants
#define B_   32
#define NS_  4096
#define D_   256
#define H_   4
#define L_   6
#define NQ_  512
#define NK_  1024
#define DH_  64
#define SCALE_ 0.125f

#define MQ (B_*NQ_)   // 16384 rows
#define MK (B_*NK_)   // 32768 rows

// -------- persistent device scratch (static, no allocation) --------
__device__ float g_U  [(size_t)B_*NS_*D_];
__device__ float g_q  [(size_t)MQ*D_];
__device__ float g_k  [(size_t)MK*D_];
__device__ float g_Qp [(size_t)MQ*D_];
__device__ float g_Kp [(size_t)MK*D_];
__device__ float g_Vp [(size_t)MK*D_];
__device__ float g_ctx[(size_t)MQ*D_];
__device__ float g_h  [(size_t)MQ*D_];
__device__ float g_t1 [(size_t)MQ*D_];
__device__ float g_f  [(size_t)MQ*D_];
__device__ float g_Wr [6 * 256 * 256];                     // tf32-rounded weights
__device__ unsigned long long g_mb[(size_t)L_*NQ_*16];     // mask bitmaps

// -------- helpers --------
__device__ __forceinline__ float to_tf32(float x) { return wmma::__float_to_tf32(x); }

__device__ __forceinline__ float wsum(float v) {
    #pragma unroll
    for (int o = 16; o; o >>= 1) v += __shfl_xor_sync(0xffffffffu, v, o);
    return v;
}

__device__ __forceinline__ float gelu_tanh(float x) {
    float x3 = x * x * x;
    float t = tanhf(0.7978845608028654f * (x + 0.044715f * x3));
    return 0.5f * x * (1.f + t);
}

__device__ __forceinline__ void cp16(void* dst, const void* src) {
    unsigned s = (unsigned)__cvta_generic_to_shared(dst);
    asm volatile("cp.async.cg.shared.global [%0], [%1], 16;\n" :: "r"(s), "l"(src));
}
#define CP_COMMIT() asm volatile("cp.async.commit_group;\n")
#define CP_WAIT(n)  asm volatile("cp.async.wait_group %0;\n" :: "n"(n))

#define MMA_TF32(c, a0, a1, a2, a3, b0v, b1v) \
    asm volatile("mma.sync.aligned.m16n8k8.row.col.f32.tf32.tf32.f32 " \
        "{%0,%1,%2,%3}, {%4,%5,%6,%7}, {%8,%9}, {%0,%1,%2,%3};" \
        : "+f"(c[0]), "+f"(c[1]), "+f"(c[2]), "+f"(c[3]) \
        : "r"(a0), "r"(a1), "r"(a2), "r"(a3), "r"(b0v), "r"(b1v))

// -------- prep kernels --------
__global__ void init_kernel(const float* __restrict__ upd, float* __restrict__ out) {
    size_t i = (size_t)blockIdx.x * blockDim.x + threadIdx.x;
    g_U[i] = upd[i];
    out[i] = 0.f;
}

// one launch for all 6 weights; grid (64, 6), each thread one float4
__global__ void round_weights(const float* __restrict__ w0, const float* __restrict__ w1,
                              const float* __restrict__ w2, const float* __restrict__ w3,
                              const float* __restrict__ w4, const float* __restrict__ w5) {
    const float* src;
    switch (blockIdx.y) {
        case 0: src = w0; break; case 1: src = w1; break;
        case 2: src = w2; break; case 3: src = w3; break;
        case 4: src = w4; break; default: src = w5; break;
    }
    int e = (blockIdx.x * 256 + threadIdx.x) * 4;
    float4 v = *(const float4*)(src + e);
    v.x = to_tf32(v.x); v.y = to_tf32(v.y); v.z = to_tf32(v.z); v.w = to_tf32(v.w);
    *(float4*)(g_Wr + (size_t)blockIdx.y * 65536 + e) = v;
}

// one warp per 64-bit word
__global__ void mask_bits_kernel(const float* __restrict__ maskl) {
    size_t gt = (size_t)blockIdx.x * blockDim.x + threadIdx.x;
    size_t wid = gt >> 5;
    int lane = (int)(gt & 31);
    if (wid >= (size_t)L_ * NQ_ * 16) return;
    const float* src = maskl + wid * 64;
    unsigned lo = __ballot_sync(0xffffffffu, src[lane]      > 0.5f);
    unsigned hi = __ballot_sync(0xffffffffu, src[lane + 32] > 0.5f);
    if (lane == 0) g_mb[wid] = (unsigned long long)lo | ((unsigned long long)hi << 32);
}

// -------- gather + LayerNorm(sys): warp per row, tf32-rounded store --------
__global__ void gather_ln_w(const float* __restrict__ emb, const int* __restrict__ idx,
                            const float* __restrict__ sc, const float* __restrict__ bi,
                            float* __restrict__ out, int logn) {
    int gw = (blockIdx.x * blockDim.x + threadIdx.x) >> 5;
    int lane = threadIdx.x & 31;
    int i = gw & ((1 << logn) - 1), b = gw >> logn;
    int id = idx[i];
    const float* e = emb + (size_t)id * D_;
    const float* u = g_U + ((size_t)b * NS_ + id) * D_;
    int c = lane * 8;
    float4 p0 = *(const float4*)(e + c), p1 = *(const float4*)(e + c + 4);
    float4 u0 = *(const float4*)(u + c), u1 = *(const float4*)(u + c + 4);
    float x[8] = {p0.x + u0.x, p0.y + u0.y, p0.z + u0.z, p0.w + u0.w,
                  p1.x + u1.x, p1.y + u1.y, p1.z + u1.z, p1.w + u1.w};
    float s = 0.f;
    #pragma unroll
    for (int j = 0; j < 8; j++) s += x[j];
    float m = wsum(s) * (1.f / D_);
    float vs = 0.f;
    #pragma unroll
    for (int j = 0; j < 8; j++) { float d = x[j] - m; vs += d * d; }
    float r = rsqrtf(wsum(vs) * (1.f / D_) + 1e-5f);
    float4 s0 = *(const float4*)(sc + c), s1 = *(const float4*)(sc + c + 4);
    float4 b0 = *(const float4*)(bi + c), b1 = *(const float4*)(bi + c + 4);
    float* o = out + ((size_t)((b << logn) + i)) * D_ + c;
    float4 o0, o1;
    o0.x = to_tf32((x[0] - m) * r * s0.x + b0.x);
    o0.y = to_tf32((x[1] - m) * r * s0.y + b0.y);
    o0.z = to_tf32((x[2] - m) * r * s0.z + b0.z);
    o0.w = to_tf32((x[3] - m) * r * s0.w + b0.w);
    o1.x = to_tf32((x[4] - m) * r * s1.x + b1.x);
    o1.y = to_tf32((x[5] - m) * r * s1.y + b1.y);
    o1.z = to_tf32((x[6] - m) * r * s1.z + b1.z);
    o1.w = to_tf32((x[7] - m) * r * s1.w + b1.w);
    *(float4*)o = o0;
    *(float4*)(o + 4) = o1;
}

// -------- plain LayerNorm: warp per row, tf32-rounded --------
__global__ void ln_w(const float* __restrict__ in, const float* __restrict__ sc,
                     const float* __restrict__ bi, float* __restrict__ out) {
    int row = (blockIdx.x * blockDim.x + threadIdx.x) >> 5;
    int lane = threadIdx.x & 31;
    int c = lane * 8;
    const float* ir = in + (size_t)row * D_ + c;
    float4 p0 = *(const float4*)ir, p1 = *(const float4*)(ir + 4);
    float x[8] = {p0.x, p0.y, p0.z, p0.w, p1.x, p1.y, p1.z, p1.w};
    float s = 0.f;
    #pragma unroll
    for (int j = 0; j < 8; j++) s += x[j];
    float m = wsum(s) * (1.f / D_);
    float vs = 0.f;
    #pragma unroll
    for (int j = 0; j < 8; j++) { float d = x[j] - m; vs += d * d; }
    float r = rsqrtf(wsum(vs) * (1.f / D_) + 1e-5f);
    float4 s0 = *(const float4*)(sc + c), s1 = *(const float4*)(sc + c + 4);
    float4 b0 = *(const float4*)(bi + c), b1 = *(const float4*)(bi + c + 4);
    float* o = out + (size_t)row * D_ + c;
    float4 o0, o1;
    o0.x = to_tf32((x[0] - m) * r * s0.x + b0.x);
    o0.y = to_tf32((x[1] - m) * r * s0.y + b0.y);
    o0.z = to_tf32((x[2] - m) * r * s0.z + b0.z);
    o0.w = to_tf32((x[3] - m) * r * s0.w + b0.w);
    o1.x = to_tf32((x[4] - m) * r * s1.x + b1.x);
    o1.y = to_tf32((x[5] - m) * r * s1.y + b1.y);
    o1.z = to_tf32((x[6] - m) * r * s1.z + b1.z);
    o1.w = to_tf32((x[7] - m) * r * s1.w + b1.w);
    *(float4*)o = o0;
    *(float4*)(o + 4) = o1;
}

// -------- fused: residual(+b2) + LN(outer) + LN(eff) + scatter-add --------
__global__ void add_ln_scatter(const float* __restrict__ hb, const float* __restrict__ fb,
                               const float* __restrict__ b2,
                               const float* __restrict__ os, const float* __restrict__ ob,
                               const float* __restrict__ es, const float* __restrict__ eb,
                               const int* __restrict__ qidx, float* __restrict__ out) {
    int row = (blockIdx.x * blockDim.x + threadIdx.x) >> 5;   // 0..MQ-1
    int lane = threadIdx.x & 31;
    int b = row >> 9, i = row & 511;
    int c = lane * 8;
    const float* hr = hb + (size_t)row * D_ + c;
    const float* fr = fb + (size_t)row * D_ + c;
    float4 h0 = *(const float4*)hr, h1 = *(const float4*)(hr + 4);
    float4 f0 = *(const float4*)fr, f1 = *(const float4*)(fr + 4);
    float4 c0 = *(const float4*)(b2 + c), c1 = *(const float4*)(b2 + c + 4);
    float x[8] = {h0.x + f0.x + c0.x, h0.y + f0.y + c0.y, h0.z + f0.z + c0.z, h0.w + f0.w + c0.w,
                  h1.x + f1.x + c1.x, h1.y + f1.y + c1.y, h1.z + f1.z + c1.z, h1.w + f1.w + c1.w};
    float s = 0.f;
    #pragma unroll
    for (int j = 0; j < 8; j++) s += x[j];
    float m = wsum(s) * (1.f / D_);
    float vs = 0.f;
    #pragma unroll
    for (int j = 0; j < 8; j++) { float d = x[j] - m; vs += d * d; }
    float r = rsqrtf(wsum(vs) * (1.f / D_) + 1e-5f);
    float4 os0 = *(const float4*)(os + c), os1 = *(const float4*)(os + c + 4);
    float4 ob0 = *(const float4*)(ob + c), ob1 = *(const float4*)(ob + c + 4);
    float u[8];
    u[0] = (x[0] - m) * r * os0.x + ob0.x;
    u[1] = (x[1] - m) * r * os0.y + ob0.y;
    u[2] = (x[2] - m) * r * os0.z + ob0.z;
    u[3] = (x[3] - m) * r * os0.w + ob0.w;
    u[4] = (x[4] - m) * r * os1.x + ob1.x;
    u[5] = (x[5] - m) * r * os1.y + ob1.y;
    u[6] = (x[6] - m) * r * os1.z + ob1.z;
    u[7] = (x[7] - m) * r * os1.w + ob1.w;
    float s2 = 0.f;
    #pragma unroll
    for (int j = 0; j < 8; j++) s2 += u[j];
    float m2 = wsum(s2) * (1.f / D_);
    float vs2 = 0.f;
    #pragma unroll
    for (int j = 0; j < 8; j++) { float d = u[j] - m2; vs2 += d * d; }
    float r2 = rsqrtf(wsum(vs2) * (1.f / D_) + 1e-5f);
    float4 es0 = *(const float4*)(es + c), es1 = *(const float4*)(es + c + 4);
    float4 eb0 = *(const float4*)(eb + c), eb1 = *(const float4*)(eb + c + 4);
    float v[8];
    v[0] = (u[0] - m2) * r2 * es0.x + eb0.x;
    v[1] = (u[1] - m2) * r2 * es0.y + eb0.y;
    v[2] = (u[2] - m2) * r2 * es0.z + eb0.z;
    v[3] = (u[3] - m2) * r2 * es0.w + eb0.w;
    v[4] = (u[4] - m2) * r2 * es1.x + eb1.x;
    v[5] = (u[5] - m2) * r2 * es1.y + eb1.y;
    v[6] = (u[6] - m2) * r2 * es1.z + eb1.z;
    v[7] = (u[7] - m2) * r2 * es1.w + eb1.w;
    int id = qidx[i];
    size_t base = ((size_t)b * NS_ + id) * D_ + c;
    #pragma unroll
    for (int j = 0; j < 8; j++) {
        atomicAdd(&g_U[base + j], v[j]);
        atomicAdd(&out[base + j], v[j]);
    }
}

// -------- tf32 GEMM, raw mma.m16n8k8, 2-stage cp.async, 1 sync/iter --------
// grid (2, M/128), block 256; warp tile 64x32 (4 mi x 4 nj of m16n8)
// EPI: 0 plain, 1 tf32-round, 2 bias+gelu+round
#define AS_LD 40
#define BS_LD 136
#define AS_STG (128 * AS_LD)
#define BS_STG (32 * BS_LD)
#define GEMM_SMEM ((2 * AS_STG + 2 * BS_STG) * sizeof(float))

template<int EPI>
__global__ __launch_bounds__(256, 2)
void gemm_tc(const float* __restrict__ A, const float* __restrict__ W,
             const float* __restrict__ bias, float* __restrict__ C) {
    extern __shared__ float sm[];
    float* As = sm;
    float* Bs = sm + 2 * AS_STG;
    int t = threadIdx.x, w = t >> 5, lane = t & 31;
    int gid = lane >> 2, tid4 = lane & 3;
    int bm = blockIdx.y * 128, bn = blockIdx.x * 128;
    int wm = (w >> 2) * 64, wn = (w & 3) * 32;

    float acc[4][4][4] = {};
    float bb[4][2];
    if (EPI == 2) {
        #pragma unroll
        for (int nj = 0; nj < 4; nj++) {
            bb[nj][0] = bias[bn + wn + nj * 8 + tid4 * 2];
            bb[nj][1] = bias[bn + wn + nj * 8 + tid4 * 2 + 1];
        }
    }

    auto load_stage = [&](int ks, int bf) {
        int k0 = ks * 32;
        #pragma unroll
        for (int i = 0; i < 4; i++) {
            int idx = t + i * 256;
            {   int row = idx >> 3, c4 = (idx & 7) * 4;
                cp16(As + bf * AS_STG + row * AS_LD + c4,
                     A + (size_t)(bm + row) * 256 + k0 + c4); }
            {   int row = idx >> 5, c4 = (idx & 31) * 4;
                cp16(Bs + bf * BS_STG + row * BS_LD + c4,
                     W + (size_t)(k0 + row) * 256 + bn + c4); }
        }
    };

    load_stage(0, 0); CP_COMMIT();
    int buf = 0;
    for (int ks8 = 0; ks8 < 8; ks8++) {
        CP_WAIT(0);
        __syncthreads();
        if (ks8 < 7) { load_stage(ks8 + 1, buf ^ 1); CP_COMMIT(); }
        const float* Ab = As + buf * AS_STG;
        const float* Bb = Bs + buf * BS_STG;
        #pragma unroll
        for (int ks = 0; ks < 4; ks++) {
            unsigned a[4][4];
            #pragma unroll
            for (int mi = 0; mi < 4; mi++) {
                const float* ap = Ab + (wm + mi * 16 + gid) * AS_LD + ks * 8 + tid4;
                a[mi][0] = __float_as_uint(ap[0]);
                a[mi][1] = __float_as_uint(ap[8 * AS_LD]);
                a[mi][2] = __float_as_uint(ap[4]);
                a[mi][3] = __float_as_uint(ap[8 * AS_LD + 4]);
            }
            #pragma unroll
            for (int nj = 0; nj < 4; nj++) {
                const float* bp = Bb + (ks * 8 + tid4) * BS_LD + wn + nj * 8 + gid;
                unsigned b0 = __float_as_uint(bp[0]);
                unsigned b1 = __float_as_uint(bp[4 * BS_LD]);
                #pragma unroll
                for (int mi = 0; mi < 4; mi++)
                    MMA_TF32(acc[mi][nj], a[mi][0], a[mi][1], a[mi][2], a[mi][3], b0, b1);
            }
        }
        buf ^= 1;
    }

    // epilogue: c0:(r0,col) c1:(r0,col+1) c2:(r0+8,col) c3:(r0+8,col+1)
    #pragma unroll
    for (int mi = 0; mi < 4; mi++) {
        int r0 = bm + wm + mi * 16 + gid;
        #pragma unroll
        for (int nj = 0; nj < 4; nj++) {
            int col = bn + wn + nj * 8 + tid4 * 2;
            float c0 = acc[mi][nj][0], c1 = acc[mi][nj][1];
            float c2 = acc[mi][nj][2], c3 = acc[mi][nj][3];
            if (EPI == 1) {
                c0 = to_tf32(c0); c1 = to_tf32(c1); c2 = to_tf32(c2); c3 = to_tf32(c3);
            }
            if (EPI == 2) {
                c0 = to_tf32(gelu_tanh(c0 + bb[nj][0]));
                c1 = to_tf32(gelu_tanh(c1 + bb[nj][1]));
                c2 = to_tf32(gelu_tanh(c2 + bb[nj][0]));
                c3 = to_tf32(gelu_tanh(c3 + bb[nj][1]));
            }
            *(float2*)&C[(size_t)r0 * 256 + col] = make_float2(c0, c1);
            *(float2*)&C[(size_t)(r0 + 8) * 256 + col] = make_float2(c2, c3);
        }
    }
}

// -------- flash attention: mma m16n8k8, register softmax, 1 sync/iter --------
#define KS_LD 68
#define VS_LD 72
#define KS_STG (64 * KS_LD)
#define VS_STG (64 * VS_LD)
#define PW_STG (16 * VS_LD)
#define FA_SMEM ((2 * KS_STG + 2 * VS_STG + 8 * PW_STG) * sizeof(float))

__global__ __launch_bounds__(256, 1)
void flash_attn(const float* __restrict__ Qp, const float* __restrict__ Kp,
                const float* __restrict__ Vp, const unsigned long long* __restrict__ mb,
                float* __restrict__ ctx) {
    extern __shared__ float sm[];
    float* Ks0 = sm;
    float* Vs0 = sm + 2 * KS_STG;
    int t = threadIdx.x, lane = t & 31, w = t >> 5;
    int gid = lane >> 2, tid4 = lane & 3;
    int qb = blockIdx.x, h = blockIdx.y, b = blockIdx.z;
    float* Pw = sm + 2 * KS_STG + 2 * VS_STG + w * PW_STG;

    int qrow = qb * 128 + w * 16 + gid;
    size_t qg0 = ((size_t)b * NQ_ + qrow) * D_ + h * DH_;

    unsigned qa[8][4];
    #pragma unroll
    for (int kc = 0; kc < 8; kc++) {
        qa[kc][0] = __float_as_uint(Qp[qg0 + kc * 8 + tid4]);
        qa[kc][1] = __float_as_uint(Qp[qg0 + (size_t)8 * D_ + kc * 8 + tid4]);
        qa[kc][2] = __float_as_uint(Qp[qg0 + kc * 8 + tid4 + 4]);
        qa[kc][3] = __float_as_uint(Qp[qg0 + (size_t)8 * D_ + kc * 8 + tid4 + 4]);
    }

    float o[8][4];
    #pragma unroll
    for (int j = 0; j < 8; j++) { o[j][0] = o[j][1] = o[j][2] = o[j][3] = 0.f; }
    float run_m0 = -1e30f, run_m1 = -1e30f, run_l0 = 0.f, run_l1 = 0.f;

    auto load_stage = [&](int kt2, int bf) {
        const float* kg = Kp + ((size_t)b * NK_ + kt2 * 64) * D_ + h * DH_;
        const float* vg = Vp + ((size_t)b * NK_ + kt2 * 64) * D_ + h * DH_;
        float* kd = Ks0 + bf * KS_STG;
        float* vd = Vs0 + bf * VS_STG;
        #pragma unroll
        for (int i = 0; i < 4; i++) {
            int idx = t + i * 256;
            int row = idx >> 4, c4 = (idx & 15) * 4;
            cp16(kd + row * KS_LD + c4, kg + (size_t)row * D_ + c4);
            cp16(vd + row * VS_LD + c4, vg + (size_t)row * D_ + c4);
        }
    };

    load_stage(0, 0); CP_COMMIT();
    int buf = 0;
    for (int kt = 0; kt < 16; kt++) {
        CP_WAIT(0);
        __syncthreads();
        if (kt < 15) { load_stage(kt + 1, buf ^ 1); CP_COMMIT(); }
        const float* Kb = Ks0 + buf * KS_STG;
        const float* Vb = Vs0 + buf * VS_STG;

        float s[8][4];
        #pragma unroll
        for (int j = 0; j < 8; j++) { s[j][0] = s[j][1] = s[j][2] = s[j][3] = 0.f; }
        #pragma unroll
        for (int kc = 0; kc < 8; kc++) {
            #pragma unroll
            for (int j = 0; j < 8; j++) {
                unsigned b0 = __float_as_uint(Kb[(j * 8 + gid) * KS_LD + kc * 8 + tid4]);
                unsigned b1 = __float_as_uint(Kb[(j * 8 + gid) * KS_LD + kc * 8 + tid4 + 4]);
                MMA_TF32(s[j], qa[kc][0], qa[kc][1], qa[kc][2], qa[kc][3], b0, b1);
            }
        }

        unsigned long long w0 = mb[(size_t)qrow * 16 + kt];
        unsigned long long w1 = mb[(size_t)(qrow + 8) * 16 + kt];
        float mx0 = -1e30f, mx1 = -1e30f;
        #pragma unroll
        for (int j = 0; j < 8; j++) {
            int sh = j * 8 + 2 * tid4;
            s[j][0] = ((w0 >> sh) & 1ull)       ? s[j][0] * SCALE_ : -1e9f;
            s[j][1] = ((w0 >> (sh + 1)) & 1ull) ? s[j][1] * SCALE_ : -1e9f;
            s[j][2] = ((w1 >> sh) & 1ull)       ? s[j][2] * SCALE_ : -1e9f;
            s[j][3] = ((w1 >> (sh + 1)) & 1ull) ? s[j][3] * SCALE_ : -1e9f;
            mx0 = fmaxf(mx0, fmaxf(s[j][0], s[j][1]));
            mx1 = fmaxf(mx1, fmaxf(s[j][2], s[j][3]));
        }
        mx0 = fmaxf(mx0, __shfl_xor_sync(0xffffffffu, mx0, 1));
        mx0 = fmaxf(mx0, __shfl_xor_sync(0xffffffffu, mx0, 2));
        mx1 = fmaxf(mx1, __shfl_xor_sync(0xffffffffu, mx1, 1));
        mx1 = fmaxf(mx1, __shfl_xor_sync(0xffffffffu, mx1, 2));
        float nm0 = fmaxf(run_m0, mx0), nm1 = fmaxf(run_m1, mx1);
        float fac0 = __expf(run_m0 - nm0), fac1 = __expf(run_m1 - nm1);
        run_m0 = nm0; run_m1 = nm1;
        float sum0 = 0.f, sum1 = 0.f;
        #pragma unroll
        for (int j = 0; j < 8; j++) {
            s[j][0] = __expf(s[j][0] - nm0); s[j][1] = __expf(s[j][1] - nm0);
            s[j][2] = __expf(s[j][2] - nm1); s[j][3] = __expf(s[j][3] - nm1);
            sum0 += s[j][0] + s[j][1]; sum1 += s[j][2] + s[j][3];
            *(float2*)&Pw[gid * VS_LD + j * 8 + 2 * tid4] =
                make_float2(to_tf32(s[j][0]), to_tf32(s[j][1]));
            *(float2*)&Pw[(gid + 8) * VS_LD + j * 8 + 2 * tid4] =
                make_float2(to_tf32(s[j][2]), to_tf32(s[j][3]));
        }
        sum0 += __shfl_xor_sync(0xffffffffu, sum0, 1);
        sum0 += __shfl_xor_sync(0xffffffffu, sum0, 2);
        sum1 += __shfl_xor_sync(0xffffffffu, sum1, 1);
        sum1 += __shfl_xor_sync(0xffffffffu, sum1, 2);
        run_l0 = run_l0 * fac0 + sum0;
        run_l1 = run_l1 * fac1 + sum1;
        #pragma unroll
        for (int j = 0; j < 8; j++) { o[j][0] *= fac0; o[j][1] *= fac0; o[j][2] *= fac1; o[j][3] *= fac1; }
        __syncwarp();

        #pragma unroll
        for (int kc = 0; kc < 8; kc++) {
            unsigned pa0 = __float_as_uint(Pw[gid * VS_LD + kc * 8 + tid4]);
            unsigned pa1 = __float_as_uint(Pw[(gid + 8) * VS_LD + kc * 8 + tid4]);
            unsigned pa2 = __float_as_uint(Pw[gid * VS_LD + kc * 8 + tid4 + 4]);
            unsigned pa3 = __float_as_uint(Pw[(gid + 8) * VS_LD + kc * 8 + tid4 + 4]);
            #pragma unroll
            for (int j2 = 0; j2 < 8; j2++) {
                unsigned b0 = __float_as_uint(Vb[(kc * 8 + tid4) * VS_LD + j2 * 8 + gid]);
                unsigned b1 = __float_as_uint(Vb[(kc * 8 + tid4 + 4) * VS_LD + j2 * 8 + gid]);
                MMA_TF32(o[j2], pa0, pa1, pa2, pa3, b0, b1);
            }
        }
        buf ^= 1;
    }

    float inv0 = 1.f / run_l0, inv1 = 1.f / run_l1;
    float* c0 = ctx + qg0;
    #pragma unroll
    for (int j2 = 0; j2 < 8; j2++) {
        *(float2*)&c0[j2 * 8 + 2 * tid4] =
            make_float2(to_tf32(o[j2][0] * inv0), to_tf32(o[j2][1] * inv0));
        *(float2*)&c0[(size_t)8 * D_ + j2 * 8 + 2 * tid4] =
            make_float2(to_tf32(o[j2][2] * inv1), to_tf32(o[j2][3] * inv1));
    }
}

// -------- host launcher --------
extern "C" void kernel_launch(void* const* d_in, const int* in_sizes, int n_in,
                              void* d_out, int out_size) {
    const float* upd   = (const float*)d_in[0];
    const float* emb   = (const float*)d_in[1];
    const float* maskl = (const float*)d_in[2];
    const float* Wq    = (const float*)d_in[3];
    const float* Wk    = (const float*)d_in[4];
    const float* Wv    = (const float*)d_in[5];
    const float* Wo    = (const float*)d_in[6];
    const float* W1    = (const float*)d_in[7];
    const float* b1    = (const float*)d_in[8];
    const float* W2    = (const float*)d_in[9];
    const float* b2    = (const float*)d_in[10];
    const float* sys_s = (const float*)d_in[11];
    const float* sys_b = (const float*)d_in[12];
    const float* eff_s = (const float*)d_in[13];
    const float* eff_b = (const float*)d_in[14];
    const float* in_s  = (const float*)d_in[15];
    const float* in_b  = (const float*)d_in[16];
    const float* out_s = (const float*)d_in[17];
    const float* out_b = (const float*)d_in[18];
    const int*   qidx  = (const int*)d_in[19];
    const int*   kidx  = (const int*)d_in[20];
    float* out = (float*)d_out;

    float *qb, *kb, *Qp, *Kp, *Vp, *ctx, *hb, *t1, *fb, *Wr;
    unsigned long long* mbp;
    cudaGetSymbolAddress((void**)&qb,  g_q);
    cudaGetSymbolAddress((void**)&kb,  g_k);
    cudaGetSymbolAddress((void**)&Qp,  g_Qp);
    cudaGetSymbolAddress((void**)&Kp,  g_Kp);
    cudaGetSymbolAddress((void**)&Vp,  g_Vp);
    cudaGetSymbolAddress((void**)&ctx, g_ctx);
    cudaGetSymbolAddress((void**)&hb,  g_h);
    cudaGetSymbolAddress((void**)&t1,  g_t1);
    cudaGetSymbolAddress((void**)&fb,  g_f);
    cudaGetSymbolAddress((void**)&Wr,  g_Wr);
    cudaGetSymbolAddress((void**)&mbp, g_mb);

    cudaFuncSetAttribute(flash_attn, cudaFuncAttributeMaxDynamicSharedMemorySize, (int)FA_SMEM);
    cudaFuncSetAttribute(gemm_tc<0>, cudaFuncAttributeMaxDynamicSharedMemorySize, (int)GEMM_SMEM);
    cudaFuncSetAttribute(gemm_tc<1>, cudaFuncAttributeMaxDynamicSharedMemorySize, (int)GEMM_SMEM);
    cudaFuncSetAttribute(gemm_tc<2>, cudaFuncAttributeMaxDynamicSharedMemorySize, (int)GEMM_SMEM);

    // prep
    init_kernel<<<(B_ * NS_ * D_) / 256, 256>>>(upd, out);
    round_weights<<<dim3(64, 6), 256>>>(Wq, Wk, Wv, Wo, W1, W2);
    mask_bits_kernel<<<(L_ * NQ_ * 16 * 32) / 256, 256>>>(maskl);

    const float* rWq = Wr;
    const float* rWk = Wr + 1 * 65536;
    const float* rWv = Wr + 2 * 65536;
    const float* rWo = Wr + 3 * 65536;
    const float* rW1 = Wr + 4 * 65536;
    const float* rW2 = Wr + 5 * 65536;

    for (int l = 0; l < L_; l++) {
        gather_ln_w<<<MQ / 8, 256>>>(emb, qidx + l * NQ_, sys_s, sys_b, qb, 9);
        gather_ln_w<<<MK / 8, 256>>>(emb, kidx + l * NK_, sys_s, sys_b, kb, 10);

        gemm_tc<1><<<dim3(2, MQ / 128), 256, GEMM_SMEM>>>(qb, rWq, nullptr, Qp);
        gemm_tc<1><<<dim3(2, MK / 128), 256, GEMM_SMEM>>>(kb, rWk, nullptr, Kp);
        gemm_tc<1><<<dim3(2, MK / 128), 256, GEMM_SMEM>>>(kb, rWv, nullptr, Vp);

        flash_attn<<<dim3(NQ_ / 128, H_, B_), 256, FA_SMEM>>>(
            Qp, Kp, Vp, mbp + (size_t)l * NQ_ * 16, ctx);

        gemm_tc<0><<<dim3(2, MQ / 128), 256, GEMM_SMEM>>>(ctx, rWo, nullptr, t1);
        ln_w<<<MQ / 8, 256>>>(t1, in_s, in_b, hb);

        gemm_tc<2><<<dim3(2, MQ / 128), 256, GEMM_SMEM>>>(hb, rW1, b1, t1);
        gemm_tc<0><<<dim3(2, MQ / 128), 256, GEMM_SMEM>>>(t1, rW2, nullptr, fb);

        add_ln_scatter<<<MQ / 8, 256>>>(hb, fb, b2, out_s, out_b, eff_s, eff_b,
                                        qidx + l * NQ_, out);
    }
}

// round 14
// speedup vs baseline: 14.7326x; 1.0510x over previous
#include <cuda_runtime.h>
#include <cuda_bf16.h>
#include <mma.h>
#include <math.h>

using namespace nvcuda;

// Problem constants
#define B_   32
#define NS_  4096
#define D_   256
#define H_   4
#define L_   6
#define NQ_  512
#define NK_  1024
#define DH_  64
#define SCALE_ 0.125f

#define MQ (B_*NQ_)   // 16384 rows
#define MK (B_*NK_)   // 32768 rows

// d-permutation within 8-groups: logical k and k+4 become adjacent storage slots
// slot(c) = (c&3)*2 + (c>>2)   for c in 0..7 ; invp(slot) = {0,4,1,5,2,6,3,7}
#define PERM8(c)  (((c) & ~7) | ((((c) & 3) << 1) | ((((c) >> 2) & 1))))

// -------- persistent device scratch (static, no allocation) --------
__device__ float g_U  [(size_t)B_*NS_*D_];   // logical layout
__device__ float g_q  [(size_t)MQ*D_];       // P-space (d-permuted)
__device__ float g_k  [(size_t)MK*D_];       // P-space
__device__ float g_Qp [(size_t)MQ*D_];       // P-space
__device__ float g_Kp [(size_t)MK*D_];       // P-space
__device__ float g_Vp [(size_t)MK*D_];       // P-space
__device__ float g_ctx[(size_t)MQ*D_];       // P-space
__device__ float g_h  [(size_t)MQ*D_];       // P-space
__device__ float g_t1 [(size_t)MQ*D_];       // P-space
__device__ float g_f  [(size_t)MQ*D_];       // P-space
__device__ float g_Wr [6 * 256 * 256];       // tf32-rounded, P-space rows AND cols
__device__ unsigned long long g_mb[(size_t)L_*NQ_*16];   // mask bitmaps (key dim)

// -------- helpers --------
__device__ __forceinline__ float to_tf32(float x) { return wmma::__float_to_tf32(x); }

__device__ __forceinline__ float wsum(float v) {
    #pragma unroll
    for (int o = 16; o; o >>= 1) v += __shfl_xor_sync(0xffffffffu, v, o);
    return v;
}

__device__ __forceinline__ float gelu_tanh(float x) {
    float x3 = x * x * x;
    float t = tanhf(0.7978845608028654f * (x + 0.044715f * x3));
    return 0.5f * x * (1.f + t);
}

__device__ __forceinline__ void cp16(void* dst, const void* src) {
    unsigned s = (unsigned)__cvta_generic_to_shared(dst);
    asm volatile("cp.async.cg.shared.global [%0], [%1], 16;\n" :: "r"(s), "l"(src));
}
#define CP_COMMIT() asm volatile("cp.async.commit_group;\n")
#define CP_WAIT(n)  asm volatile("cp.async.wait_group %0;\n" :: "n"(n))

#define MMA_TF32(c, a0, a1, a2, a3, b0v, b1v) \
    asm volatile("mma.sync.aligned.m16n8k8.row.col.f32.tf32.tf32.f32 " \
        "{%0,%1,%2,%3}, {%4,%5,%6,%7}, {%8,%9}, {%0,%1,%2,%3};" \
        : "+f"(c[0]), "+f"(c[1]), "+f"(c[2]), "+f"(c[3]) \
        : "r"(a0), "r"(a1), "r"(a2), "r"(a3), "r"(b0v), "r"(b1v))

// -------- mega prep: init U/out (float4!) | round+permute weights | mask bitmaps --------
// grid regions: [0,32768) init x4, [32768, 33152) weights, [33152, 39296) mask
__global__ void prep_kernel(const float* __restrict__ upd, float* __restrict__ out,
                            const float* __restrict__ w0, const float* __restrict__ w1,
                            const float* __restrict__ w2, const float* __restrict__ w3,
                            const float* __restrict__ w4, const float* __restrict__ w5,
                            const float* __restrict__ maskl) {
    int bid = blockIdx.x, tid = threadIdx.x;
    if (bid < 32768) {
        // float4 copy: 32768 * 256 * 4 = 33,554,432 = B*NS*D exactly
        size_t i = ((size_t)bid * 256 + tid) * 4;
        float4 v = *(const float4*)(upd + i);
        *(float4*)(g_U + i) = v;
        *(float4*)(out + i) = make_float4(0.f, 0.f, 0.f, 0.f);
    } else if (bid < 33152) {
        int wb = bid - 32768;
        int widx = wb >> 6, blk = wb & 63;
        const float* src;
        switch (widx) {
            case 0: src = w0; break; case 1: src = w1; break;
            case 2: src = w2; break; case 3: src = w3; break;
            case 4: src = w4; break; default: src = w5; break;
        }
        int e = (blk * 256 + tid) * 4;
        int r = e >> 8, c0 = e & 255;
        float4 v = *(const float4*)(src + (size_t)r * 256 + c0);
        int rp = PERM8(r);
        float* dst = g_Wr + (size_t)widx * 65536 + (size_t)rp * 256;
        dst[PERM8(c0 + 0)] = to_tf32(v.x);
        dst[PERM8(c0 + 1)] = to_tf32(v.y);
        dst[PERM8(c0 + 2)] = to_tf32(v.z);
        dst[PERM8(c0 + 3)] = to_tf32(v.w);
    } else {
        size_t gt = (size_t)(bid - 33152) * 256 + tid;
        size_t wid = gt >> 5;
        int lane = (int)(gt & 31);
        const float* src = maskl + wid * 64;
        unsigned lo = __ballot_sync(0xffffffffu, src[lane]      > 0.5f);
        unsigned hi = __ballot_sync(0xffffffffu, src[lane + 32] > 0.5f);
        if (lane == 0) g_mb[wid] = (unsigned long long)lo | ((unsigned long long)hi << 32);
    }
}

// -------- gather + LN(sys), q and k in one launch; writes P-space --------
__global__ void gather_ln_qk(const float* __restrict__ emb,
                             const int* __restrict__ qidx, const int* __restrict__ kidx,
                             const float* __restrict__ sc, const float* __restrict__ bi,
                             float* __restrict__ qout, float* __restrict__ kout) {
    int gw = (blockIdx.x * blockDim.x + threadIdx.x) >> 5;   // 0..MQ+MK-1
    int lane = threadIdx.x & 31;
    int id, b_of; float* o;
    if (gw < MQ) {
        int i = gw & 511; b_of = gw >> 9;
        id = qidx[i];
        o = qout + ((size_t)((b_of << 9) + i)) * D_;
    } else {
        int g2 = gw - MQ;
        int i = g2 & 1023; b_of = g2 >> 10;
        id = kidx[i];
        o = kout + ((size_t)((b_of << 10) + i)) * D_;
    }
    const float* e = emb + (size_t)id * D_;
    const float* u = g_U + ((size_t)b_of * NS_ + id) * D_;
    int c = lane * 8;
    float4 p0 = *(const float4*)(e + c), p1 = *(const float4*)(e + c + 4);
    float4 u0 = *(const float4*)(u + c), u1 = *(const float4*)(u + c + 4);
    float x[8] = {p0.x + u0.x, p0.y + u0.y, p0.z + u0.z, p0.w + u0.w,
                  p1.x + u1.x, p1.y + u1.y, p1.z + u1.z, p1.w + u1.w};
    float s = 0.f;
    #pragma unroll
    for (int j = 0; j < 8; j++) s += x[j];
    float m = wsum(s) * (1.f / D_);
    float vs = 0.f;
    #pragma unroll
    for (int j = 0; j < 8; j++) { float d = x[j] - m; vs += d * d; }
    float r = rsqrtf(wsum(vs) * (1.f / D_) + 1e-5f);
    float4 s0 = *(const float4*)(sc + c), s1 = *(const float4*)(sc + c + 4);
    float4 b0 = *(const float4*)(bi + c), b1 = *(const float4*)(bi + c + 4);
    float v[8];   // logical values
    v[0] = to_tf32((x[0] - m) * r * s0.x + b0.x);
    v[1] = to_tf32((x[1] - m) * r * s0.y + b0.y);
    v[2] = to_tf32((x[2] - m) * r * s0.z + b0.z);
    v[3] = to_tf32((x[3] - m) * r * s0.w + b0.w);
    v[4] = to_tf32((x[4] - m) * r * s1.x + b1.x);
    v[5] = to_tf32((x[5] - m) * r * s1.y + b1.y);
    v[6] = to_tf32((x[6] - m) * r * s1.z + b1.z);
    v[7] = to_tf32((x[7] - m) * r * s1.w + b1.w);
    // pack P-space: slot j holds logical invp(j) = {0,4,1,5,2,6,3,7}
    *(float4*)(o + c)     = make_float4(v[0], v[4], v[1], v[5]);
    *(float4*)(o + c + 4) = make_float4(v[2], v[6], v[3], v[7]);
}

// -------- plain LN (P-space in/out) --------
__global__ void ln_w(const float* __restrict__ in, const float* __restrict__ sc,
                     const float* __restrict__ bi, float* __restrict__ out) {
    int row = (blockIdx.x * blockDim.x + threadIdx.x) >> 5;
    int lane = threadIdx.x & 31;
    int c = lane * 8;
    const float* ir = in + (size_t)row * D_ + c;
    float4 p0 = *(const float4*)ir, p1 = *(const float4*)(ir + 4);
    float x[8] = {p0.x, p0.y, p0.z, p0.w, p1.x, p1.y, p1.z, p1.w};  // slot order
    float s = 0.f;
    #pragma unroll
    for (int j = 0; j < 8; j++) s += x[j];
    float m = wsum(s) * (1.f / D_);
    float vs = 0.f;
    #pragma unroll
    for (int j = 0; j < 8; j++) { float d = x[j] - m; vs += d * d; }
    float r = rsqrtf(wsum(vs) * (1.f / D_) + 1e-5f);
    float4 s0 = *(const float4*)(sc + c), s1 = *(const float4*)(sc + c + 4);
    float4 b0 = *(const float4*)(bi + c), b1 = *(const float4*)(bi + c + 4);
    // slot j pairs with logical sc/bi invp(j)
    float scp[8] = {s0.x, s1.x, s0.y, s1.y, s0.z, s1.z, s0.w, s1.w};
    float bip[8] = {b0.x, b1.x, b0.y, b1.y, b0.z, b1.z, b0.w, b1.w};
    float* o = out + (size_t)row * D_ + c;
    float4 o0, o1;
    o0.x = to_tf32((x[0] - m) * r * scp[0] + bip[0]);
    o0.y = to_tf32((x[1] - m) * r * scp[1] + bip[1]);
    o0.z = to_tf32((x[2] - m) * r * scp[2] + bip[2]);
    o0.w = to_tf32((x[3] - m) * r * scp[3] + bip[3]);
    o1.x = to_tf32((x[4] - m) * r * scp[4] + bip[4]);
    o1.y = to_tf32((x[5] - m) * r * scp[5] + bip[5]);
    o1.z = to_tf32((x[6] - m) * r * scp[6] + bip[6]);
    o1.w = to_tf32((x[7] - m) * r * scp[7] + bip[7]);
    *(float4*)o = o0;
    *(float4*)(o + 4) = o1;
}

// -------- fused: residual(+b2) + LN + LN + scatter (P-space in, logical out) --------
__global__ void add_ln_scatter(const float* __restrict__ hb, const float* __restrict__ fb,
                               const float* __restrict__ b2,
                               const float* __restrict__ os, const float* __restrict__ ob,
                               const float* __restrict__ es, const float* __restrict__ eb,
                               const int* __restrict__ qidx, float* __restrict__ out) {
    int row = (blockIdx.x * blockDim.x + threadIdx.x) >> 5;   // 0..MQ-1
    int lane = threadIdx.x & 31;
    int b = row >> 9, i = row & 511;
    int c = lane * 8;
    const float* hr = hb + (size_t)row * D_ + c;
    const float* fr = fb + (size_t)row * D_ + c;
    float4 h0 = *(const float4*)hr, h1 = *(const float4*)(hr + 4);
    float4 f0 = *(const float4*)fr, f1 = *(const float4*)(fr + 4);
    float4 c0 = *(const float4*)(b2 + c), c1 = *(const float4*)(b2 + c + 4);
    float b2p[8] = {c0.x, c1.x, c0.y, c1.y, c0.z, c1.z, c0.w, c1.w};
    float x[8] = {h0.x + f0.x + b2p[0], h0.y + f0.y + b2p[1],
                  h0.z + f0.z + b2p[2], h0.w + f0.w + b2p[3],
                  h1.x + f1.x + b2p[4], h1.y + f1.y + b2p[5],
                  h1.z + f1.z + b2p[6], h1.w + f1.w + b2p[7]};
    float s = 0.f;
    #pragma unroll
    for (int j = 0; j < 8; j++) s += x[j];
    float m = wsum(s) * (1.f / D_);
    float vs = 0.f;
    #pragma unroll
    for (int j = 0; j < 8; j++) { float d = x[j] - m; vs += d * d; }
    float r = rsqrtf(wsum(vs) * (1.f / D_) + 1e-5f);
    float4 os0 = *(const float4*)(os + c), os1 = *(const float4*)(os + c + 4);
    float4 ob0 = *(const float4*)(ob + c), ob1 = *(const float4*)(ob + c + 4);
    float osp[8] = {os0.x, os1.x, os0.y, os1.y, os0.z, os1.z, os0.w, os1.w};
    float obp[8] = {ob0.x, ob1.x, ob0.y, ob1.y, ob0.z, ob1.z, ob0.w, ob1.w};
    float u[8];
    #pragma unroll
    for (int j = 0; j < 8; j++) u[j] = (x[j] - m) * r * osp[j] + obp[j];
    float s2 = 0.f;
    #pragma unroll
    for (int j = 0; j < 8; j++) s2 += u[j];
    float m2 = wsum(s2) * (1.f / D_);
    float vs2 = 0.f;
    #pragma unroll
    for (int j = 0; j < 8; j++) { float d = u[j] - m2; vs2 += d * d; }
    float r2 = rsqrtf(wsum(vs2) * (1.f / D_) + 1e-5f);
    float4 es0 = *(const float4*)(es + c), es1 = *(const float4*)(es + c + 4);
    float4 eb0 = *(const float4*)(eb + c), eb1 = *(const float4*)(eb + c + 4);
    float esp[8] = {es0.x, es1.x, es0.y, es1.y, es0.z, es1.z, es0.w, es1.w};
    float ebp[8] = {eb0.x, eb1.x, eb0.y, eb1.y, eb0.z, eb1.z, eb0.w, eb1.w};
    int id = qidx[i];
    size_t base = ((size_t)b * NS_ + id) * D_ + c;
    const int I[8] = {0, 4, 1, 5, 2, 6, 3, 7};   // slot -> logical offset
    #pragma unroll
    for (int j = 0; j < 8; j++) {
        float v = (u[j] - m2) * r2 * esp[j] + ebp[j];
        atomicAdd(&g_U[base + I[j]], v);
        atomicAdd(&out[base + I[j]], v);
    }
}

// -------- tf32 GEMM, P-space operands, float2 A-frag loads --------
#define AS_LD 40
#define BS_LD 132
#define AS_STG (128 * AS_LD)
#define BS_STG (32 * BS_LD)
#define GEMM_SMEM ((2 * AS_STG + 2 * BS_STG) * sizeof(float))

template<int EPI>   // 0 plain, 1 tf32-round, 2 bias+gelu+round
__device__ __forceinline__ void gemm_body(const float* __restrict__ A,
                                          const float* __restrict__ W,
                                          const float* __restrict__ bias,
                                          float* __restrict__ C,
                                          int bm, int bn, float* sm) {
    float* As = sm;
    float* Bs = sm + 2 * AS_STG;
    int t = threadIdx.x, w = t >> 5, lane = t & 31;
    int gid = lane >> 2, tid4 = lane & 3;
    int wm = (w >> 2) * 64, wn = (w & 3) * 32;

    float acc[4][4][4] = {};
    float bb[4][2];
    if (EPI == 2) {
        #pragma unroll
        for (int nj = 0; nj < 4; nj++) {
            // P-cols (slots) tid4*2, tid4*2+1 = logical tid4, tid4+4 within 8-group
            bb[nj][0] = bias[bn + wn + nj * 8 + tid4];
            bb[nj][1] = bias[bn + wn + nj * 8 + tid4 + 4];
        }
    }

    auto load_stage = [&](int ks, int bf) {
        int k0 = ks * 32;
        #pragma unroll
        for (int i = 0; i < 4; i++) {
            int idx = t + i * 256;
            {   int row = idx >> 3, c4 = (idx & 7) * 4;
                cp16(As + bf * AS_STG + row * AS_LD + c4,
                     A + (size_t)(bm + row) * 256 + k0 + c4); }
            {   int row = idx >> 5, c4 = (idx & 31) * 4;
                cp16(Bs + bf * BS_STG + row * BS_LD + c4,
                     W + (size_t)(k0 + row) * 256 + bn + c4); }
        }
    };

    load_stage(0, 0); CP_COMMIT();
    int buf = 0;
    for (int ks8 = 0; ks8 < 8; ks8++) {
        CP_WAIT(0);
        __syncthreads();
        if (ks8 < 7) { load_stage(ks8 + 1, buf ^ 1); CP_COMMIT(); }
        const float* Ab = As + buf * AS_STG;
        const float* Bb = Bs + buf * BS_STG;
        #pragma unroll
        for (int ks = 0; ks < 4; ks++) {
            unsigned a[4][4];
            #pragma unroll
            for (int mi = 0; mi < 4; mi++) {
                // P-space slots (2*tid4, 2*tid4+1) = logical (tid4, tid4+4)
                float2 lo = *(const float2*)(Ab + (wm + mi * 16 + gid) * AS_LD + ks * 8 + tid4 * 2);
                float2 hi = *(const float2*)(Ab + (wm + mi * 16 + gid + 8) * AS_LD + ks * 8 + tid4 * 2);
                a[mi][0] = __float_as_uint(lo.x);
                a[mi][1] = __float_as_uint(hi.x);
                a[mi][2] = __float_as_uint(lo.y);
                a[mi][3] = __float_as_uint(hi.y);
            }
            #pragma unroll
            for (int nj = 0; nj < 4; nj++) {
                const float* bp = Bb + (ks * 8 + tid4 * 2) * BS_LD + wn + nj * 8 + gid;
                unsigned b0 = __float_as_uint(bp[0]);        // P-row slot 2t   = logical t
                unsigned b1 = __float_as_uint(bp[BS_LD]);    // P-row slot 2t+1 = logical t+4
                #pragma unroll
                for (int mi = 0; mi < 4; mi++)
                    MMA_TF32(acc[mi][nj], a[mi][0], a[mi][1], a[mi][2], a[mi][3], b0, b1);
            }
        }
        buf ^= 1;
    }

    #pragma unroll
    for (int mi = 0; mi < 4; mi++) {
        int r0 = bm + wm + mi * 16 + gid;
        #pragma unroll
        for (int nj = 0; nj < 4; nj++) {
            int col = bn + wn + nj * 8 + tid4 * 2;
            float c0 = acc[mi][nj][0], c1 = acc[mi][nj][1];
            float c2 = acc[mi][nj][2], c3 = acc[mi][nj][3];
            if (EPI == 1) {
                c0 = to_tf32(c0); c1 = to_tf32(c1); c2 = to_tf32(c2); c3 = to_tf32(c3);
            }
            if (EPI == 2) {
                c0 = to_tf32(gelu_tanh(c0 + bb[nj][0]));
                c1 = to_tf32(gelu_tanh(c1 + bb[nj][1]));
                c2 = to_tf32(gelu_tanh(c2 + bb[nj][0]));
                c3 = to_tf32(gelu_tanh(c3 + bb[nj][1]));
            }
            *(float2*)&C[(size_t)r0 * 256 + col] = make_float2(c0, c1);
            *(float2*)&C[(size_t)(r0 + 8) * 256 + col] = make_float2(c2, c3);
        }
    }
}

template<int EPI>
__global__ __launch_bounds__(256, 2)
void gemm_tc(const float* __restrict__ A, const float* __restrict__ W,
             const float* __restrict__ bias, float* __restrict__ C) {
    extern __shared__ float sm[];
    gemm_body<EPI>(A, W, bias, C, blockIdx.y * 128, blockIdx.x * 128, sm);
}

// batched Q/K/V projection: grid.x = 1280; decode (n-half, tile, which)
__global__ __launch_bounds__(256, 2)
void gemm_qkv(const float* __restrict__ qb, const float* __restrict__ kb,
              const float* __restrict__ Wq, const float* __restrict__ Wk,
              const float* __restrict__ Wv,
              float* __restrict__ Qp, float* __restrict__ Kp, float* __restrict__ Vp) {
    extern __shared__ float sm[];
    int u = blockIdx.x;
    int bn = (u & 1) * 128;
    int v = u >> 1;
    const float* A; const float* W; float* C; int bm;
    if (v < 128)      { A = qb; W = Wq; C = Qp; bm = v * 128; }
    else if (v < 384) { A = kb; W = Wk; C = Kp; bm = (v - 128) * 128; }
    else              { A = kb; W = Wv; C = Vp; bm = (v - 384) * 128; }
    gemm_body<1>(A, W, nullptr, C, bm, bn, sm);
}

// -------- flash attention: P-space d-dim, float2 Q/K frag loads --------
#define KS_LD 72
#define VS_LD 72
#define KS_STG (64 * KS_LD)
#define VS_STG (64 * VS_LD)
#define PW_STG (16 * VS_LD)
#define FA_SMEM ((2 * KS_STG + 2 * VS_STG + 8 * PW_STG) * sizeof(float))

__global__ __launch_bounds__(256, 1)
void flash_attn(const float* __restrict__ Qp, const float* __restrict__ Kp,
                const float* __restrict__ Vp, const unsigned long long* __restrict__ mb,
                float* __restrict__ ctx) {
    extern __shared__ float sm[];
    float* Ks0 = sm;
    float* Vs0 = sm + 2 * KS_STG;
    int t = threadIdx.x, lane = t & 31, w = t >> 5;
    int gid = lane >> 2, tid4 = lane & 3;
    int qb = blockIdx.x, h = blockIdx.y, b = blockIdx.z;
    float* Pw = sm + 2 * KS_STG + 2 * VS_STG + w * PW_STG;

    int qrow = qb * 128 + w * 16 + gid;
    size_t qg0 = ((size_t)b * NQ_ + qrow) * D_ + h * DH_;

    unsigned qa[8][4];
    #pragma unroll
    for (int kc = 0; kc < 8; kc++) {
        float2 lo = *(const float2*)(Qp + qg0 + kc * 8 + tid4 * 2);
        float2 hi = *(const float2*)(Qp + qg0 + (size_t)8 * D_ + kc * 8 + tid4 * 2);
        qa[kc][0] = __float_as_uint(lo.x);
        qa[kc][1] = __float_as_uint(hi.x);
        qa[kc][2] = __float_as_uint(lo.y);
        qa[kc][3] = __float_as_uint(hi.y);
    }

    float o[8][4];
    #pragma unroll
    for (int j = 0; j < 8; j++) { o[j][0] = o[j][1] = o[j][2] = o[j][3] = 0.f; }
    float run_m0 = -1e30f, run_m1 = -1e30f, run_l0 = 0.f, run_l1 = 0.f;

    auto load_stage = [&](int kt2, int bf) {
        const float* kg = Kp + ((size_t)b * NK_ + kt2 * 64) * D_ + h * DH_;
        const float* vg = Vp + ((size_t)b * NK_ + kt2 * 64) * D_ + h * DH_;
        float* kd = Ks0 + bf * KS_STG;
        float* vd = Vs0 + bf * VS_STG;
        #pragma unroll
        for (int i = 0; i < 4; i++) {
            int idx = t + i * 256;
            int row = idx >> 4, c4 = (idx & 15) * 4;
            cp16(kd + row * KS_LD + c4, kg + (size_t)row * D_ + c4);
            cp16(vd + row * VS_LD + c4, vg + (size_t)row * D_ + c4);
        }
    };

    load_stage(0, 0); CP_COMMIT();
    int buf = 0;
    for (int kt = 0; kt < 16; kt++) {
        CP_WAIT(0);
        __syncthreads();
        if (kt < 15) { load_stage(kt + 1, buf ^ 1); CP_COMMIT(); }
        const float* Kb = Ks0 + buf * KS_STG;
        const float* Vb = Vs0 + buf * VS_STG;

        float s[8][4];
        #pragma unroll
        for (int j = 0; j < 8; j++) { s[j][0] = s[j][1] = s[j][2] = s[j][3] = 0.f; }
        #pragma unroll
        for (int kc = 0; kc < 8; kc++) {
            #pragma unroll
            for (int j = 0; j < 8; j++) {
                float2 kk = *(const float2*)(Kb + (j * 8 + gid) * KS_LD + kc * 8 + tid4 * 2);
                MMA_TF32(s[j], qa[kc][0], qa[kc][1], qa[kc][2], qa[kc][3],
                         __float_as_uint(kk.x), __float_as_uint(kk.y));
            }
        }

        unsigned long long w0 = mb[(size_t)qrow * 16 + kt];
        unsigned long long w1 = mb[(size_t)(qrow + 8) * 16 + kt];
        float mx0 = -1e30f, mx1 = -1e30f;
        #pragma unroll
        for (int j = 0; j < 8; j++) {
            int sh = j * 8 + 2 * tid4;
            s[j][0] = ((w0 >> sh) & 1ull)       ? s[j][0] * SCALE_ : -1e9f;
            s[j][1] = ((w0 >> (sh + 1)) & 1ull) ? s[j][1] * SCALE_ : -1e9f;
            s[j][2] = ((w1 >> sh) & 1ull)       ? s[j][2] * SCALE_ : -1e9f;
            s[j][3] = ((w1 >> (sh + 1)) & 1ull) ? s[j][3] * SCALE_ : -1e9f;
            mx0 = fmaxf(mx0, fmaxf(s[j][0], s[j][1]));
            mx1 = fmaxf(mx1, fmaxf(s[j][2], s[j][3]));
        }
        mx0 = fmaxf(mx0, __shfl_xor_sync(0xffffffffu, mx0, 1));
        mx0 = fmaxf(mx0, __shfl_xor_sync(0xffffffffu, mx0, 2));
        mx1 = fmaxf(mx1, __shfl_xor_sync(0xffffffffu, mx1, 1));
        mx1 = fmaxf(mx1, __shfl_xor_sync(0xffffffffu, mx1, 2));
        float nm0 = fmaxf(run_m0, mx0), nm1 = fmaxf(run_m1, mx1);
        float fac0 = __expf(run_m0 - nm0), fac1 = __expf(run_m1 - nm1);
        run_m0 = nm0; run_m1 = nm1;
        float sum0 = 0.f, sum1 = 0.f;
        #pragma unroll
        for (int j = 0; j < 8; j++) {
            s[j][0] = __expf(s[j][0] - nm0); s[j][1] = __expf(s[j][1] - nm0);
            s[j][2] = __expf(s[j][2] - nm1); s[j][3] = __expf(s[j][3] - nm1);
            sum0 += s[j][0] + s[j][1]; sum1 += s[j][2] + s[j][3];
            *(float2*)&Pw[gid * VS_LD + j * 8 + 2 * tid4] =
                make_float2(to_tf32(s[j][0]), to_tf32(s[j][1]));
            *(float2*)&Pw[(gid + 8) * VS_LD + j * 8 + 2 * tid4] =
                make_float2(to_tf32(s[j][2]), to_tf32(s[j][3]));
        }
        sum0 += __shfl_xor_sync(0xffffffffu, sum0, 1);
        sum0 += __shfl_xor_sync(0xffffffffu, sum0, 2);
        sum1 += __shfl_xor_sync(0xffffffffu, sum1, 1);
        sum1 += __shfl_xor_sync(0xffffffffu, sum1, 2);
        run_l0 = run_l0 * fac0 + sum0;
        run_l1 = run_l1 * fac1 + sum1;
        #pragma unroll
        for (int j = 0; j < 8; j++) { o[j][0] *= fac0; o[j][1] *= fac0; o[j][2] *= fac1; o[j][3] *= fac1; }
        __syncwarp();

        #pragma unroll
        for (int kc = 0; kc < 8; kc++) {
            unsigned pa0 = __float_as_uint(Pw[gid * VS_LD + kc * 8 + tid4]);
            unsigned pa1 = __float_as_uint(Pw[(gid + 8) * VS_LD + kc * 8 + tid4]);
            unsigned pa2 = __float_as_uint(Pw[gid * VS_LD + kc * 8 + tid4 + 4]);
            unsigned pa3 = __float_as_uint(Pw[(gid + 8) * VS_LD + kc * 8 + tid4 + 4]);
            #pragma unroll
            for (int j2 = 0; j2 < 8; j2++) {
                unsigned b0 = __float_as_uint(Vb[(kc * 8 + tid4) * VS_LD + j2 * 8 + gid]);
                unsigned b1 = __float_as_uint(Vb[(kc * 8 + tid4 + 4) * VS_LD + j2 * 8 + gid]);
                MMA_TF32(o[j2], pa0, pa1, pa2, pa3, b0, b1);
            }
        }
        buf ^= 1;
    }

    float inv0 = 1.f / run_l0, inv1 = 1.f / run_l1;
    float* c0 = ctx + qg0;
    #pragma unroll
    for (int j2 = 0; j2 < 8; j2++) {
        *(float2*)&c0[j2 * 8 + 2 * tid4] =
            make_float2(to_tf32(o[j2][0] * inv0), to_tf32(o[j2][1] * inv0));
        *(float2*)&c0[(size_t)8 * D_ + j2 * 8 + 2 * tid4] =
            make_float2(to_tf32(o[j2][2] * inv1), to_tf32(o[j2][3] * inv1));
    }
}

// -------- host launcher --------
extern "C" void kernel_launch(void* const* d_in, const int* in_sizes, int n_in,
                              void* d_out, int out_size) {
    const float* upd   = (const float*)d_in[0];
    const float* emb   = (const float*)d_in[1];
    const float* maskl = (const float*)d_in[2];
    const float* Wq    = (const float*)d_in[3];
    const float* Wk    = (const float*)d_in[4];
    const float* Wv    = (const float*)d_in[5];
    const float* Wo    = (const float*)d_in[6];
    const float* W1    = (const float*)d_in[7];
    const float* b1    = (const float*)d_in[8];
    const float* W2    = (const float*)d_in[9];
    const float* b2    = (const float*)d_in[10];
    const float* sys_s = (const float*)d_in[11];
    const float* sys_b = (const float*)d_in[12];
    const float* eff_s = (const float*)d_in[13];
    const float* eff_b = (const float*)d_in[14];
    const float* in_s  = (const float*)d_in[15];
    const float* in_b  = (const float*)d_in[16];
    const float* out_s = (const float*)d_in[17];
    const float* out_b = (const float*)d_in[18];
    const int*   qidx  = (const int*)d_in[19];
    const int*   kidx  = (const int*)d_in[20];
    float* out = (float*)d_out;

    float *qb, *kb, *Qp, *Kp, *Vp, *ctx, *hb, *t1, *fb, *Wr;
    unsigned long long* mbp;
    cudaGetSymbolAddress((void**)&qb,  g_q);
    cudaGetSymbolAddress((void**)&kb,  g_k);
    cudaGetSymbolAddress((void**)&Qp,  g_Qp);
    cudaGetSymbolAddress((void**)&Kp,  g_Kp);
    cudaGetSymbolAddress((void**)&Vp,  g_Vp);
    cudaGetSymbolAddress((void**)&ctx, g_ctx);
    cudaGetSymbolAddress((void**)&hb,  g_h);
    cudaGetSymbolAddress((void**)&t1,  g_t1);
    cudaGetSymbolAddress((void**)&fb,  g_f);
    cudaGetSymbolAddress((void**)&Wr,  g_Wr);
    cudaGetSymbolAddress((void**)&mbp, g_mb);

    cudaFuncSetAttribute(flash_attn, cudaFuncAttributeMaxDynamicSharedMemorySize, (int)FA_SMEM);
    cudaFuncSetAttribute(gemm_tc<0>, cudaFuncAttributeMaxDynamicSharedMemorySize, (int)GEMM_SMEM);
    cudaFuncSetAttribute(gemm_tc<1>, cudaFuncAttributeMaxDynamicSharedMemorySize, (int)GEMM_SMEM);
    cudaFuncSetAttribute(gemm_tc<2>, cudaFuncAttributeMaxDynamicSharedMemorySize, (int)GEMM_SMEM);
    cudaFuncSetAttribute(gemm_qkv,   cudaFuncAttributeMaxDynamicSharedMemorySize, (int)GEMM_SMEM);

    prep_kernel<<<39296, 256>>>(upd, out, Wq, Wk, Wv, Wo, W1, W2, maskl);

    const float* rWq = Wr;
    const float* rWk = Wr + 1 * 65536;
    const float* rWv = Wr + 2 * 65536;
    const float* rWo = Wr + 3 * 65536;
    const float* rW1 = Wr + 4 * 65536;
    const float* rW2 = Wr + 5 * 65536;

    for (int l = 0; l < L_; l++) {
        gather_ln_qk<<<(MQ + MK) / 8, 256>>>(emb, qidx + l * NQ_, kidx + l * NK_,
                                             sys_s, sys_b, qb, kb);

        gemm_qkv<<<1280, 256, GEMM_SMEM>>>(qb, kb, rWq, rWk, rWv, Qp, Kp, Vp);

        flash_attn<<<dim3(NQ_ / 128, H_, B_), 256, FA_SMEM>>>(
            Qp, Kp, Vp, mbp + (size_t)l * NQ_ * 16, ctx);

        gemm_tc<0><<<dim3(2, MQ / 128), 256, GEMM_SMEM>>>(ctx, rWo, nullptr, t1);
        ln_w<<<MQ / 8, 256>>>(t1, in_s, in_b, hb);

        gemm_tc<2><<<dim3(2, MQ / 128), 256, GEMM_SMEM>>>(hb, rW1, b1, t1);
        gemm_tc<0><<<dim3(2, MQ / 128), 256, GEMM_SMEM>>>(t1, rW2, nullptr, fb);

        add_ln_scatter<<<MQ / 8, 256>>>(hb, fb, b2, out_s, out_b, eff_s, eff_b,
                                        qidx + l * NQ_, out);
    }
}

// round 15
// speedup vs baseline: 15.5286x; 1.0540x over previous
#include <cuda_runtime.h>
#include <cuda_bf16.h>
#include <mma.h>
#include <math.h>

using namespace nvcuda;

// Problem constants
#define B_   32
#define NS_  4096
#define D_   256
#define H_   4
#define L_   6
#define NQ_  512
#define NK_  1024
#define DH_  64
#define SCALE_ 0.125f

#define MQ (B_*NQ_)   // 16384 rows
#define MK (B_*NK_)   // 32768 rows

// d-permutation within 8-groups: logical k and k+4 become adjacent storage slots
// slot(c) = (c&3)*2 + (c>>2)   for c in 0..7 ; invp(slot) = {0,4,1,5,2,6,3,7}
#define PERM8(c)  (((c) & ~7) | ((((c) & 3) << 1) | ((((c) >> 2) & 1))))

// -------- persistent device scratch (static, no allocation) --------
__device__ float g_U  [(size_t)B_*NS_*D_];   // logical layout
__device__ float g_q  [(size_t)MQ*D_];       // P-space (d-permuted)
__device__ float g_k  [(size_t)MK*D_];       // P-space
__device__ float g_Qp [(size_t)MQ*D_];       // P-space
__device__ float g_Kp [(size_t)MK*D_];       // P-space
__device__ float g_Vp [(size_t)MK*D_];       // P-space
__device__ float g_ctx[(size_t)MQ*D_];       // P-space
__device__ float g_h  [(size_t)MQ*D_];       // P-space
__device__ float g_t1 [(size_t)MQ*D_];       // P-space
__device__ float g_f  [(size_t)MQ*D_];       // P-space
__device__ float g_Wr [6 * 256 * 256];       // tf32-rounded, P-space rows AND cols
__device__ unsigned long long g_mb[(size_t)L_*NQ_*16];   // mask bitmaps (key dim)

// -------- helpers --------
__device__ __forceinline__ float to_tf32(float x) { return wmma::__float_to_tf32(x); }

__device__ __forceinline__ float wsum(float v) {
    #pragma unroll
    for (int o = 16; o; o >>= 1) v += __shfl_xor_sync(0xffffffffu, v, o);
    return v;
}

__device__ __forceinline__ float gelu_tanh(float x) {
    float x3 = x * x * x;
    float t = tanhf(0.7978845608028654f * (x + 0.044715f * x3));
    return 0.5f * x * (1.f + t);
}

__device__ __forceinline__ void cp16(void* dst, const void* src) {
    unsigned s = (unsigned)__cvta_generic_to_shared(dst);
    asm volatile("cp.async.cg.shared.global [%0], [%1], 16;\n" :: "r"(s), "l"(src));
}
#define CP_COMMIT() asm volatile("cp.async.commit_group;\n")
#define CP_WAIT(n)  asm volatile("cp.async.wait_group %0;\n" :: "n"(n))

#define MMA_TF32(c, a0, a1, a2, a3, b0v, b1v) \
    asm volatile("mma.sync.aligned.m16n8k8.row.col.f32.tf32.tf32.f32 " \
        "{%0,%1,%2,%3}, {%4,%5,%6,%7}, {%8,%9}, {%0,%1,%2,%3};" \
        : "+f"(c[0]), "+f"(c[1]), "+f"(c[2]), "+f"(c[3]) \
        : "r"(a0), "r"(a1), "r"(a2), "r"(a3), "r"(b0v), "r"(b1v))

// -------- mega prep: init U/out (float4) | round+permute weights | mask bitmaps --------
// grid regions: [0,32768) init x4, [32768, 33152) weights, [33152, 39296) mask
__global__ void prep_kernel(const float* __restrict__ upd, float* __restrict__ out,
                            const float* __restrict__ w0, const float* __restrict__ w1,
                            const float* __restrict__ w2, const float* __restrict__ w3,
                            const float* __restrict__ w4, const float* __restrict__ w5,
                            const float* __restrict__ maskl) {
    int bid = blockIdx.x, tid = threadIdx.x;
    if (bid < 32768) {
        // float4 copy: 32768 * 256 * 4 = 33,554,432 = B*NS*D exactly
        size_t i = ((size_t)bid * 256 + tid) * 4;
        float4 v = *(const float4*)(upd + i);
        *(float4*)(g_U + i) = v;
        *(float4*)(out + i) = make_float4(0.f, 0.f, 0.f, 0.f);
    } else if (bid < 33152) {
        int wb = bid - 32768;
        int widx = wb >> 6, blk = wb & 63;
        const float* src;
        switch (widx) {
            case 0: src = w0; break; case 1: src = w1; break;
            case 2: src = w2; break; case 3: src = w3; break;
            case 4: src = w4; break; default: src = w5; break;
        }
        int e = (blk * 256 + tid) * 4;
        int r = e >> 8, c0 = e & 255;
        float4 v = *(const float4*)(src + (size_t)r * 256 + c0);
        int rp = PERM8(r);
        float* dst = g_Wr + (size_t)widx * 65536 + (size_t)rp * 256;
        dst[PERM8(c0 + 0)] = to_tf32(v.x);
        dst[PERM8(c0 + 1)] = to_tf32(v.y);
        dst[PERM8(c0 + 2)] = to_tf32(v.z);
        dst[PERM8(c0 + 3)] = to_tf32(v.w);
    } else {
        size_t gt = (size_t)(bid - 33152) * 256 + tid;
        size_t wid = gt >> 5;
        int lane = (int)(gt & 31);
        const float* src = maskl + wid * 64;
        unsigned lo = __ballot_sync(0xffffffffu, src[lane]      > 0.5f);
        unsigned hi = __ballot_sync(0xffffffffu, src[lane + 32] > 0.5f);
        if (lane == 0) g_mb[wid] = (unsigned long long)lo | ((unsigned long long)hi << 32);
    }
}

// -------- gather + LN(sys), q and k in one launch; writes P-space --------
__global__ void gather_ln_qk(const float* __restrict__ emb,
                             const int* __restrict__ qidx, const int* __restrict__ kidx,
                             const float* __restrict__ sc, const float* __restrict__ bi,
                             float* __restrict__ qout, float* __restrict__ kout) {
    int gw = (blockIdx.x * blockDim.x + threadIdx.x) >> 5;   // 0..MQ+MK-1
    int lane = threadIdx.x & 31;
    int id, b_of; float* o;
    if (gw < MQ) {
        int i = gw & 511; b_of = gw >> 9;
        id = qidx[i];
        o = qout + ((size_t)((b_of << 9) + i)) * D_;
    } else {
        int g2 = gw - MQ;
        int i = g2 & 1023; b_of = g2 >> 10;
        id = kidx[i];
        o = kout + ((size_t)((b_of << 10) + i)) * D_;
    }
    const float* e = emb + (size_t)id * D_;
    const float* u = g_U + ((size_t)b_of * NS_ + id) * D_;
    int c = lane * 8;
    float4 p0 = *(const float4*)(e + c), p1 = *(const float4*)(e + c + 4);
    float4 u0 = *(const float4*)(u + c), u1 = *(const float4*)(u + c + 4);
    float x[8] = {p0.x + u0.x, p0.y + u0.y, p0.z + u0.z, p0.w + u0.w,
                  p1.x + u1.x, p1.y + u1.y, p1.z + u1.z, p1.w + u1.w};
    float s = 0.f;
    #pragma unroll
    for (int j = 0; j < 8; j++) s += x[j];
    float m = wsum(s) * (1.f / D_);
    float vs = 0.f;
    #pragma unroll
    for (int j = 0; j < 8; j++) { float d = x[j] - m; vs += d * d; }
    float r = rsqrtf(wsum(vs) * (1.f / D_) + 1e-5f);
    float4 s0 = *(const float4*)(sc + c), s1 = *(const float4*)(sc + c + 4);
    float4 b0 = *(const float4*)(bi + c), b1 = *(const float4*)(bi + c + 4);
    float v[8];   // logical values
    v[0] = to_tf32((x[0] - m) * r * s0.x + b0.x);
    v[1] = to_tf32((x[1] - m) * r * s0.y + b0.y);
    v[2] = to_tf32((x[2] - m) * r * s0.z + b0.z);
    v[3] = to_tf32((x[3] - m) * r * s0.w + b0.w);
    v[4] = to_tf32((x[4] - m) * r * s1.x + b1.x);
    v[5] = to_tf32((x[5] - m) * r * s1.y + b1.y);
    v[6] = to_tf32((x[6] - m) * r * s1.z + b1.z);
    v[7] = to_tf32((x[7] - m) * r * s1.w + b1.w);
    // pack P-space: slot j holds logical invp(j) = {0,4,1,5,2,6,3,7}
    *(float4*)(o + c)     = make_float4(v[0], v[4], v[1], v[5]);
    *(float4*)(o + c + 4) = make_float4(v[2], v[6], v[3], v[7]);
}

// -------- plain LN (P-space in/out) --------
__global__ void ln_w(const float* __restrict__ in, const float* __restrict__ sc,
                     const float* __restrict__ bi, float* __restrict__ out) {
    int row = (blockIdx.x * blockDim.x + threadIdx.x) >> 5;
    int lane = threadIdx.x & 31;
    int c = lane * 8;
    const float* ir = in + (size_t)row * D_ + c;
    float4 p0 = *(const float4*)ir, p1 = *(const float4*)(ir + 4);
    float x[8] = {p0.x, p0.y, p0.z, p0.w, p1.x, p1.y, p1.z, p1.w};  // slot order
    float s = 0.f;
    #pragma unroll
    for (int j = 0; j < 8; j++) s += x[j];
    float m = wsum(s) * (1.f / D_);
    float vs = 0.f;
    #pragma unroll
    for (int j = 0; j < 8; j++) { float d = x[j] - m; vs += d * d; }
    float r = rsqrtf(wsum(vs) * (1.f / D_) + 1e-5f);
    float4 s0 = *(const float4*)(sc + c), s1 = *(const float4*)(sc + c + 4);
    float4 b0 = *(const float4*)(bi + c), b1 = *(const float4*)(bi + c + 4);
    // slot j pairs with logical sc/bi invp(j)
    float scp[8] = {s0.x, s1.x, s0.y, s1.y, s0.z, s1.z, s0.w, s1.w};
    float bip[8] = {b0.x, b1.x, b0.y, b1.y, b0.z, b1.z, b0.w, b1.w};
    float* o = out + (size_t)row * D_ + c;
    float4 o0, o1;
    o0.x = to_tf32((x[0] - m) * r * scp[0] + bip[0]);
    o0.y = to_tf32((x[1] - m) * r * scp[1] + bip[1]);
    o0.z = to_tf32((x[2] - m) * r * scp[2] + bip[2]);
    o0.w = to_tf32((x[3] - m) * r * scp[3] + bip[3]);
    o1.x = to_tf32((x[4] - m) * r * scp[4] + bip[4]);
    o1.y = to_tf32((x[5] - m) * r * scp[5] + bip[5]);
    o1.z = to_tf32((x[6] - m) * r * scp[6] + bip[6]);
    o1.w = to_tf32((x[7] - m) * r * scp[7] + bip[7]);
    *(float4*)o = o0;
    *(float4*)(o + 4) = o1;
}

// -------- fused: residual(+b2) + LN + LN + scatter (P-space in, logical out) --------
__global__ void add_ln_scatter(const float* __restrict__ hb, const float* __restrict__ fb,
                               const float* __restrict__ b2,
                               const float* __restrict__ os, const float* __restrict__ ob,
                               const float* __restrict__ es, const float* __restrict__ eb,
                               const int* __restrict__ qidx, float* __restrict__ out) {
    int row = (blockIdx.x * blockDim.x + threadIdx.x) >> 5;   // 0..MQ-1
    int lane = threadIdx.x & 31;
    int b = row >> 9, i = row & 511;
    int c = lane * 8;
    const float* hr = hb + (size_t)row * D_ + c;
    const float* fr = fb + (size_t)row * D_ + c;
    float4 h0 = *(const float4*)hr, h1 = *(const float4*)(hr + 4);
    float4 f0 = *(const float4*)fr, f1 = *(const float4*)(fr + 4);
    float4 c0 = *(const float4*)(b2 + c), c1 = *(const float4*)(b2 + c + 4);
    float b2p[8] = {c0.x, c1.x, c0.y, c1.y, c0.z, c1.z, c0.w, c1.w};
    float x[8] = {h0.x + f0.x + b2p[0], h0.y + f0.y + b2p[1],
                  h0.z + f0.z + b2p[2], h0.w + f0.w + b2p[3],
                  h1.x + f1.x + b2p[4], h1.y + f1.y + b2p[5],
                  h1.z + f1.z + b2p[6], h1.w + f1.w + b2p[7]};
    float s = 0.f;
    #pragma unroll
    for (int j = 0; j < 8; j++) s += x[j];
    float m = wsum(s) * (1.f / D_);
    float vs = 0.f;
    #pragma unroll
    for (int j = 0; j < 8; j++) { float d = x[j] - m; vs += d * d; }
    float r = rsqrtf(wsum(vs) * (1.f / D_) + 1e-5f);
    float4 os0 = *(const float4*)(os + c), os1 = *(const float4*)(os + c + 4);
    float4 ob0 = *(const float4*)(ob + c), ob1 = *(const float4*)(ob + c + 4);
    float osp[8] = {os0.x, os1.x, os0.y, os1.y, os0.z, os1.z, os0.w, os1.w};
    float obp[8] = {ob0.x, ob1.x, ob0.y, ob1.y, ob0.z, ob1.z, ob0.w, ob1.w};
    float u[8];
    #pragma unroll
    for (int j = 0; j < 8; j++) u[j] = (x[j] - m) * r * osp[j] + obp[j];
    float s2 = 0.f;
    #pragma unroll
    for (int j = 0; j < 8; j++) s2 += u[j];
    float m2 = wsum(s2) * (1.f / D_);
    float vs2 = 0.f;
    #pragma unroll
    for (int j = 0; j < 8; j++) { float d = u[j] - m2; vs2 += d * d; }
    float r2 = rsqrtf(wsum(vs2) * (1.f / D_) + 1e-5f);
    float4 es0 = *(const float4*)(es + c), es1 = *(const float4*)(es + c + 4);
    float4 eb0 = *(const float4*)(eb + c), eb1 = *(const float4*)(eb + c + 4);
    float esp[8] = {es0.x, es1.x, es0.y, es1.y, es0.z, es1.z, es0.w, es1.w};
    float ebp[8] = {eb0.x, eb1.x, eb0.y, eb1.y, eb0.z, eb1.z, eb0.w, eb1.w};
    int id = qidx[i];
    size_t base = ((size_t)b * NS_ + id) * D_ + c;
    const int I[8] = {0, 4, 1, 5, 2, 6, 3, 7};   // slot -> logical offset
    #pragma unroll
    for (int j = 0; j < 8; j++) {
        float v = (u[j] - m2) * r2 * esp[j] + ebp[j];
        atomicAdd(&g_U[base + I[j]], v);
        atomicAdd(&out[base + I[j]], v);
    }
}

// -------- tf32 GEMM, P-space operands, float2 A-frag loads --------
#define AS_LD 40
#define BS_LD 132
#define AS_STG (128 * AS_LD)
#define BS_STG (32 * BS_LD)
#define GEMM_SMEM ((2 * AS_STG + 2 * BS_STG) * sizeof(float))

template<int EPI>   // 0 plain, 1 tf32-round, 2 bias+gelu+round
__device__ __forceinline__ void gemm_body(const float* __restrict__ A,
                                          const float* __restrict__ W,
                                          const float* __restrict__ bias,
                                          float* __restrict__ C,
                                          int bm, int bn, float* sm) {
    float* As = sm;
    float* Bs = sm + 2 * AS_STG;
    int t = threadIdx.x, w = t >> 5, lane = t & 31;
    int gid = lane >> 2, tid4 = lane & 3;
    int wm = (w >> 2) * 64, wn = (w & 3) * 32;

    float acc[4][4][4] = {};
    float bb[4][2];
    if (EPI == 2) {
        #pragma unroll
        for (int nj = 0; nj < 4; nj++) {
            bb[nj][0] = bias[bn + wn + nj * 8 + tid4];
            bb[nj][1] = bias[bn + wn + nj * 8 + tid4 + 4];
        }
    }

    auto load_stage = [&](int ks, int bf) {
        int k0 = ks * 32;
        #pragma unroll
        for (int i = 0; i < 4; i++) {
            int idx = t + i * 256;
            {   int row = idx >> 3, c4 = (idx & 7) * 4;
                cp16(As + bf * AS_STG + row * AS_LD + c4,
                     A + (size_t)(bm + row) * 256 + k0 + c4); }
            {   int row = idx >> 5, c4 = (idx & 31) * 4;
                cp16(Bs + bf * BS_STG + row * BS_LD + c4,
                     W + (size_t)(k0 + row) * 256 + bn + c4); }
        }
    };

    load_stage(0, 0); CP_COMMIT();
    int buf = 0;
    for (int ks8 = 0; ks8 < 8; ks8++) {
        CP_WAIT(0);
        __syncthreads();
        if (ks8 < 7) { load_stage(ks8 + 1, buf ^ 1); CP_COMMIT(); }
        const float* Ab = As + buf * AS_STG;
        const float* Bb = Bs + buf * BS_STG;
        #pragma unroll
        for (int ks = 0; ks < 4; ks++) {
            unsigned a[4][4];
            #pragma unroll
            for (int mi = 0; mi < 4; mi++) {
                float2 lo = *(const float2*)(Ab + (wm + mi * 16 + gid) * AS_LD + ks * 8 + tid4 * 2);
                float2 hi = *(const float2*)(Ab + (wm + mi * 16 + gid + 8) * AS_LD + ks * 8 + tid4 * 2);
                a[mi][0] = __float_as_uint(lo.x);
                a[mi][1] = __float_as_uint(hi.x);
                a[mi][2] = __float_as_uint(lo.y);
                a[mi][3] = __float_as_uint(hi.y);
            }
            #pragma unroll
            for (int nj = 0; nj < 4; nj++) {
                const float* bp = Bb + (ks * 8 + tid4 * 2) * BS_LD + wn + nj * 8 + gid;
                unsigned b0 = __float_as_uint(bp[0]);
                unsigned b1 = __float_as_uint(bp[BS_LD]);
                #pragma unroll
                for (int mi = 0; mi < 4; mi++)
                    MMA_TF32(acc[mi][nj], a[mi][0], a[mi][1], a[mi][2], a[mi][3], b0, b1);
            }
        }
        buf ^= 1;
    }

    #pragma unroll
    for (int mi = 0; mi < 4; mi++) {
        int r0 = bm + wm + mi * 16 + gid;
        #pragma unroll
        for (int nj = 0; nj < 4; nj++) {
            int col = bn + wn + nj * 8 + tid4 * 2;
            float c0 = acc[mi][nj][0], c1 = acc[mi][nj][1];
            float c2 = acc[mi][nj][2], c3 = acc[mi][nj][3];
            if (EPI == 1) {
                c0 = to_tf32(c0); c1 = to_tf32(c1); c2 = to_tf32(c2); c3 = to_tf32(c3);
            }
            if (EPI == 2) {
                c0 = to_tf32(gelu_tanh(c0 + bb[nj][0]));
                c1 = to_tf32(gelu_tanh(c1 + bb[nj][1]));
                c2 = to_tf32(gelu_tanh(c2 + bb[nj][0]));
                c3 = to_tf32(gelu_tanh(c3 + bb[nj][1]));
            }
            *(float2*)&C[(size_t)r0 * 256 + col] = make_float2(c0, c1);
            *(float2*)&C[(size_t)(r0 + 8) * 256 + col] = make_float2(c2, c3);
        }
    }
}

template<int EPI>
__global__ __launch_bounds__(256, 2)
void gemm_tc(const float* __restrict__ A, const float* __restrict__ W,
             const float* __restrict__ bias, float* __restrict__ C) {
    extern __shared__ float sm[];
    gemm_body<EPI>(A, W, bias, C, blockIdx.y * 128, blockIdx.x * 128, sm);
}

// batched Q/K/V projection: grid.x = 1280; decode (n-half, tile, which)
__global__ __launch_bounds__(256, 2)
void gemm_qkv(const float* __restrict__ qb, const float* __restrict__ kb,
              const float* __restrict__ Wq, const float* __restrict__ Wk,
              const float* __restrict__ Wv,
              float* __restrict__ Qp, float* __restrict__ Kp, float* __restrict__ Vp) {
    extern __shared__ float sm[];
    int u = blockIdx.x;
    int bn = (u & 1) * 128;
    int v = u >> 1;
    const float* A; const float* W; float* C; int bm;
    if (v < 128)      { A = qb; W = Wq; C = Qp; bm = v * 128; }
    else if (v < 384) { A = kb; W = Wk; C = Kp; bm = (v - 128) * 128; }
    else              { A = kb; W = Wv; C = Vp; bm = (v - 384) * 128; }
    gemm_body<1>(A, W, nullptr, C, bm, bn, sm);
}

// -------- flash attention: register-direct PV (V key-rows PERM8'd in smem) --------
#define KS_LD 72
#define VS_LD 72
#define KS_STG (64 * KS_LD)
#define VS_STG (64 * VS_LD)
#define FA_SMEM ((2 * KS_STG + 2 * VS_STG) * sizeof(float))

__global__ __launch_bounds__(256, 1)
void flash_attn(const float* __restrict__ Qp, const float* __restrict__ Kp,
                const float* __restrict__ Vp, const unsigned long long* __restrict__ mb,
                float* __restrict__ ctx) {
    extern __shared__ float sm[];
    float* Ks0 = sm;
    float* Vs0 = sm + 2 * KS_STG;
    int t = threadIdx.x, lane = t & 31, w = t >> 5;
    int gid = lane >> 2, tid4 = lane & 3;
    int qb = blockIdx.x, h = blockIdx.y, b = blockIdx.z;

    int qrow = qb * 128 + w * 16 + gid;
    size_t qg0 = ((size_t)b * NQ_ + qrow) * D_ + h * DH_;

    unsigned qa[8][4];
    #pragma unroll
    for (int kc = 0; kc < 8; kc++) {
        float2 lo = *(const float2*)(Qp + qg0 + kc * 8 + tid4 * 2);
        float2 hi = *(const float2*)(Qp + qg0 + (size_t)8 * D_ + kc * 8 + tid4 * 2);
        qa[kc][0] = __float_as_uint(lo.x);
        qa[kc][1] = __float_as_uint(hi.x);
        qa[kc][2] = __float_as_uint(lo.y);
        qa[kc][3] = __float_as_uint(hi.y);
    }

    float o[8][4];
    #pragma unroll
    for (int j = 0; j < 8; j++) { o[j][0] = o[j][1] = o[j][2] = o[j][3] = 0.f; }
    float run_m0 = -1e30f, run_m1 = -1e30f, run_l0 = 0.f, run_l1 = 0.f;

    auto load_stage = [&](int kt2, int bf) {
        const float* kg = Kp + ((size_t)b * NK_ + kt2 * 64) * D_ + h * DH_;
        const float* vg = Vp + ((size_t)b * NK_ + kt2 * 64) * D_ + h * DH_;
        float* kd = Ks0 + bf * KS_STG;
        float* vd = Vs0 + bf * VS_STG;
        #pragma unroll
        for (int i = 0; i < 4; i++) {
            int idx = t + i * 256;
            int row = idx >> 4, c4 = (idx & 15) * 4;
            // K: natural key order (mask indexing depends on it)
            cp16(kd + row * KS_LD + c4, kg + (size_t)row * D_ + c4);
            // V: key rows permuted so tile row r holds logical key (r&~7)|PERM8(r&7);
            // then MMA k-slot k contracts against logical key PERM8(k), matching the
            // S C-fragment register order (keys 2t, 2t+1 per thread).
            int vrow = PERM8(row);
            cp16(vd + row * VS_LD + c4, vg + (size_t)vrow * D_ + c4);
        }
    };

    load_stage(0, 0); CP_COMMIT();
    int buf = 0;
    for (int kt = 0; kt < 16; kt++) {
        CP_WAIT(0);
        __syncthreads();
        if (kt < 15) { load_stage(kt + 1, buf ^ 1); CP_COMMIT(); }
        const float* Kb = Ks0 + buf * KS_STG;
        const float* Vb = Vs0 + buf * VS_STG;

        // ---- S = Q . K^T ----
        float s[8][4];
        #pragma unroll
        for (int j = 0; j < 8; j++) { s[j][0] = s[j][1] = s[j][2] = s[j][3] = 0.f; }
        #pragma unroll
        for (int kc = 0; kc < 8; kc++) {
            #pragma unroll
            for (int j = 0; j < 8; j++) {
                float2 kk = *(const float2*)(Kb + (j * 8 + gid) * KS_LD + kc * 8 + tid4 * 2);
                MMA_TF32(s[j], qa[kc][0], qa[kc][1], qa[kc][2], qa[kc][3],
                         __float_as_uint(kk.x), __float_as_uint(kk.y));
            }
        }

        // ---- mask + online softmax, P rounded in-register ----
        unsigned long long w0 = mb[(size_t)qrow * 16 + kt];
        unsigned long long w1 = mb[(size_t)(qrow + 8) * 16 + kt];
        float mx0 = -1e30f, mx1 = -1e30f;
        #pragma unroll
        for (int j = 0; j < 8; j++) {
            int sh = j * 8 + 2 * tid4;
            s[j][0] = ((w0 >> sh) & 1ull)       ? s[j][0] * SCALE_ : -1e9f;
            s[j][1] = ((w0 >> (sh + 1)) & 1ull) ? s[j][1] * SCALE_ : -1e9f;
            s[j][2] = ((w1 >> sh) & 1ull)       ? s[j][2] * SCALE_ : -1e9f;
            s[j][3] = ((w1 >> (sh + 1)) & 1ull) ? s[j][3] * SCALE_ : -1e9f;
            mx0 = fmaxf(mx0, fmaxf(s[j][0], s[j][1]));
            mx1 = fmaxf(mx1, fmaxf(s[j][2], s[j][3]));
        }
        mx0 = fmaxf(mx0, __shfl_xor_sync(0xffffffffu, mx0, 1));
        mx0 = fmaxf(mx0, __shfl_xor_sync(0xffffffffu, mx0, 2));
        mx1 = fmaxf(mx1, __shfl_xor_sync(0xffffffffu, mx1, 1));
        mx1 = fmaxf(mx1, __shfl_xor_sync(0xffffffffu, mx1, 2));
        float nm0 = fmaxf(run_m0, mx0), nm1 = fmaxf(run_m1, mx1);
        float fac0 = __expf(run_m0 - nm0), fac1 = __expf(run_m1 - nm1);
        run_m0 = nm0; run_m1 = nm1;
        float sum0 = 0.f, sum1 = 0.f;
        #pragma unroll
        for (int j = 0; j < 8; j++) {
            float e0 = __expf(s[j][0] - nm0), e1 = __expf(s[j][1] - nm0);
            float e2 = __expf(s[j][2] - nm1), e3 = __expf(s[j][3] - nm1);
            sum0 += e0 + e1; sum1 += e2 + e3;
            s[j][0] = to_tf32(e0); s[j][1] = to_tf32(e1);
            s[j][2] = to_tf32(e2); s[j][3] = to_tf32(e3);
        }
        sum0 += __shfl_xor_sync(0xffffffffu, sum0, 1);
        sum0 += __shfl_xor_sync(0xffffffffu, sum0, 2);
        sum1 += __shfl_xor_sync(0xffffffffu, sum1, 1);
        sum1 += __shfl_xor_sync(0xffffffffu, sum1, 2);
        run_l0 = run_l0 * fac0 + sum0;
        run_l1 = run_l1 * fac1 + sum1;
        #pragma unroll
        for (int j = 0; j < 8; j++) { o[j][0] *= fac0; o[j][1] *= fac0; o[j][2] *= fac1; o[j][3] *= fac1; }

        // ---- O += P . V : P straight from registers ----
        // A-frag (a0,a1,a2,a3) = (s[kc][0], s[kc][2], s[kc][1], s[kc][3]):
        //   a0 = (row gid,   k=tid4)   = key 2*tid4   = s[kc][0]
        //   a1 = (row gid+8, k=tid4)   = key 2*tid4   = s[kc][2]
        //   a2 = (row gid,   k=tid4+4) = key 2*tid4+1 = s[kc][1]
        //   a3 = (row gid+8, k=tid4+4) = key 2*tid4+1 = s[kc][3]
        #pragma unroll
        for (int kc = 0; kc < 8; kc++) {
            unsigned pa0 = __float_as_uint(s[kc][0]);
            unsigned pa1 = __float_as_uint(s[kc][2]);
            unsigned pa2 = __float_as_uint(s[kc][1]);
            unsigned pa3 = __float_as_uint(s[kc][3]);
            #pragma unroll
            for (int j2 = 0; j2 < 8; j2++) {
                unsigned b0 = __float_as_uint(Vb[(kc * 8 + tid4) * VS_LD + j2 * 8 + gid]);
                unsigned b1 = __float_as_uint(Vb[(kc * 8 + tid4 + 4) * VS_LD + j2 * 8 + gid]);
                MMA_TF32(o[j2], pa0, pa1, pa2, pa3, b0, b1);
            }
        }
        buf ^= 1;
    }

    float inv0 = 1.f / run_l0, inv1 = 1.f / run_l1;
    float* c0 = ctx + qg0;
    #pragma unroll
    for (int j2 = 0; j2 < 8; j2++) {
        *(float2*)&c0[j2 * 8 + 2 * tid4] =
            make_float2(to_tf32(o[j2][0] * inv0), to_tf32(o[j2][1] * inv0));
        *(float2*)&c0[(size_t)8 * D_ + j2 * 8 + 2 * tid4] =
            make_float2(to_tf32(o[j2][2] * inv1), to_tf32(o[j2][3] * inv1));
    }
}

// -------- host launcher --------
extern "C" void kernel_launch(void* const* d_in, const int* in_sizes, int n_in,
                              void* d_out, int out_size) {
    const float* upd   = (const float*)d_in[0];
    const float* emb   = (const float*)d_in[1];
    const float* maskl = (const float*)d_in[2];
    const float* Wq    = (const float*)d_in[3];
    const float* Wk    = (const float*)d_in[4];
    const float* Wv    = (const float*)d_in[5];
    const float* Wo    = (const float*)d_in[6];
    const float* W1    = (const float*)d_in[7];
    const float* b1    = (const float*)d_in[8];
    const float* W2    = (const float*)d_in[9];
    const float* b2    = (const float*)d_in[10];
    const float* sys_s = (const float*)d_in[11];
    const float* sys_b = (const float*)d_in[12];
    const float* eff_s = (const float*)d_in[13];
    const float* eff_b = (const float*)d_in[14];
    const float* in_s  = (const float*)d_in[15];
    const float* in_b  = (const float*)d_in[16];
    const float* out_s = (const float*)d_in[17];
    const float* out_b = (const float*)d_in[18];
    const int*   qidx  = (const int*)d_in[19];
    const int*   kidx  = (const int*)d_in[20];
    float* out = (float*)d_out;

    float *qb, *kb, *Qp, *Kp, *Vp, *ctx, *hb, *t1, *fb, *Wr;
    unsigned long long* mbp;
    cudaGetSymbolAddress((void**)&qb,  g_q);
    cudaGetSymbolAddress((void**)&kb,  g_k);
    cudaGetSymbolAddress((void**)&Qp,  g_Qp);
    cudaGetSymbolAddress((void**)&Kp,  g_Kp);
    cudaGetSymbolAddress((void**)&Vp,  g_Vp);
    cudaGetSymbolAddress((void**)&ctx, g_ctx);
    cudaGetSymbolAddress((void**)&hb,  g_h);
    cudaGetSymbolAddress((void**)&t1,  g_t1);
    cudaGetSymbolAddress((void**)&fb,  g_f);
    cudaGetSymbolAddress((void**)&Wr,  g_Wr);
    cudaGetSymbolAddress((void**)&mbp, g_mb);

    cudaFuncSetAttribute(flash_attn, cudaFuncAttributeMaxDynamicSharedMemorySize, (int)FA_SMEM);
    cudaFuncSetAttribute(gemm_tc<0>, cudaFuncAttributeMaxDynamicSharedMemorySize, (int)GEMM_SMEM);
    cudaFuncSetAttribute(gemm_tc<1>, cudaFuncAttributeMaxDynamicSharedMemorySize, (int)GEMM_SMEM);
    cudaFuncSetAttribute(gemm_tc<2>, cudaFuncAttributeMaxDynamicSharedMemorySize, (int)GEMM_SMEM);
    cudaFuncSetAttribute(gemm_qkv,   cudaFuncAttributeMaxDynamicSharedMemorySize, (int)GEMM_SMEM);

    prep_kernel<<<39296, 256>>>(upd, out, Wq, Wk, Wv, Wo, W1, W2, maskl);

    const float* rWq = Wr;
    const float* rWk = Wr + 1 * 65536;
    const float* rWv = Wr + 2 * 65536;
    const float* rWo = Wr + 3 * 65536;
    const float* rW1 = Wr + 4 * 65536;
    const float* rW2 = Wr + 5 * 65536;

    for (int l = 0; l < L_; l++) {
        gather_ln_qk<<<(MQ + MK) / 8, 256>>>(emb, qidx + l * NQ_, kidx + l * NK_,
                                             sys_s, sys_b, qb, kb);

        gemm_qkv<<<1280, 256, GEMM_SMEM>>>(qb, kb, rWq, rWk, rWv, Qp, Kp, Vp);

        flash_attn<<<dim3(NQ_ / 128, H_, B_), 256, FA_SMEM>>>(
            Qp, Kp, Vp, mbp + (size_t)l * NQ_ * 16, ctx);

        gemm_tc<0><<<dim3(2, MQ / 128), 256, GEMM_SMEM>>>(ctx, rWo, nullptr, t1);
        ln_w<<<MQ / 8, 256>>>(t1, in_s, in_b, hb);

        gemm_tc<2><<<dim3(2, MQ / 128), 256, GEMM_SMEM>>>(hb, rW1, b1, t1);
        gemm_tc<0><<<dim3(2, MQ / 128), 256, GEMM_SMEM>>>(t1, rW2, nullptr, fb);

        add_ln_scatter<<<MQ / 8, 256>>>(hb, fb, b2, out_s, out_b, eff_s, eff_b,
                                        qidx + l * NQ_, out);
    }
}

// round 16
// speedup vs baseline: 15.6481x; 1.0077x over previous
#include <cuda_runtime.h>
#include <cuda_bf16.h>
#include <mma.h>
#include <math.h>

using namespace nvcuda;

// Problem constants
#define B_   32
#define NS_  4096
#define D_   256
#define H_   4
#define L_   6
#define NQ_  512
#define NK_  1024
#define DH_  64
#define SCALE_ 0.125f

#define MQ (B_*NQ_)   // 16384 rows
#define MK (B_*NK_)   // 32768 rows

// d-permutation within 8-groups: logical k and k+4 become adjacent storage slots
// slot(c) = (c&3)*2 + (c>>2)   for c in 0..7 ; invp(slot) = {0,4,1,5,2,6,3,7}
#define PERM8(c)  (((c) & ~7) | ((((c) & 3) << 1) | ((((c) >> 2) & 1))))

// -------- persistent device scratch (static, no allocation) --------
__device__ float g_U  [(size_t)B_*NS_*D_];   // logical layout
__device__ float g_q  [(size_t)MQ*D_];       // P-space (d-permuted)
__device__ float g_k  [(size_t)MK*D_];       // P-space
__device__ float g_Qp [(size_t)MQ*D_];       // P-space
__device__ float g_Kp [(size_t)MK*D_];       // P-space
__device__ float g_Vp [(size_t)MK*D_];       // V TRANSPOSED: [(b*H+h)*64 + d_slot][key]
__device__ float g_ctx[(size_t)MQ*D_];       // P-space
__device__ float g_h  [(size_t)MQ*D_];       // P-space
__device__ float g_t1 [(size_t)MQ*D_];       // P-space
__device__ float g_f  [(size_t)MQ*D_];       // P-space
__device__ float g_Wr [6 * 256 * 256];       // tf32-rounded, P-space rows AND cols
__device__ unsigned long long g_mb[(size_t)L_*NQ_*16];   // mask bitmaps (key dim)

// -------- helpers --------
__device__ __forceinline__ float to_tf32(float x) { return wmma::__float_to_tf32(x); }

__device__ __forceinline__ float wsum(float v) {
    #pragma unroll
    for (int o = 16; o; o >>= 1) v += __shfl_xor_sync(0xffffffffu, v, o);
    return v;
}

__device__ __forceinline__ float gelu_tanh(float x) {
    float x3 = x * x * x;
    float t = tanhf(0.7978845608028654f * (x + 0.044715f * x3));
    return 0.5f * x * (1.f + t);
}

__device__ __forceinline__ void cp16(void* dst, const void* src) {
    unsigned s = (unsigned)__cvta_generic_to_shared(dst);
    asm volatile("cp.async.cg.shared.global [%0], [%1], 16;\n" :: "r"(s), "l"(src));
}
#define CP_COMMIT() asm volatile("cp.async.commit_group;\n")
#define CP_WAIT(n)  asm volatile("cp.async.wait_group %0;\n" :: "n"(n))

#define MMA_TF32(c, a0, a1, a2, a3, b0v, b1v) \
    asm volatile("mma.sync.aligned.m16n8k8.row.col.f32.tf32.tf32.f32 " \
        "{%0,%1,%2,%3}, {%4,%5,%6,%7}, {%8,%9}, {%0,%1,%2,%3};" \
        : "+f"(c[0]), "+f"(c[1]), "+f"(c[2]), "+f"(c[3]) \
        : "r"(a0), "r"(a1), "r"(a2), "r"(a3), "r"(b0v), "r"(b1v))

// -------- mega prep: init U/out (float4) | round+permute weights | mask bitmaps --------
// grid regions: [0,32768) init x4, [32768, 33152) weights, [33152, 39296) mask
__global__ void prep_kernel(const float* __restrict__ upd, float* __restrict__ out,
                            const float* __restrict__ w0, const float* __restrict__ w1,
                            const float* __restrict__ w2, const float* __restrict__ w3,
                            const float* __restrict__ w4, const float* __restrict__ w5,
                            const float* __restrict__ maskl) {
    int bid = blockIdx.x, tid = threadIdx.x;
    if (bid < 32768) {
        // float4 copy: 32768 * 256 * 4 = 33,554,432 = B*NS*D exactly
        size_t i = ((size_t)bid * 256 + tid) * 4;
        float4 v = *(const float4*)(upd + i);
        *(float4*)(g_U + i) = v;
        *(float4*)(out + i) = make_float4(0.f, 0.f, 0.f, 0.f);
    } else if (bid < 33152) {
        int wb = bid - 32768;
        int widx = wb >> 6, blk = wb & 63;
        const float* src;
        switch (widx) {
            case 0: src = w0; break; case 1: src = w1; break;
            case 2: src = w2; break; case 3: src = w3; break;
            case 4: src = w4; break; default: src = w5; break;
        }
        int e = (blk * 256 + tid) * 4;
        int r = e >> 8, c0 = e & 255;
        float4 v = *(const float4*)(src + (size_t)r * 256 + c0);
        int rp = PERM8(r);
        float* dst = g_Wr + (size_t)widx * 65536 + (size_t)rp * 256;
        dst[PERM8(c0 + 0)] = to_tf32(v.x);
        dst[PERM8(c0 + 1)] = to_tf32(v.y);
        dst[PERM8(c0 + 2)] = to_tf32(v.z);
        dst[PERM8(c0 + 3)] = to_tf32(v.w);
    } else {
        size_t gt = (size_t)(bid - 33152) * 256 + tid;
        size_t wid = gt >> 5;
        int lane = (int)(gt & 31);
        const float* src = maskl + wid * 64;
        unsigned lo = __ballot_sync(0xffffffffu, src[lane]      > 0.5f);
        unsigned hi = __ballot_sync(0xffffffffu, src[lane + 32] > 0.5f);
        if (lane == 0) g_mb[wid] = (unsigned long long)lo | ((unsigned long long)hi << 32);
    }
}

// -------- gather + LN(sys), q and k in one launch; writes P-space --------
__global__ void gather_ln_qk(const float* __restrict__ emb,
                             const int* __restrict__ qidx, const int* __restrict__ kidx,
                             const float* __restrict__ sc, const float* __restrict__ bi,
                             float* __restrict__ qout, float* __restrict__ kout) {
    int gw = (blockIdx.x * blockDim.x + threadIdx.x) >> 5;   // 0..MQ+MK-1
    int lane = threadIdx.x & 31;
    int id, b_of; float* o;
    if (gw < MQ) {
        int i = gw & 511; b_of = gw >> 9;
        id = qidx[i];
        o = qout + ((size_t)((b_of << 9) + i)) * D_;
    } else {
        int g2 = gw - MQ;
        int i = g2 & 1023; b_of = g2 >> 10;
        id = kidx[i];
        o = kout + ((size_t)((b_of << 10) + i)) * D_;
    }
    const float* e = emb + (size_t)id * D_;
    const float* u = g_U + ((size_t)b_of * NS_ + id) * D_;
    int c = lane * 8;
    float4 p0 = *(const float4*)(e + c), p1 = *(const float4*)(e + c + 4);
    float4 u0 = *(const float4*)(u + c), u1 = *(const float4*)(u + c + 4);
    float x[8] = {p0.x + u0.x, p0.y + u0.y, p0.z + u0.z, p0.w + u0.w,
                  p1.x + u1.x, p1.y + u1.y, p1.z + u1.z, p1.w + u1.w};
    float s = 0.f;
    #pragma unroll
    for (int j = 0; j < 8; j++) s += x[j];
    float m = wsum(s) * (1.f / D_);
    float vs = 0.f;
    #pragma unroll
    for (int j = 0; j < 8; j++) { float d = x[j] - m; vs += d * d; }
    float r = rsqrtf(wsum(vs) * (1.f / D_) + 1e-5f);
    float4 s0 = *(const float4*)(sc + c), s1 = *(const float4*)(sc + c + 4);
    float4 b0 = *(const float4*)(bi + c), b1 = *(const float4*)(bi + c + 4);
    float v[8];   // logical values
    v[0] = to_tf32((x[0] - m) * r * s0.x + b0.x);
    v[1] = to_tf32((x[1] - m) * r * s0.y + b0.y);
    v[2] = to_tf32((x[2] - m) * r * s0.z + b0.z);
    v[3] = to_tf32((x[3] - m) * r * s0.w + b0.w);
    v[4] = to_tf32((x[4] - m) * r * s1.x + b1.x);
    v[5] = to_tf32((x[5] - m) * r * s1.y + b1.y);
    v[6] = to_tf32((x[6] - m) * r * s1.z + b1.z);
    v[7] = to_tf32((x[7] - m) * r * s1.w + b1.w);
    // pack P-space: slot j holds logical invp(j) = {0,4,1,5,2,6,3,7}
    *(float4*)(o + c)     = make_float4(v[0], v[4], v[1], v[5]);
    *(float4*)(o + c + 4) = make_float4(v[2], v[6], v[3], v[7]);
}

// -------- plain LN (P-space in/out) --------
__global__ void ln_w(const float* __restrict__ in, const float* __restrict__ sc,
                     const float* __restrict__ bi, float* __restrict__ out) {
    int row = (blockIdx.x * blockDim.x + threadIdx.x) >> 5;
    int lane = threadIdx.x & 31;
    int c = lane * 8;
    const float* ir = in + (size_t)row * D_ + c;
    float4 p0 = *(const float4*)ir, p1 = *(const float4*)(ir + 4);
    float x[8] = {p0.x, p0.y, p0.z, p0.w, p1.x, p1.y, p1.z, p1.w};  // slot order
    float s = 0.f;
    #pragma unroll
    for (int j = 0; j < 8; j++) s += x[j];
    float m = wsum(s) * (1.f / D_);
    float vs = 0.f;
    #pragma unroll
    for (int j = 0; j < 8; j++) { float d = x[j] - m; vs += d * d; }
    float r = rsqrtf(wsum(vs) * (1.f / D_) + 1e-5f);
    float4 s0 = *(const float4*)(sc + c), s1 = *(const float4*)(sc + c + 4);
    float4 b0 = *(const float4*)(bi + c), b1 = *(const float4*)(bi + c + 4);
    // slot j pairs with logical sc/bi invp(j)
    float scp[8] = {s0.x, s1.x, s0.y, s1.y, s0.z, s1.z, s0.w, s1.w};
    float bip[8] = {b0.x, b1.x, b0.y, b1.y, b0.z, b1.z, b0.w, b1.w};
    float* o = out + (size_t)row * D_ + c;
    float4 o0, o1;
    o0.x = to_tf32((x[0] - m) * r * scp[0] + bip[0]);
    o0.y = to_tf32((x[1] - m) * r * scp[1] + bip[1]);
    o0.z = to_tf32((x[2] - m) * r * scp[2] + bip[2]);
    o0.w = to_tf32((x[3] - m) * r * scp[3] + bip[3]);
    o1.x = to_tf32((x[4] - m) * r * scp[4] + bip[4]);
    o1.y = to_tf32((x[5] - m) * r * scp[5] + bip[5]);
    o1.z = to_tf32((x[6] - m) * r * scp[6] + bip[6]);
    o1.w = to_tf32((x[7] - m) * r * scp[7] + bip[7]);
    *(float4*)o = o0;
    *(float4*)(o + 4) = o1;
}

// -------- fused: residual(+b2) + LN + LN + scatter (P-space in, logical out) --------
__global__ void add_ln_scatter(const float* __restrict__ hb, const float* __restrict__ fb,
                               const float* __restrict__ b2,
                               const float* __restrict__ os, const float* __restrict__ ob,
                               const float* __restrict__ es, const float* __restrict__ eb,
                               const int* __restrict__ qidx, float* __restrict__ out) {
    int row = (blockIdx.x * blockDim.x + threadIdx.x) >> 5;   // 0..MQ-1
    int lane = threadIdx.x & 31;
    int b = row >> 9, i = row & 511;
    int c = lane * 8;
    const float* hr = hb + (size_t)row * D_ + c;
    const float* fr = fb + (size_t)row * D_ + c;
    float4 h0 = *(const float4*)hr, h1 = *(const float4*)(hr + 4);
    float4 f0 = *(const float4*)fr, f1 = *(const float4*)(fr + 4);
    float4 c0 = *(const float4*)(b2 + c), c1 = *(const float4*)(b2 + c + 4);
    float b2p[8] = {c0.x, c1.x, c0.y, c1.y, c0.z, c1.z, c0.w, c1.w};
    float x[8] = {h0.x + f0.x + b2p[0], h0.y + f0.y + b2p[1],
                  h0.z + f0.z + b2p[2], h0.w + f0.w + b2p[3],
                  h1.x + f1.x + b2p[4], h1.y + f1.y + b2p[5],
                  h1.z + f1.z + b2p[6], h1.w + f1.w + b2p[7]};
    float s = 0.f;
    #pragma unroll
    for (int j = 0; j < 8; j++) s += x[j];
    float m = wsum(s) * (1.f / D_);
    float vs = 0.f;
    #pragma unroll
    for (int j = 0; j < 8; j++) { float d = x[j] - m; vs += d * d; }
    float r = rsqrtf(wsum(vs) * (1.f / D_) + 1e-5f);
    float4 os0 = *(const float4*)(os + c), os1 = *(const float4*)(os + c + 4);
    float4 ob0 = *(const float4*)(ob + c), ob1 = *(const float4*)(ob + c + 4);
    float osp[8] = {os0.x, os1.x, os0.y, os1.y, os0.z, os1.z, os0.w, os1.w};
    float obp[8] = {ob0.x, ob1.x, ob0.y, ob1.y, ob0.z, ob1.z, ob0.w, ob1.w};
    float u[8];
    #pragma unroll
    for (int j = 0; j < 8; j++) u[j] = (x[j] - m) * r * osp[j] + obp[j];
    float s2 = 0.f;
    #pragma unroll
    for (int j = 0; j < 8; j++) s2 += u[j];
    float m2 = wsum(s2) * (1.f / D_);
    float vs2 = 0.f;
    #pragma unroll
    for (int j = 0; j < 8; j++) { float d = u[j] - m2; vs2 += d * d; }
    float r2 = rsqrtf(wsum(vs2) * (1.f / D_) + 1e-5f);
    float4 es0 = *(const float4*)(es + c), es1 = *(const float4*)(es + c + 4);
    float4 eb0 = *(const float4*)(eb + c), eb1 = *(const float4*)(eb + c + 4);
    float esp[8] = {es0.x, es1.x, es0.y, es1.y, es0.z, es1.z, es0.w, es1.w};
    float ebp[8] = {eb0.x, eb1.x, eb0.y, eb1.y, eb0.z, eb1.z, eb0.w, eb1.w};
    int id = qidx[i];
    size_t base = ((size_t)b * NS_ + id) * D_ + c;
    const int I[8] = {0, 4, 1, 5, 2, 6, 3, 7};   // slot -> logical offset
    #pragma unroll
    for (int j = 0; j < 8; j++) {
        float v = (u[j] - m2) * r2 * esp[j] + ebp[j];
        atomicAdd(&g_U[base + I[j]], v);
        atomicAdd(&out[base + I[j]], v);
    }
}

// -------- tf32 GEMM, P-space operands, float2 A-frag loads --------
#define AS_LD 40
#define BS_LD 132
#define AS_STG (128 * AS_LD)
#define BS_STG (32 * BS_LD)
#define GEMM_SMEM ((2 * AS_STG + 2 * BS_STG) * sizeof(float))

// EPI: 0 plain, 1 tf32-round, 2 bias+gelu+round, 3 transposed-V store (round)
template<int EPI>
__device__ __forceinline__ void gemm_body(const float* __restrict__ A,
                                          const float* __restrict__ W,
                                          const float* __restrict__ bias,
                                          float* __restrict__ C,
                                          int bm, int bn, float* sm) {
    float* As = sm;
    float* Bs = sm + 2 * AS_STG;
    int t = threadIdx.x, w = t >> 5, lane = t & 31;
    int gid = lane >> 2, tid4 = lane & 3;
    int wm = (w >> 2) * 64, wn = (w & 3) * 32;

    float acc[4][4][4] = {};
    float bb[4][2];
    if (EPI == 2) {
        #pragma unroll
        for (int nj = 0; nj < 4; nj++) {
            bb[nj][0] = bias[bn + wn + nj * 8 + tid4];
            bb[nj][1] = bias[bn + wn + nj * 8 + tid4 + 4];
        }
    }

    auto load_stage = [&](int ks, int bf) {
        int k0 = ks * 32;
        #pragma unroll
        for (int i = 0; i < 4; i++) {
            int idx = t + i * 256;
            {   int row = idx >> 3, c4 = (idx & 7) * 4;
                cp16(As + bf * AS_STG + row * AS_LD + c4,
                     A + (size_t)(bm + row) * 256 + k0 + c4); }
            {   int row = idx >> 5, c4 = (idx & 31) * 4;
                cp16(Bs + bf * BS_STG + row * BS_LD + c4,
                     W + (size_t)(k0 + row) * 256 + bn + c4); }
        }
    };

    load_stage(0, 0); CP_COMMIT();
    int buf = 0;
    for (int ks8 = 0; ks8 < 8; ks8++) {
        CP_WAIT(0);
        __syncthreads();
        if (ks8 < 7) { load_stage(ks8 + 1, buf ^ 1); CP_COMMIT(); }
        const float* Ab = As + buf * AS_STG;
        const float* Bb = Bs + buf * BS_STG;
        #pragma unroll
        for (int ks = 0; ks < 4; ks++) {
            unsigned a[4][4];
            #pragma unroll
            for (int mi = 0; mi < 4; mi++) {
                float2 lo = *(const float2*)(Ab + (wm + mi * 16 + gid) * AS_LD + ks * 8 + tid4 * 2);
                float2 hi = *(const float2*)(Ab + (wm + mi * 16 + gid + 8) * AS_LD + ks * 8 + tid4 * 2);
                a[mi][0] = __float_as_uint(lo.x);
                a[mi][1] = __float_as_uint(hi.x);
                a[mi][2] = __float_as_uint(lo.y);
                a[mi][3] = __float_as_uint(hi.y);
            }
            #pragma unroll
            for (int nj = 0; nj < 4; nj++) {
                const float* bp = Bb + (ks * 8 + tid4 * 2) * BS_LD + wn + nj * 8 + gid;
                unsigned b0 = __float_as_uint(bp[0]);
                unsigned b1 = __float_as_uint(bp[BS_LD]);
                #pragma unroll
                for (int mi = 0; mi < 4; mi++)
                    MMA_TF32(acc[mi][nj], a[mi][0], a[mi][1], a[mi][2], a[mi][3], b0, b1);
            }
        }
        buf ^= 1;
    }

    #pragma unroll
    for (int mi = 0; mi < 4; mi++) {
        int r0 = bm + wm + mi * 16 + gid;
        #pragma unroll
        for (int nj = 0; nj < 4; nj++) {
            int col = bn + wn + nj * 8 + tid4 * 2;
            float c0 = acc[mi][nj][0], c1 = acc[mi][nj][1];
            float c2 = acc[mi][nj][2], c3 = acc[mi][nj][3];
            if (EPI == 1 || EPI == 3) {
                c0 = to_tf32(c0); c1 = to_tf32(c1); c2 = to_tf32(c2); c3 = to_tf32(c3);
            }
            if (EPI == 2) {
                c0 = to_tf32(gelu_tanh(c0 + bb[nj][0]));
                c1 = to_tf32(gelu_tanh(c1 + bb[nj][1]));
                c2 = to_tf32(gelu_tanh(c2 + bb[nj][0]));
                c3 = to_tf32(gelu_tanh(c3 + bb[nj][1]));
            }
            if (EPI == 3) {
                // transposed V store: Vt[((b*H + h)*64 + d_slot)][key]
                int bb_ = r0 >> 10, key = r0 & 1023;
                size_t vr = ((size_t)(bb_ * H_ + (col >> 6)) * 64 + (col & 63));
                C[vr * NK_ + key]           = c0;
                C[(vr + 1) * NK_ + key]     = c1;   // col even, col+1 stays in same head block
                C[vr * NK_ + key + 8]       = c2;
                C[(vr + 1) * NK_ + key + 8] = c3;
            } else {
                *(float2*)&C[(size_t)r0 * 256 + col] = make_float2(c0, c1);
                *(float2*)&C[(size_t)(r0 + 8) * 256 + col] = make_float2(c2, c3);
            }
        }
    }
}

template<int EPI>
__global__ __launch_bounds__(256, 2)
void gemm_tc(const float* __restrict__ A, const float* __restrict__ W,
             const float* __restrict__ bias, float* __restrict__ C) {
    extern __shared__ float sm[];
    gemm_body<EPI>(A, W, bias, C, blockIdx.y * 128, blockIdx.x * 128, sm);
}

// batched Q/K/V projection: grid.x = 1280; decode (n-half, tile, which)
__global__ __launch_bounds__(256, 2)
void gemm_qkv(const float* __restrict__ qb, const float* __restrict__ kb,
              const float* __restrict__ Wq, const float* __restrict__ Wk,
              const float* __restrict__ Wv,
              float* __restrict__ Qp, float* __restrict__ Kp, float* __restrict__ Vp) {
    extern __shared__ float sm[];
    int u = blockIdx.x;
    int bn = (u & 1) * 128;
    int v = u >> 1;
    if (v < 128)      gemm_body<1>(qb, Wq, nullptr, Qp, v * 128,         bn, sm);
    else if (v < 384) gemm_body<1>(kb, Wk, nullptr, Kp, (v - 128) * 128, bn, sm);
    else              gemm_body<3>(kb, Wv, nullptr, Vp, (v - 384) * 128, bn, sm);
}

// -------- flash attention: transposed-V smem, all-vector LDS --------
#define KS_LD 72
#define VS_LD 72
#define KS_STG (64 * KS_LD)
#define VS_STG (64 * VS_LD)
#define FA_SMEM ((2 * KS_STG + 2 * VS_STG) * sizeof(float))

__global__ __launch_bounds__(256, 1)
void flash_attn(const float* __restrict__ Qp, const float* __restrict__ Kp,
                const float* __restrict__ Vt, const unsigned long long* __restrict__ mb,
                float* __restrict__ ctx) {
    extern __shared__ float sm[];
    float* Ks0 = sm;
    float* Vs0 = sm + 2 * KS_STG;
    int t = threadIdx.x, lane = t & 31, w = t >> 5;
    int gid = lane >> 2, tid4 = lane & 3;
    int qb = blockIdx.x, h = blockIdx.y, b = blockIdx.z;

    int qrow = qb * 128 + w * 16 + gid;
    size_t qg0 = ((size_t)b * NQ_ + qrow) * D_ + h * DH_;

    unsigned qa[8][4];
    #pragma unroll
    for (int kc = 0; kc < 8; kc++) {
        float2 lo = *(const float2*)(Qp + qg0 + kc * 8 + tid4 * 2);
        float2 hi = *(const float2*)(Qp + qg0 + (size_t)8 * D_ + kc * 8 + tid4 * 2);
        qa[kc][0] = __float_as_uint(lo.x);
        qa[kc][1] = __float_as_uint(hi.x);
        qa[kc][2] = __float_as_uint(lo.y);
        qa[kc][3] = __float_as_uint(hi.y);
    }

    float o[8][4];
    #pragma unroll
    for (int j = 0; j < 8; j++) { o[j][0] = o[j][1] = o[j][2] = o[j][3] = 0.f; }
    float run_m0 = -1e30f, run_m1 = -1e30f, run_l0 = 0.f, run_l1 = 0.f;

    // Vt global: row = (b*H + h)*64 + d_slot (64 rows), col = key (NK)
    const float* vt_base = Vt + ((size_t)(b * H_ + h) * 64) * NK_;

    auto load_stage = [&](int kt2, int bf) {
        const float* kg = Kp + ((size_t)b * NK_ + kt2 * 64) * D_ + h * DH_;
        const float* vg = vt_base + kt2 * 64;
        float* kd = Ks0 + bf * KS_STG;
        float* vd = Vs0 + bf * VS_STG;
        #pragma unroll
        for (int i = 0; i < 4; i++) {
            int idx = t + i * 256;
            int row = idx >> 4, c4 = (idx & 15) * 4;
            // K: key-major (row = key), natural key order (mask indexing)
            cp16(kd + row * KS_LD + c4, kg + (size_t)row * D_ + c4);
            // V: d-major (row = d_slot), cols = keys (natural order)
            cp16(vd + row * VS_LD + c4, vg + (size_t)row * NK_ + c4);
        }
    };

    load_stage(0, 0); CP_COMMIT();
    int buf = 0;
    for (int kt = 0; kt < 16; kt++) {
        CP_WAIT(0);
        __syncthreads();
        if (kt < 15) { load_stage(kt + 1, buf ^ 1); CP_COMMIT(); }
        const float* Kb = Ks0 + buf * KS_STG;
        const float* Vb = Vs0 + buf * VS_STG;

        // ---- S = Q . K^T ----
        float s[8][4];
        #pragma unroll
        for (int j = 0; j < 8; j++) { s[j][0] = s[j][1] = s[j][2] = s[j][3] = 0.f; }
        #pragma unroll
        for (int kc = 0; kc < 8; kc++) {
            #pragma unroll
            for (int j = 0; j < 8; j++) {
                float2 kk = *(const float2*)(Kb + (j * 8 + gid) * KS_LD + kc * 8 + tid4 * 2);
                MMA_TF32(s[j], qa[kc][0], qa[kc][1], qa[kc][2], qa[kc][3],
                         __float_as_uint(kk.x), __float_as_uint(kk.y));
            }
        }

        // ---- mask + online softmax, P rounded in-register ----
        unsigned long long w0 = mb[(size_t)qrow * 16 + kt];
        unsigned long long w1 = mb[(size_t)(qrow + 8) * 16 + kt];
        float mx0 = -1e30f, mx1 = -1e30f;
        #pragma unroll
        for (int j = 0; j < 8; j++) {
            int sh = j * 8 + 2 * tid4;
            s[j][0] = ((w0 >> sh) & 1ull)       ? s[j][0] * SCALE_ : -1e9f;
            s[j][1] = ((w0 >> (sh + 1)) & 1ull) ? s[j][1] * SCALE_ : -1e9f;
            s[j][2] = ((w1 >> sh) & 1ull)       ? s[j][2] * SCALE_ : -1e9f;
            s[j][3] = ((w1 >> (sh + 1)) & 1ull) ? s[j][3] * SCALE_ : -1e9f;
            mx0 = fmaxf(mx0, fmaxf(s[j][0], s[j][1]));
            mx1 = fmaxf(mx1, fmaxf(s[j][2], s[j][3]));
        }
        mx0 = fmaxf(mx0, __shfl_xor_sync(0xffffffffu, mx0, 1));
        mx0 = fmaxf(mx0, __shfl_xor_sync(0xffffffffu, mx0, 2));
        mx1 = fmaxf(mx1, __shfl_xor_sync(0xffffffffu, mx1, 1));
        mx1 = fmaxf(mx1, __shfl_xor_sync(0xffffffffu, mx1, 2));
        float nm0 = fmaxf(run_m0, mx0), nm1 = fmaxf(run_m1, mx1);
        float fac0 = __expf(run_m0 - nm0), fac1 = __expf(run_m1 - nm1);
        run_m0 = nm0; run_m1 = nm1;
        float sum0 = 0.f, sum1 = 0.f;
        #pragma unroll
        for (int j = 0; j < 8; j++) {
            float e0 = __expf(s[j][0] - nm0), e1 = __expf(s[j][1] - nm0);
            float e2 = __expf(s[j][2] - nm1), e3 = __expf(s[j][3] - nm1);
            sum0 += e0 + e1; sum1 += e2 + e3;
            s[j][0] = to_tf32(e0); s[j][1] = to_tf32(e1);
            s[j][2] = to_tf32(e2); s[j][3] = to_tf32(e3);
        }
        sum0 += __shfl_xor_sync(0xffffffffu, sum0, 1);
        sum0 += __shfl_xor_sync(0xffffffffu, sum0, 2);
        sum1 += __shfl_xor_sync(0xffffffffu, sum1, 1);
        sum1 += __shfl_xor_sync(0xffffffffu, sum1, 2);
        run_l0 = run_l0 * fac0 + sum0;
        run_l1 = run_l1 * fac1 + sum1;
        #pragma unroll
        for (int j = 0; j < 8; j++) { o[j][0] *= fac0; o[j][1] *= fac0; o[j][2] *= fac1; o[j][3] *= fac1; }

        // ---- O += P . V : P from registers, V^T float2 loads ----
        // A-frag keys at k-slots (tid4, tid4+4) = S-register keys (2*tid4, 2*tid4+1)
        // B-frag: Vb is [d_slot][key]; b-pair = keys (2*tid4, 2*tid4+1) at column n
        //   -> one float2 at Vb[n * VS_LD + kc*8 + 2*tid4]
        #pragma unroll
        for (int kc = 0; kc < 8; kc++) {
            unsigned pa0 = __float_as_uint(s[kc][0]);
            unsigned pa1 = __float_as_uint(s[kc][2]);
            unsigned pa2 = __float_as_uint(s[kc][1]);
            unsigned pa3 = __float_as_uint(s[kc][3]);
            #pragma unroll
            for (int j2 = 0; j2 < 8; j2++) {
                float2 vv = *(const float2*)(Vb + (j2 * 8 + gid) * VS_LD + kc * 8 + 2 * tid4);
                MMA_TF32(o[j2], pa0, pa1, pa2, pa3,
                         __float_as_uint(vv.x), __float_as_uint(vv.y));
            }
        }
        buf ^= 1;
    }

    float inv0 = 1.f / run_l0, inv1 = 1.f / run_l1;
    float* c0 = ctx + qg0;
    #pragma unroll
    for (int j2 = 0; j2 < 8; j2++) {
        *(float2*)&c0[j2 * 8 + 2 * tid4] =
            make_float2(to_tf32(o[j2][0] * inv0), to_tf32(o[j2][1] * inv0));
        *(float2*)&c0[(size_t)8 * D_ + j2 * 8 + 2 * tid4] =
            make_float2(to_tf32(o[j2][2] * inv1), to_tf32(o[j2][3] * inv1));
    }
}

// -------- host launcher --------
extern "C" void kernel_launch(void* const* d_in, const int* in_sizes, int n_in,
                              void* d_out, int out_size) {
    const float* upd   = (const float*)d_in[0];
    const float* emb   = (const float*)d_in[1];
    const float* maskl = (const float*)d_in[2];
    const float* Wq    = (const float*)d_in[3];
    const float* Wk    = (const float*)d_in[4];
    const float* Wv    = (const float*)d_in[5];
    const float* Wo    = (const float*)d_in[6];
    const float* W1    = (const float*)d_in[7];
    const float* b1    = (const float*)d_in[8];
    const float* W2    = (const float*)d_in[9];
    const float* b2    = (const float*)d_in[10];
    const float* sys_s = (const float*)d_in[11];
    const float* sys_b = (const float*)d_in[12];
    const float* eff_s = (const float*)d_in[13];
    const float* eff_b = (const float*)d_in[14];
    const float* in_s  = (const float*)d_in[15];
    const float* in_b  = (const float*)d_in[16];
    const float* out_s = (const float*)d_in[17];
    const float* out_b = (const float*)d_in[18];
    const int*   qidx  = (const int*)d_in[19];
    const int*   kidx  = (const int*)d_in[20];
    float* out = (float*)d_out;

    float *qb, *kb, *Qp, *Kp, *Vp, *ctx, *hb, *t1, *fb, *Wr;
    unsigned long long* mbp;
    cudaGetSymbolAddress((void**)&qb,  g_q);
    cudaGetSymbolAddress((void**)&kb,  g_k);
    cudaGetSymbolAddress((void**)&Qp,  g_Qp);
    cudaGetSymbolAddress((void**)&Kp,  g_Kp);
    cudaGetSymbolAddress((void**)&Vp,  g_Vp);
    cudaGetSymbolAddress((void**)&ctx, g_ctx);
    cudaGetSymbolAddress((void**)&hb,  g_h);
    cudaGetSymbolAddress((void**)&t1,  g_t1);
    cudaGetSymbolAddress((void**)&fb,  g_f);
    cudaGetSymbolAddress((void**)&Wr,  g_Wr);
    cudaGetSymbolAddress((void**)&mbp, g_mb);

    cudaFuncSetAttribute(flash_attn, cudaFuncAttributeMaxDynamicSharedMemorySize, (int)FA_SMEM);
    cudaFuncSetAttribute(gemm_tc<0>, cudaFuncAttributeMaxDynamicSharedMemorySize, (int)GEMM_SMEM);
    cudaFuncSetAttribute(gemm_tc<1>, cudaFuncAttributeMaxDynamicSharedMemorySize, (int)GEMM_SMEM);
    cudaFuncSetAttribute(gemm_tc<2>, cudaFuncAttributeMaxDynamicSharedMemorySize, (int)GEMM_SMEM);
    cudaFuncSetAttribute(gemm_qkv,   cudaFuncAttributeMaxDynamicSharedMemorySize, (int)GEMM_SMEM);

    prep_kernel<<<39296, 256>>>(upd, out, Wq, Wk, Wv, Wo, W1, W2, maskl);

    const float* rWq = Wr;
    const float* rWk = Wr + 1 * 65536;
    const float* rWv = Wr + 2 * 65536;
    const float* rWo = Wr + 3 * 65536;
    const float* rW1 = Wr + 4 * 65536;
    const float* rW2 = Wr + 5 * 65536;

    for (int l = 0; l < L_; l++) {
        gather_ln_qk<<<(MQ + MK) / 8, 256>>>(emb, qidx + l * NQ_, kidx + l * NK_,
                                             sys_s, sys_b, qb, kb);

        gemm_qkv<<<1280, 256, GEMM_SMEM>>>(qb, kb, rWq, rWk, rWv, Qp, Kp, Vp);

        flash_attn<<<dim3(NQ_ / 128, H_, B_), 256, FA_SMEM>>>(
            Qp, Kp, Vp, mbp + (size_t)l * NQ_ * 16, ctx);

        gemm_tc<0><<<dim3(2, MQ / 128), 256, GEMM_SMEM>>>(ctx, rWo, nullptr, t1);
        ln_w<<<MQ / 8, 256>>>(t1, in_s, in_b, hb);

        gemm_tc<2><<<dim3(2, MQ / 128), 256, GEMM_SMEM>>>(hb, rW1, b1, t1);
        gemm_tc<0><<<dim3(2, MQ / 128), 256, GEMM_SMEM>>>(t1, rW2, nullptr, fb);

        add_ln_scatter<<<MQ / 8, 256>>>(hb, fb, b2, out_s, out_b, eff_s, eff_b,
                                        qidx + l * NQ_, out);
    }
}